// round 6
// baseline (speedup 1.0000x reference)
#include <cuda_runtime.h>
#include <cuda_fp16.h>
#include <cstdint>
#include <cstddef>

// Problem constants
#define HD 1024
#define ID 2048
#define NSTATE 16
#define RD 64
#define BB 2
#define LL 512
#define ML (BB*LL)

// ---------------------------------------------------------------------------
// Scratch
// ---------------------------------------------------------------------------
__device__ __align__(16) float g_x   [(size_t)ML*ID];
__device__ __align__(16) float g_gate[(size_t)ML*ID];
__device__ __align__(16) float g_u   [(size_t)ML*ID];
__device__ __align__(16) float g_ssm [2][(size_t)ML*96];   // only cols 64..95 valid (B|C)
__device__ __align__(16) float g_delta[2][(size_t)ML*ID];
__device__ __align__(16) float g_y   [2][(size_t)ML*ID];

// fp16 split-plane pools (fragment-packed u32 = half2 pairs)
#define U_HS_A    0u
#define U_HS2_A   524288u
#define U_INW_B   1048576u
#define U_INDW_B  2097152u
#define U_SSM0_A  3145728u
#define U_SSM1_A  3178496u
#define U_DTW0_B  3211264u
#define U_DTW1_B  3276800u
#define U_YT_A    3342336u
#define U_OUTW_B  4390912u
#define U_TOTAL   5439488u
__device__ __align__(16) unsigned g_hi[U_TOTAL];
__device__ __align__(16) unsigned g_lo[U_TOTAL];

__device__ __forceinline__ float siluf(float v)     { return v * (1.0f / (1.0f + __expf(-v))); }
__device__ __forceinline__ float softplusf(float v) { return v > 20.f ? v : log1pf(__expf(v)); }

__device__ __forceinline__ void split_pack(float x0, float x1, unsigned& ph, unsigned& pl) {
    __half h0 = __float2half_rn(x0), h1 = __float2half_rn(x1);
    __half l0 = __float2half_rn(x0 - __half2float(h0));
    __half l1 = __float2half_rn(x1 - __half2float(h1));
    ph = ((unsigned)__half_as_ushort(h1) << 16) | __half_as_ushort(h0);
    pl = ((unsigned)__half_as_ushort(l1) << 16) | __half_as_ushort(l0);
}

// A-fragment u32 index within a 128x32 chunk, for element pair (r, k even)
__device__ __forceinline__ int afrag_idx(int r, int k) {
    int mt = r >> 4, rr = r & 15;
    int ks = k >> 4, kk = k & 15;
    int lane = ((rr & 7) << 2) | ((kk >> 1) & 3);
    int reg  = (rr >> 3) | ((kk >> 3) << 1);
    return ((mt * 2 + ks) * 32 + lane) * 4 + reg;
}

// ---------------------------------------------------------------------------
// Batched converter: fp32 -> fragment-packed fp16 hi/lo planes.
// ---------------------------------------------------------------------------
struct CDesc { const float* src; unsigned off; int ld; int nchunks; int nblk; int isA; };
struct CTable { CDesc d[7]; };

__global__ __launch_bounds__(256) void conv_all(CTable t)
{
    __shared__ float s[128][33];
    int b = blockIdx.x;
    int di = 0;
    while (b >= t.d[di].nblk) { b -= t.d[di].nblk; di++; }
    const CDesc d = t.d[di];
    const int rb = b / d.nchunks, c = b % d.nchunks;
    const int tid = threadIdx.x;
    const float* sp = d.src + (size_t)(rb * 128) * d.ld + c * 32;
#pragma unroll
    for (int it = 0; it < 4; it++) {
        int r = (tid >> 3) + it * 32, c4 = tid & 7;
        float4 v = *reinterpret_cast<const float4*>(sp + (size_t)r * d.ld + c4 * 4);
        s[r][c4*4+0]=v.x; s[r][c4*4+1]=v.y; s[r][c4*4+2]=v.z; s[r][c4*4+3]=v.w;
    }
    __syncthreads();
    unsigned* oh = g_hi + d.off + (size_t)(rb * d.nchunks + c) * 2048;
    unsigned* ol = g_lo + d.off + (size_t)(rb * d.nchunks + c) * 2048;
    if (d.isA) {
#pragma unroll
        for (int j = 0; j < 8; j++) {
            int idx = tid + 256*j;
            int reg = idx&3, lane=(idx>>2)&31, ks=(idx>>7)&1, mt=idx>>8;
            int r = mt*16 + ((reg&1)<<3) + (lane>>2);
            int k = ks*16 + ((reg>>1)<<3) + ((lane&3)<<1);
            unsigned ph, pl;
            split_pack(s[r][k], s[r][k+1], ph, pl);
            oh[idx] = ph; ol[idx] = pl;
        }
    } else {
#pragma unroll
        for (int j = 0; j < 8; j++) {
            int idx = tid + 256*j;
            int reg = idx&1, lane=(idx>>1)&31, ks=(idx>>6)&1, nt=idx>>7;
            int n = nt*8 + (lane>>2);
            int k = ks*16 + reg*8 + ((lane&3)<<1);
            unsigned ph, pl;
            split_pack(s[n][k], s[n][k+1], ph, pl);
            oh[idx] = ph; ol[idx] = pl;
        }
    }
}

// ---------------------------------------------------------------------------
// fp16 3-pass split GEMM: C = A @ B^T, 128x128 tiles, BK=32, cp.async double buffer.
// ---------------------------------------------------------------------------
struct HArgs { unsigned aoff; unsigned boff; float* C; const float* bias; };

__device__ __forceinline__ void mma_h(float* c, const unsigned* a, const unsigned* b) {
    asm volatile(
        "mma.sync.aligned.m16n8k16.row.col.f32.f16.f16.f32 "
        "{%0,%1,%2,%3},{%4,%5,%6,%7},{%8,%9},{%0,%1,%2,%3};"
        : "+f"(c[0]), "+f"(c[1]), "+f"(c[2]), "+f"(c[3])
        : "r"(a[0]), "r"(a[1]), "r"(a[2]), "r"(a[3]), "r"(b[0]), "r"(b[1]));
}
__device__ __forceinline__ void cp16(unsigned saddr, const void* g) {
    asm volatile("cp.async.cg.shared.global [%0], [%1], 16;" :: "r"(saddr), "l"(g));
}

#define HG_SMEM_BYTES 65536

template<int EPI>
__global__ __launch_bounds__(256) void hgemm(HArgs h0, HArgs h1, int nchunks, int ldc)
{
    extern __shared__ unsigned sm[];
    const unsigned sbase = (unsigned)__cvta_generic_to_shared(sm);
    HArgs h = blockIdx.z ? h1 : h0;
    const int tid = threadIdx.x, lane = tid & 31, wid = tid >> 5;
    const int warp_m = wid & 1, warp_n = wid >> 1;
    const unsigned* gAh = g_hi + h.aoff + (size_t)blockIdx.y * nchunks * 2048;
    const unsigned* gAl = g_lo + h.aoff + (size_t)blockIdx.y * nchunks * 2048;
    const unsigned* gBh = g_hi + h.boff + (size_t)blockIdx.x * nchunks * 2048;
    const unsigned* gBl = g_lo + h.boff + (size_t)blockIdx.x * nchunks * 2048;

    auto issue = [&](int s, int c) {
        const unsigned dst = sbase + s * 32768;
        const unsigned* srcs[4] = {gAh + c*2048, gAl + c*2048, gBh + c*2048, gBl + c*2048};
#pragma unroll
        for (int p = 0; p < 4; p++)
#pragma unroll
            for (int q = 0; q < 2; q++) {
                const int o = (tid + q*256) * 4;
                cp16(dst + p*8192 + o*4, srcs[p] + o);
            }
        asm volatile("cp.async.commit_group;");
    };

    float acc[4][4][4];
#pragma unroll
    for (int mt = 0; mt < 4; mt++)
#pragma unroll
        for (int nt = 0; nt < 4; nt++)
#pragma unroll
            for (int j = 0; j < 4; j++) acc[mt][nt][j] = 0.f;

    issue(0, 0);
    for (int c = 0; c < nchunks; c++) {
        if (c + 1 < nchunks) {
            issue((c + 1) & 1, c + 1);
            asm volatile("cp.async.wait_group 1;");
        } else {
            asm volatile("cp.async.wait_group 0;");
        }
        __syncthreads();
        const unsigned* st  = sm + (c & 1) * 8192;
        const unsigned* sAh = st;
        const unsigned* sAl = st + 2048;
        const unsigned* sBh = st + 4096;
        const unsigned* sBl = st + 6144;
#pragma unroll
        for (int ks = 0; ks < 2; ks++) {
            unsigned ah[4][4], al[4][4], bh[4][2], bl[4][2];
#pragma unroll
            for (int mt = 0; mt < 4; mt++) {
                const int base = (((warp_m*4 + mt)*2 + ks)*32 + lane) * 4;
                uint4 v = *reinterpret_cast<const uint4*>(sAh + base);
                ah[mt][0]=v.x; ah[mt][1]=v.y; ah[mt][2]=v.z; ah[mt][3]=v.w;
                v = *reinterpret_cast<const uint4*>(sAl + base);
                al[mt][0]=v.x; al[mt][1]=v.y; al[mt][2]=v.z; al[mt][3]=v.w;
            }
#pragma unroll
            for (int nt = 0; nt < 4; nt++) {
                const int base = (((warp_n*4 + nt)*2 + ks)*32 + lane) * 2;
                uint2 v = *reinterpret_cast<const uint2*>(sBh + base);
                bh[nt][0]=v.x; bh[nt][1]=v.y;
                v = *reinterpret_cast<const uint2*>(sBl + base);
                bl[nt][0]=v.x; bl[nt][1]=v.y;
            }
#pragma unroll
            for (int mt = 0; mt < 4; mt++)
#pragma unroll
                for (int nt = 0; nt < 4; nt++) mma_h(acc[mt][nt], ah[mt], bh[nt]);
#pragma unroll
            for (int mt = 0; mt < 4; mt++)
#pragma unroll
                for (int nt = 0; nt < 4; nt++) mma_h(acc[mt][nt], ah[mt], bl[nt]);
#pragma unroll
            for (int mt = 0; mt < 4; mt++)
#pragma unroll
                for (int nt = 0; nt < 4; nt++) mma_h(acc[mt][nt], al[mt], bh[nt]);
        }
        __syncthreads();
    }

    const int row0 = blockIdx.y * 128, col0 = blockIdx.x * 128;
    const int rw = lane >> 2;
    const int cw = (lane & 3) * 2;
#pragma unroll
    for (int mt = 0; mt < 4; mt++) {
        const int m = row0 + warp_m*64 + mt*16 + rw;
#pragma unroll
        for (int nt = 0; nt < 4; nt++) {
            const int n = col0 + warp_n*32 + nt*8 + cw;
            float v0 = acc[mt][nt][0], v1 = acc[mt][nt][1];
            float v2 = acc[mt][nt][2], v3 = acc[mt][nt][3];
            if (EPI == 1) {
                const float b0 = __ldg(h.bias + n);
                const float b1 = __ldg(h.bias + n + 1);
                v0 = softplusf(v0 + b0); v1 = softplusf(v1 + b1);
                v2 = softplusf(v2 + b0); v3 = softplusf(v3 + b1);
            }
            *reinterpret_cast<float2*>(h.C + (size_t)m * ldc + n)       = make_float2(v0, v1);
            *reinterpret_cast<float2*>(h.C + (size_t)(m + 8) * ldc + n) = make_float2(v2, v3);
        }
    }
}

// ---------------------------------------------------------------------------
// G3 SIMT GEMM: ssm = u @ xw^T  (M=1024, N=96, K=2048)
// Epilogue: cols 0..63 (dt) -> split planes (A-fragment layout, nchunks=2);
//           cols 64..95 (B|C) -> float g_ssm[dir]
// ---------------------------------------------------------------------------
__global__ __launch_bounds__(256)
void sgemm_g3(const float* __restrict__ u, const float* xw_f, const float* xw_b)
{
    constexpr int BM = 64, BN = 32, TM = 4, TN = 2, BK = 16, THREADS = 256, KV = BK/4;
    __shared__ float As[BK][BM];
    __shared__ float Bs[BK][BN];
    const int dir = blockIdx.z;
    const float* B = dir ? xw_b : xw_f;
    const int tid  = threadIdx.x;
    const int row0 = blockIdx.y * BM;
    const int col0 = blockIdx.x * BN;
    const float* __restrict__ Ap = u + (size_t)row0 * ID;
    const float* __restrict__ Bp = B + (size_t)col0 * ID;
    float acc[TM][TN];
#pragma unroll
    for (int i = 0; i < TM; i++) { acc[i][0] = 0.f; acc[i][1] = 0.f; }
    const int tcol = tid % (BN/TN);
    const int trow = tid / (BN/TN);
    for (int k0 = 0; k0 < ID; k0 += BK) {
#pragma unroll
        for (int idx = tid; idx < BM*KV; idx += THREADS) {
            int rr = idx / KV, kv = idx % KV;
            float4 v = *reinterpret_cast<const float4*>(Ap + (size_t)rr*ID + k0 + kv*4);
            As[kv*4+0][rr] = v.x; As[kv*4+1][rr] = v.y;
            As[kv*4+2][rr] = v.z; As[kv*4+3][rr] = v.w;
        }
#pragma unroll
        for (int idx = tid; idx < BN*KV; idx += THREADS) {
            int rr = idx / KV, kv = idx % KV;
            float4 v = *reinterpret_cast<const float4*>(Bp + (size_t)rr*ID + k0 + kv*4);
            Bs[kv*4+0][rr] = v.x; Bs[kv*4+1][rr] = v.y;
            Bs[kv*4+2][rr] = v.z; Bs[kv*4+3][rr] = v.w;
        }
        __syncthreads();
#pragma unroll
        for (int k = 0; k < BK; k++) {
            float a[TM], b[TN];
#pragma unroll
            for (int i = 0; i < TM; i += 4) {
                float4 v = *reinterpret_cast<const float4*>(&As[k][trow*TM + i]);
                a[i] = v.x; a[i+1] = v.y; a[i+2] = v.z; a[i+3] = v.w;
            }
            float2 v2 = *reinterpret_cast<const float2*>(&Bs[k][tcol*TN]);
            b[0] = v2.x; b[1] = v2.y;
#pragma unroll
            for (int i = 0; i < TM; i++) {
                acc[i][0] = fmaf(a[i], b[0], acc[i][0]);
                acc[i][1] = fmaf(a[i], b[1], acc[i][1]);
            }
        }
        __syncthreads();
    }
    const unsigned uoff = dir ? U_SSM1_A : U_SSM0_A;
    const int c0 = col0 + tcol*TN;
#pragma unroll
    for (int i = 0; i < TM; i++) {
        const int R = row0 + trow*TM + i;
        if (c0 < 64) {
            unsigned ph, pl;
            split_pack(acc[i][0], acc[i][1], ph, pl);
            const int idx = uoff + ((R >> 7) * 2 + (c0 >> 5)) * 2048 + afrag_idx(R & 127, c0 & 31);
            g_hi[idx] = ph; g_lo[idx] = pl;
        } else {
            g_ssm[dir][(size_t)R*96 + c0]     = acc[i][0];
            g_ssm[dir][(size_t)R*96 + c0 + 1] = acc[i][1];
        }
    }
}

// ---------------------------------------------------------------------------
// conv + silu
// ---------------------------------------------------------------------------
__global__ void conv_silu_kernel(const float* __restrict__ w,
                                 const float* __restrict__ bias)
{
    int idx = blockIdx.x * blockDim.x + threadIdx.x;
    int i = idx % ID;
    int l = (idx / ID) % LL;
    float acc = bias[i];
#pragma unroll
    for (int k = 0; k < 4; k++) {
        int ls = l - 3 + k;
        if (ls >= 0) acc = fmaf(g_x[(size_t)idx + (ptrdiff_t)(k-3)*ID], w[i*4 + k], acc);
    }
    g_u[idx] = siluf(acc);
}

// ---------------------------------------------------------------------------
// selective scan
// ---------------------------------------------------------------------------
__global__ void scan_kernel(const float* __restrict__ Alog_f,
                            const float* __restrict__ Alog_b,
                            const float* __restrict__ D_f,
                            const float* __restrict__ D_b)
{
    int gw   = (blockIdx.x * blockDim.x + threadIdx.x) >> 5;
    int lane = threadIdx.x & 31;
    int dir  = gw >> 11;
    int b    = (gw >> 10) & 1;
    int i    = ((gw & 1023) << 1) | (lane >> 4);
    int n    = lane & 15;

    const float* Alog = dir ? Alog_b : Alog_f;
    float An = -expf(Alog[i*NSTATE + n]);
    float Dv = dir ? D_b[i] : D_f[i];

    const float* dbase = g_delta[dir] + (size_t)(b*LL)*ID + i;
    const float* ubase = g_u          + (size_t)(b*LL)*ID + i;
    const float* sbase = g_ssm[dir]   + (size_t)(b*LL)*96;
    float*       ybase = g_y[dir]     + (size_t)(b*LL)*ID + i;

    int l0 = dir ? (LL-1) : 0;
    ptrdiff_t dstep = dir ? -(ptrdiff_t)ID : (ptrdiff_t)ID;
    ptrdiff_t sstep = dir ? -96 : 96;

    const float* dp = dbase + (size_t)l0*ID;
    const float* up = ubase + (size_t)l0*ID;
    const float* sp = sbase + (size_t)l0*96;
    float*       yp = ybase + (size_t)l0*ID;

    float x = 0.f;
#pragma unroll 2
    for (int t = 0; t < LL; t++) {
        float d  = *dp;
        float uu = *up;
        float Bv = *(sp + RD + n);
        float Cv = *(sp + RD + NSTATE + n);
        float dA = __expf(d * An);
        x = fmaf(x, dA, d * Bv * uu);
        float p = x * Cv;
        p += __shfl_xor_sync(0xffffffffu, p, 1);
        p += __shfl_xor_sync(0xffffffffu, p, 2);
        p += __shfl_xor_sync(0xffffffffu, p, 4);
        p += __shfl_xor_sync(0xffffffffu, p, 8);
        if (n == 0) *yp = fmaf(uu, Dv, p);
        dp += dstep; up += dstep; sp += sstep; yp += dstep;
    }
}

// ---------------------------------------------------------------------------
// combine: yt = (yf+yb)*silu(gate), written directly as split planes (A layout)
// ---------------------------------------------------------------------------
__global__ __launch_bounds__(256) void combine_kernel()
{
    const int idx = blockIdx.x * blockDim.x + threadIdx.x;   // over ML*ID/2
    const int R  = idx >> 10;
    const int ch = (idx & 1023) << 1;
    const size_t o = (size_t)R * ID + ch;
    float2 yf = *reinterpret_cast<const float2*>(g_y[0] + o);
    float2 yb = *reinterpret_cast<const float2*>(g_y[1] + o);
    float2 gt = *reinterpret_cast<const float2*>(g_gate + o);
    float yt0 = (yf.x + yb.x) * siluf(gt.x);
    float yt1 = (yf.y + yb.y) * siluf(gt.y);
    unsigned ph, pl;
    split_pack(yt0, yt1, ph, pl);
    const int d = U_YT_A + ((R >> 7) * 64 + (ch >> 5)) * 2048 + afrag_idx(R & 127, ch & 31);
    g_hi[d] = ph; g_lo[d] = pl;
}

// ---------------------------------------------------------------------------
// Launch
// ---------------------------------------------------------------------------
extern "C" void kernel_launch(void* const* d_in, const int* in_sizes, int n_in,
                              void* d_out, int out_size)
{
    const float* hs     = (const float*)d_in[0];
    const float* hs2    = (const float*)d_in[1];
    const float* in_w   = (const float*)d_in[2];
    const float* in_dw  = (const float*)d_in[3];
    const float* conv_w = (const float*)d_in[4];
    const float* conv_b = (const float*)d_in[5];
    const float* xw_f   = (const float*)d_in[6];
    const float* xw_b   = (const float*)d_in[7];
    const float* dtw_f  = (const float*)d_in[8];
    const float* dtb_f  = (const float*)d_in[9];
    const float* dtw_b  = (const float*)d_in[10];
    const float* dtb_b  = (const float*)d_in[11];
    const float* Alog_f = (const float*)d_in[12];
    const float* Alog_b = (const float*)d_in[13];
    const float* D_f    = (const float*)d_in[14];
    const float* D_b    = (const float*)d_in[15];
    const float* outw   = (const float*)d_in[16];
    float* out = (float*)d_out;

    float *px, *pgate, *pu, *pdelta;
    cudaGetSymbolAddress((void**)&px,     g_x);
    cudaGetSymbolAddress((void**)&pgate,  g_gate);
    cudaGetSymbolAddress((void**)&pu,     g_u);
    cudaGetSymbolAddress((void**)&pdelta, g_delta);
    float* pd0 = pdelta;
    float* pd1 = pdelta + (size_t)ML*ID;

    cudaFuncSetAttribute(hgemm<0>, cudaFuncAttributeMaxDynamicSharedMemorySize, HG_SMEM_BYTES);
    cudaFuncSetAttribute(hgemm<1>, cudaFuncAttributeMaxDynamicSharedMemorySize, HG_SMEM_BYTES);

    // Batched conversions (weights + inputs) in ONE launch
    {
        CTable t;
        t.d[0] = {in_w,                  U_INW_B,  HD, 32, 512, 0};
        t.d[1] = {in_dw + (size_t)ID*HD, U_INDW_B, HD, 32, 512, 0};
        t.d[2] = {dtw_f,                 U_DTW0_B, RD, 2,  32,  0};
        t.d[3] = {dtw_b,                 U_DTW1_B, RD, 2,  32,  0};
        t.d[4] = {outw,                  U_OUTW_B, ID, 64, 512, 0};
        t.d[5] = {hs,                    U_HS_A,   HD, 32, 256, 1};
        t.d[6] = {hs2,                   U_HS2_A,  HD, 32, 256, 1};
        conv_all<<<2112, 256>>>(t);
    }

    // G1: x = hs @ in_w[:I]^T ; gate = hs2 @ in_dw[I:2I]^T
    {
        HArgs a{U_HS_A,  U_INW_B,  px,    nullptr};
        HArgs b{U_HS2_A, U_INDW_B, pgate, nullptr};
        hgemm<0><<<dim3(ID/128, ML/128, 2), 256, HG_SMEM_BYTES>>>(a, b, 32, ID);
    }

    conv_silu_kernel<<<(ML*ID)/256, 256>>>(conv_w, conv_b);

    // G3: ssm = u @ xw^T, fused split-plane epilogue for dt cols
    sgemm_g3<<<dim3(96/32, ML/64, 2), 256>>>(pu, xw_f, xw_b);

    // G4: delta = softplus(dt @ dt_w^T + b)
    {
        HArgs a{U_SSM0_A, U_DTW0_B, pd0, dtb_f};
        HArgs b{U_SSM1_A, U_DTW1_B, pd1, dtb_b};
        hgemm<1><<<dim3(ID/128, ML/128, 2), 256, HG_SMEM_BYTES>>>(a, b, 2, ID);
    }

    scan_kernel<<<512, 256>>>(Alog_f, Alog_b, D_f, D_b);
    combine_kernel<<<(ML*ID)/512, 256>>>();

    // G5: out = yt @ out_proj_w^T
    {
        HArgs a{U_YT_A, U_OUTW_B, out, nullptr};
        hgemm<0><<<dim3(HD/128, ML/128, 1), 256, HG_SMEM_BYTES>>>(a, a, 64, HD);
    }

    (void)in_sizes; (void)n_in; (void)out_size;
}

// round 8
// speedup vs baseline: 1.1016x; 1.1016x over previous
#include <cuda_runtime.h>
#include <cuda_fp16.h>
#include <cstdint>
#include <cstddef>

// Problem constants
#define HD 1024
#define ID 2048
#define NSTATE 16
#define RD 64
#define BB 2
#define LL 512
#define ML (BB*LL)

// ---------------------------------------------------------------------------
// Scratch
// ---------------------------------------------------------------------------
__device__ __align__(16) float g_x   [(size_t)ML*ID];
__device__ __align__(16) float g_gate[(size_t)ML*ID];
__device__ __align__(16) float g_u   [(size_t)ML*ID];
__device__ __align__(16) float g_ssm [2][(size_t)ML*96];   // only cols 64..95 read (B|C)
__device__ __align__(16) float g_part[2][4][(size_t)ML*96]; // split-K partials for G3
__device__ __align__(16) float g_delta[2][(size_t)ML*ID];
__device__ __align__(16) float g_y   [2][(size_t)ML*ID];

// fp16 split-plane pools (fragment-packed u32 = half2 pairs)
#define U_HS_A    0u
#define U_HS2_A   524288u
#define U_INW_B   1048576u
#define U_INDW_B  2097152u
#define U_SSM0_A  3145728u
#define U_SSM1_A  3178496u
#define U_DTW0_B  3211264u
#define U_DTW1_B  3276800u
#define U_YT_A    3342336u
#define U_OUTW_B  4390912u
#define U_TOTAL   5439488u
__device__ __align__(16) unsigned g_hi[U_TOTAL];
__device__ __align__(16) unsigned g_lo[U_TOTAL];

__device__ __forceinline__ float siluf(float v)     { return v * (1.0f / (1.0f + __expf(-v))); }
__device__ __forceinline__ float softplusf(float v) { return v > 20.f ? v : log1pf(__expf(v)); }

__device__ __forceinline__ void split_pack(float x0, float x1, unsigned& ph, unsigned& pl) {
    __half h0 = __float2half_rn(x0), h1 = __float2half_rn(x1);
    __half l0 = __float2half_rn(x0 - __half2float(h0));
    __half l1 = __float2half_rn(x1 - __half2float(h1));
    ph = ((unsigned)__half_as_ushort(h1) << 16) | __half_as_ushort(h0);
    pl = ((unsigned)__half_as_ushort(l1) << 16) | __half_as_ushort(l0);
}

// A-fragment u32 index within a 128x32 chunk, for element pair (r, k even)
__device__ __forceinline__ int afrag_idx(int r, int k) {
    int mt = r >> 4, rr = r & 15;
    int ks = k >> 4, kk = k & 15;
    int lane = ((rr & 7) << 2) | ((kk >> 1) & 3);
    int reg  = (rr >> 3) | ((kk >> 3) << 1);
    return ((mt * 2 + ks) * 32 + lane) * 4 + reg;
}

// ---------------------------------------------------------------------------
// Batched converter: fp32 -> fragment-packed fp16 hi/lo planes.
// ---------------------------------------------------------------------------
struct CDesc { const float* src; unsigned off; int ld; int nchunks; int nblk; int isA; };
struct CTable { CDesc d[7]; };

__global__ __launch_bounds__(256) void conv_all(CTable t)
{
    __shared__ float s[128][33];
    int b = blockIdx.x;
    int di = 0;
    while (b >= t.d[di].nblk) { b -= t.d[di].nblk; di++; }
    const CDesc d = t.d[di];
    const int rb = b / d.nchunks, c = b % d.nchunks;
    const int tid = threadIdx.x;
    const float* sp = d.src + (size_t)(rb * 128) * d.ld + c * 32;
#pragma unroll
    for (int it = 0; it < 4; it++) {
        int r = (tid >> 3) + it * 32, c4 = tid & 7;
        float4 v = *reinterpret_cast<const float4*>(sp + (size_t)r * d.ld + c4 * 4);
        s[r][c4*4+0]=v.x; s[r][c4*4+1]=v.y; s[r][c4*4+2]=v.z; s[r][c4*4+3]=v.w;
    }
    __syncthreads();
    unsigned* oh = g_hi + d.off + (size_t)(rb * d.nchunks + c) * 2048;
    unsigned* ol = g_lo + d.off + (size_t)(rb * d.nchunks + c) * 2048;
    if (d.isA) {
#pragma unroll
        for (int j = 0; j < 8; j++) {
            int idx = tid + 256*j;
            int reg = idx&3, lane=(idx>>2)&31, ks=(idx>>7)&1, mt=idx>>8;
            int r = mt*16 + ((reg&1)<<3) + (lane>>2);
            int k = ks*16 + ((reg>>1)<<3) + ((lane&3)<<1);
            unsigned ph, pl;
            split_pack(s[r][k], s[r][k+1], ph, pl);
            oh[idx] = ph; ol[idx] = pl;
        }
    } else {
#pragma unroll
        for (int j = 0; j < 8; j++) {
            int idx = tid + 256*j;
            int reg = idx&1, lane=(idx>>1)&31, ks=(idx>>6)&1, nt=idx>>7;
            int n = nt*8 + (lane>>2);
            int k = ks*16 + reg*8 + ((lane&3)<<1);
            unsigned ph, pl;
            split_pack(s[n][k], s[n][k+1], ph, pl);
            oh[idx] = ph; ol[idx] = pl;
        }
    }
}

// ---------------------------------------------------------------------------
// fp16 3-pass split GEMM: C = A @ B^T, 128x128 tiles, BK=32, cp.async double buffer.
// ---------------------------------------------------------------------------
struct HArgs { unsigned aoff; unsigned boff; float* C; const float* bias; };

__device__ __forceinline__ void mma_h(float* c, const unsigned* a, const unsigned* b) {
    asm volatile(
        "mma.sync.aligned.m16n8k16.row.col.f32.f16.f16.f32 "
        "{%0,%1,%2,%3},{%4,%5,%6,%7},{%8,%9},{%0,%1,%2,%3};"
        : "+f"(c[0]), "+f"(c[1]), "+f"(c[2]), "+f"(c[3])
        : "r"(a[0]), "r"(a[1]), "r"(a[2]), "r"(a[3]), "r"(b[0]), "r"(b[1]));
}
__device__ __forceinline__ void cp16(unsigned saddr, const void* g) {
    asm volatile("cp.async.cg.shared.global [%0], [%1], 16;" :: "r"(saddr), "l"(g));
}

#define HG_SMEM_BYTES 65536

template<int EPI>
__global__ __launch_bounds__(256) void hgemm(HArgs h0, HArgs h1, int nchunks, int ldc)
{
    extern __shared__ unsigned sm[];
    const unsigned sbase = (unsigned)__cvta_generic_to_shared(sm);
    HArgs h = blockIdx.z ? h1 : h0;
    const int tid = threadIdx.x, lane = tid & 31, wid = tid >> 5;
    const int warp_m = wid & 1, warp_n = wid >> 1;
    const unsigned* gAh = g_hi + h.aoff + (size_t)blockIdx.y * nchunks * 2048;
    const unsigned* gAl = g_lo + h.aoff + (size_t)blockIdx.y * nchunks * 2048;
    const unsigned* gBh = g_hi + h.boff + (size_t)blockIdx.x * nchunks * 2048;
    const unsigned* gBl = g_lo + h.boff + (size_t)blockIdx.x * nchunks * 2048;

    auto issue = [&](int s, int c) {
        const unsigned dst = sbase + s * 32768;
        const unsigned* srcs[4] = {gAh + c*2048, gAl + c*2048, gBh + c*2048, gBl + c*2048};
#pragma unroll
        for (int p = 0; p < 4; p++)
#pragma unroll
            for (int q = 0; q < 2; q++) {
                const int o = (tid + q*256) * 4;
                cp16(dst + p*8192 + o*4, srcs[p] + o);
            }
        asm volatile("cp.async.commit_group;");
    };

    float acc[4][4][4];
#pragma unroll
    for (int mt = 0; mt < 4; mt++)
#pragma unroll
        for (int nt = 0; nt < 4; nt++)
#pragma unroll
            for (int j = 0; j < 4; j++) acc[mt][nt][j] = 0.f;

    issue(0, 0);
    for (int c = 0; c < nchunks; c++) {
        if (c + 1 < nchunks) {
            issue((c + 1) & 1, c + 1);
            asm volatile("cp.async.wait_group 1;");
        } else {
            asm volatile("cp.async.wait_group 0;");
        }
        __syncthreads();
        const unsigned* st  = sm + (c & 1) * 8192;
        const unsigned* sAh = st;
        const unsigned* sAl = st + 2048;
        const unsigned* sBh = st + 4096;
        const unsigned* sBl = st + 6144;
#pragma unroll
        for (int ks = 0; ks < 2; ks++) {
            unsigned ah[4][4], al[4][4], bh[4][2], bl[4][2];
#pragma unroll
            for (int mt = 0; mt < 4; mt++) {
                const int base = (((warp_m*4 + mt)*2 + ks)*32 + lane) * 4;
                uint4 v = *reinterpret_cast<const uint4*>(sAh + base);
                ah[mt][0]=v.x; ah[mt][1]=v.y; ah[mt][2]=v.z; ah[mt][3]=v.w;
                v = *reinterpret_cast<const uint4*>(sAl + base);
                al[mt][0]=v.x; al[mt][1]=v.y; al[mt][2]=v.z; al[mt][3]=v.w;
            }
#pragma unroll
            for (int nt = 0; nt < 4; nt++) {
                const int base = (((warp_n*4 + nt)*2 + ks)*32 + lane) * 2;
                uint2 v = *reinterpret_cast<const uint2*>(sBh + base);
                bh[nt][0]=v.x; bh[nt][1]=v.y;
                v = *reinterpret_cast<const uint2*>(sBl + base);
                bl[nt][0]=v.x; bl[nt][1]=v.y;
            }
#pragma unroll
            for (int mt = 0; mt < 4; mt++)
#pragma unroll
                for (int nt = 0; nt < 4; nt++) mma_h(acc[mt][nt], ah[mt], bh[nt]);
#pragma unroll
            for (int mt = 0; mt < 4; mt++)
#pragma unroll
                for (int nt = 0; nt < 4; nt++) mma_h(acc[mt][nt], ah[mt], bl[nt]);
#pragma unroll
            for (int mt = 0; mt < 4; mt++)
#pragma unroll
                for (int nt = 0; nt < 4; nt++) mma_h(acc[mt][nt], al[mt], bh[nt]);
        }
        __syncthreads();
    }

    const int row0 = blockIdx.y * 128, col0 = blockIdx.x * 128;
    const int rw = lane >> 2;
    const int cw = (lane & 3) * 2;
#pragma unroll
    for (int mt = 0; mt < 4; mt++) {
        const int m = row0 + warp_m*64 + mt*16 + rw;
#pragma unroll
        for (int nt = 0; nt < 4; nt++) {
            const int n = col0 + warp_n*32 + nt*8 + cw;
            float v0 = acc[mt][nt][0], v1 = acc[mt][nt][1];
            float v2 = acc[mt][nt][2], v3 = acc[mt][nt][3];
            if (EPI == 1) {
                const float b0 = __ldg(h.bias + n);
                const float b1 = __ldg(h.bias + n + 1);
                v0 = softplusf(v0 + b0); v1 = softplusf(v1 + b1);
                v2 = softplusf(v2 + b0); v3 = softplusf(v3 + b1);
            }
            *reinterpret_cast<float2*>(h.C + (size_t)m * ldc + n)       = make_float2(v0, v1);
            *reinterpret_cast<float2*>(h.C + (size_t)(m + 8) * ldc + n) = make_float2(v2, v3);
        }
    }
}

// ---------------------------------------------------------------------------
// G3 split-K SIMT GEMM: partial[dir][split] = u[:, ks] @ xw[:, ks]^T
// M=1024, N=96, K-split = 512 per block set. grid (3, 16, 8): z = dir*4+split
// ---------------------------------------------------------------------------
__global__ __launch_bounds__(256)
void sgemm_g3_split(const float* __restrict__ u, const float* xw_f, const float* xw_b)
{
    constexpr int BM = 64, BN = 32, TM = 4, TN = 2, BK = 32, THREADS = 256, KV = BK/4;
    constexpr int KSEG = ID / 4;   // 512
    __shared__ float As[BK][BM];
    __shared__ float Bs[BK][BN];
    const int dir   = blockIdx.z >> 2;
    const int split = blockIdx.z & 3;
    const float* B = dir ? xw_b : xw_f;
    const int tid  = threadIdx.x;
    const int row0 = blockIdx.y * BM;
    const int col0 = blockIdx.x * BN;
    const int kbeg = split * KSEG;
    const float* __restrict__ Ap = u + (size_t)row0 * ID + kbeg;
    const float* __restrict__ Bp = B + (size_t)col0 * ID + kbeg;
    float acc[TM][TN];
#pragma unroll
    for (int i = 0; i < TM; i++) { acc[i][0] = 0.f; acc[i][1] = 0.f; }
    const int tcol = tid % (BN/TN);
    const int trow = tid / (BN/TN);
    for (int k0 = 0; k0 < KSEG; k0 += BK) {
#pragma unroll
        for (int idx = tid; idx < BM*KV; idx += THREADS) {
            int rr = idx / KV, kv = idx % KV;
            float4 v = *reinterpret_cast<const float4*>(Ap + (size_t)rr*ID + k0 + kv*4);
            As[kv*4+0][rr] = v.x; As[kv*4+1][rr] = v.y;
            As[kv*4+2][rr] = v.z; As[kv*4+3][rr] = v.w;
        }
#pragma unroll
        for (int idx = tid; idx < BN*KV; idx += THREADS) {
            int rr = idx / KV, kv = idx % KV;
            float4 v = *reinterpret_cast<const float4*>(Bp + (size_t)rr*ID + k0 + kv*4);
            Bs[kv*4+0][rr] = v.x; Bs[kv*4+1][rr] = v.y;
            Bs[kv*4+2][rr] = v.z; Bs[kv*4+3][rr] = v.w;
        }
        __syncthreads();
#pragma unroll
        for (int k = 0; k < BK; k++) {
            float a[TM], b[TN];
#pragma unroll
            for (int i = 0; i < TM; i += 4) {
                float4 v = *reinterpret_cast<const float4*>(&As[k][trow*TM + i]);
                a[i] = v.x; a[i+1] = v.y; a[i+2] = v.z; a[i+3] = v.w;
            }
            float2 v2 = *reinterpret_cast<const float2*>(&Bs[k][tcol*TN]);
            b[0] = v2.x; b[1] = v2.y;
#pragma unroll
            for (int i = 0; i < TM; i++) {
                acc[i][0] = fmaf(a[i], b[0], acc[i][0]);
                acc[i][1] = fmaf(a[i], b[1], acc[i][1]);
            }
        }
        __syncthreads();
    }
    float* dst = g_part[dir][split];
    const int c0 = col0 + tcol*TN;
#pragma unroll
    for (int i = 0; i < TM; i++) {
        const int R = row0 + trow*TM + i;
        *reinterpret_cast<float2*>(dst + (size_t)R*96 + c0) = make_float2(acc[i][0], acc[i][1]);
    }
}

// ---------------------------------------------------------------------------
// reduce partials; dt cols -> split planes (A-frag layout), B/C cols -> g_ssm
// idx over 2 dirs x 1024 rows x 48 col-pairs
// ---------------------------------------------------------------------------
__global__ __launch_bounds__(256) void reduce_pack_g3()
{
    const int idx = blockIdx.x * blockDim.x + threadIdx.x;   // < 2*1024*48
    const int pr  = idx % 48;
    const int R   = (idx / 48) % ML;
    const int dir = idx / (48 * ML);
    const int c0  = pr * 2;
    const size_t o = (size_t)R * 96 + c0;
    float2 s = make_float2(0.f, 0.f);
#pragma unroll
    for (int p = 0; p < 4; p++) {
        float2 v = *reinterpret_cast<const float2*>(g_part[dir][p] + o);
        s.x += v.x; s.y += v.y;
    }
    if (c0 < 64) {
        unsigned ph, pl;
        split_pack(s.x, s.y, ph, pl);
        const unsigned uoff = dir ? U_SSM1_A : U_SSM0_A;
        const int d = uoff + ((R >> 7) * 2 + (c0 >> 5)) * 2048 + afrag_idx(R & 127, c0 & 31);
        g_hi[d] = ph; g_lo[d] = pl;
    } else {
        *reinterpret_cast<float2*>(g_ssm[dir] + o) = s;
    }
}

// ---------------------------------------------------------------------------
// conv + silu
// ---------------------------------------------------------------------------
__global__ void conv_silu_kernel(const float* __restrict__ w,
                                 const float* __restrict__ bias)
{
    int idx = blockIdx.x * blockDim.x + threadIdx.x;
    int i = idx % ID;
    int l = (idx / ID) % LL;
    float acc = bias[i];
#pragma unroll
    for (int k = 0; k < 4; k++) {
        int ls = l - 3 + k;
        if (ls >= 0) acc = fmaf(g_x[(size_t)idx + (ptrdiff_t)(k-3)*ID], w[i*4 + k], acc);
    }
    g_u[idx] = siluf(acc);
}

// ---------------------------------------------------------------------------
// selective scan
// ---------------------------------------------------------------------------
__global__ void scan_kernel(const float* __restrict__ Alog_f,
                            const float* __restrict__ Alog_b,
                            const float* __restrict__ D_f,
                            const float* __restrict__ D_b)
{
    int gw   = (blockIdx.x * blockDim.x + threadIdx.x) >> 5;
    int lane = threadIdx.x & 31;
    int dir  = gw >> 11;
    int b    = (gw >> 10) & 1;
    int i    = ((gw & 1023) << 1) | (lane >> 4);
    int n    = lane & 15;

    const float* Alog = dir ? Alog_b : Alog_f;
    float An = -expf(Alog[i*NSTATE + n]);
    float Dv = dir ? D_b[i] : D_f[i];

    const float* dbase = g_delta[dir] + (size_t)(b*LL)*ID + i;
    const float* ubase = g_u          + (size_t)(b*LL)*ID + i;
    const float* sbase = g_ssm[dir]   + (size_t)(b*LL)*96;
    float*       ybase = g_y[dir]     + (size_t)(b*LL)*ID + i;

    int l0 = dir ? (LL-1) : 0;
    ptrdiff_t dstep = dir ? -(ptrdiff_t)ID : (ptrdiff_t)ID;
    ptrdiff_t sstep = dir ? -96 : 96;

    const float* dp = dbase + (size_t)l0*ID;
    const float* up = ubase + (size_t)l0*ID;
    const float* sp = sbase + (size_t)l0*96;
    float*       yp = ybase + (size_t)l0*ID;

    float x = 0.f;
#pragma unroll 2
    for (int t = 0; t < LL; t++) {
        float d  = *dp;
        float uu = *up;
        float Bv = *(sp + RD + n);
        float Cv = *(sp + RD + NSTATE + n);
        float dA = __expf(d * An);
        x = fmaf(x, dA, d * Bv * uu);
        float p = x * Cv;
        p += __shfl_xor_sync(0xffffffffu, p, 1);
        p += __shfl_xor_sync(0xffffffffu, p, 2);
        p += __shfl_xor_sync(0xffffffffu, p, 4);
        p += __shfl_xor_sync(0xffffffffu, p, 8);
        if (n == 0) *yp = fmaf(uu, Dv, p);
        dp += dstep; up += dstep; sp += sstep; yp += dstep;
    }
}

// ---------------------------------------------------------------------------
// combine: yt = (yf+yb)*silu(gate), written directly as split planes (A layout)
// ---------------------------------------------------------------------------
__global__ __launch_bounds__(256) void combine_kernel()
{
    const int idx = blockIdx.x * blockDim.x + threadIdx.x;   // over ML*ID/2
    const int R  = idx >> 10;
    const int ch = (idx & 1023) << 1;
    const size_t o = (size_t)R * ID + ch;
    float2 yf = *reinterpret_cast<const float2*>(g_y[0] + o);
    float2 yb = *reinterpret_cast<const float2*>(g_y[1] + o);
    float2 gt = *reinterpret_cast<const float2*>(g_gate + o);
    float yt0 = (yf.x + yb.x) * siluf(gt.x);
    float yt1 = (yf.y + yb.y) * siluf(gt.y);
    unsigned ph, pl;
    split_pack(yt0, yt1, ph, pl);
    const int d = U_YT_A + ((R >> 7) * 64 + (ch >> 5)) * 2048 + afrag_idx(R & 127, ch & 31);
    g_hi[d] = ph; g_lo[d] = pl;
}

// ---------------------------------------------------------------------------
// Launch
// ---------------------------------------------------------------------------
extern "C" void kernel_launch(void* const* d_in, const int* in_sizes, int n_in,
                              void* d_out, int out_size)
{
    const float* hs     = (const float*)d_in[0];
    const float* hs2    = (const float*)d_in[1];
    const float* in_w   = (const float*)d_in[2];
    const float* in_dw  = (const float*)d_in[3];
    const float* conv_w = (const float*)d_in[4];
    const float* conv_b = (const float*)d_in[5];
    const float* xw_f   = (const float*)d_in[6];
    const float* xw_b   = (const float*)d_in[7];
    const float* dtw_f  = (const float*)d_in[8];
    const float* dtb_f  = (const float*)d_in[9];
    const float* dtw_b  = (const float*)d_in[10];
    const float* dtb_b  = (const float*)d_in[11];
    const float* Alog_f = (const float*)d_in[12];
    const float* Alog_b = (const float*)d_in[13];
    const float* D_f    = (const float*)d_in[14];
    const float* D_b    = (const float*)d_in[15];
    const float* outw   = (const float*)d_in[16];
    float* out = (float*)d_out;

    float *px, *pgate, *pu, *pdelta;
    cudaGetSymbolAddress((void**)&px,     g_x);
    cudaGetSymbolAddress((void**)&pgate,  g_gate);
    cudaGetSymbolAddress((void**)&pu,     g_u);
    cudaGetSymbolAddress((void**)&pdelta, g_delta);
    float* pd0 = pdelta;
    float* pd1 = pdelta + (size_t)ML*ID;

    cudaFuncSetAttribute(hgemm<0>, cudaFuncAttributeMaxDynamicSharedMemorySize, HG_SMEM_BYTES);
    cudaFuncSetAttribute(hgemm<1>, cudaFuncAttributeMaxDynamicSharedMemorySize, HG_SMEM_BYTES);

    // Batched conversions (weights + inputs) in ONE launch
    {
        CTable t;
        t.d[0] = {in_w,                  U_INW_B,  HD, 32, 512, 0};
        t.d[1] = {in_dw + (size_t)ID*HD, U_INDW_B, HD, 32, 512, 0};
        t.d[2] = {dtw_f,                 U_DTW0_B, RD, 2,  32,  0};
        t.d[3] = {dtw_b,                 U_DTW1_B, RD, 2,  32,  0};
        t.d[4] = {outw,                  U_OUTW_B, ID, 64, 512, 0};
        t.d[5] = {hs,                    U_HS_A,   HD, 32, 256, 1};
        t.d[6] = {hs2,                   U_HS2_A,  HD, 32, 256, 1};
        conv_all<<<2112, 256>>>(t);
    }

    // G1: x = hs @ in_w[:I]^T ; gate = hs2 @ in_dw[I:2I]^T
    {
        HArgs a{U_HS_A,  U_INW_B,  px,    nullptr};
        HArgs b{U_HS2_A, U_INDW_B, pgate, nullptr};
        hgemm<0><<<dim3(ID/128, ML/128, 2), 256, HG_SMEM_BYTES>>>(a, b, 32, ID);
    }

    conv_silu_kernel<<<(ML*ID)/256, 256>>>(conv_w, conv_b);

    // G3: split-K partials then reduce+pack
    sgemm_g3_split<<<dim3(96/32, ML/64, 8), 256>>>(pu, xw_f, xw_b);
    reduce_pack_g3<<<(2*ML*48)/256, 256>>>();

    // G4: delta = softplus(dt @ dt_w^T + b)
    {
        HArgs a{U_SSM0_A, U_DTW0_B, pd0, dtb_f};
        HArgs b{U_SSM1_A, U_DTW1_B, pd1, dtb_b};
        hgemm<1><<<dim3(ID/128, ML/128, 2), 256, HG_SMEM_BYTES>>>(a, b, 2, ID);
    }

    scan_kernel<<<512, 256>>>(Alog_f, Alog_b, D_f, D_b);
    combine_kernel<<<(ML*ID)/512, 256>>>();

    // G5: out = yt @ out_proj_w^T
    {
        HArgs a{U_YT_A, U_OUTW_B, out, nullptr};
        hgemm<0><<<dim3(HD/128, ML/128, 1), 256, HG_SMEM_BYTES>>>(a, a, 64, HD);
    }

    (void)in_sizes; (void)n_in; (void)out_size;
}

// round 9
// speedup vs baseline: 1.1494x; 1.0434x over previous
#include <cuda_runtime.h>
#include <cuda_fp16.h>
#include <cstdint>
#include <cstddef>

// Problem constants
#define HD 1024
#define ID 2048
#define NSTATE 16
#define RD 64
#define BB 2
#define LL 512
#define ML (BB*LL)

// ---------------------------------------------------------------------------
// Scratch
// ---------------------------------------------------------------------------
__device__ __align__(16) float g_x   [(size_t)ML*ID];
__device__ __align__(16) float g_gate[(size_t)ML*ID];
__device__ __align__(16) float g_u   [(size_t)ML*ID];
__device__ __align__(16) float g_ssm [2][(size_t)ML*96];    // only cols 64..95 read (B|C)
__device__ __align__(16) float g_part[2][4][(size_t)ML*96]; // split-K partials for G3
__device__ __align__(16) float g_delta[2][(size_t)ML*ID];
__device__ __align__(16) float g_y   [2][(size_t)ML*ID];

// fp16 split-plane pools (fragment-packed u32 = half2 pairs)
#define U_HS_A    0u
#define U_HS2_A   524288u
#define U_INW_B   1048576u
#define U_INDW_B  2097152u
#define U_SSM0_A  3145728u
#define U_SSM1_A  3178496u
#define U_DTW0_B  3211264u
#define U_DTW1_B  3276800u
#define U_YT_A    3342336u
#define U_OUTW_B  4390912u
#define U_U_A     5439488u
#define U_XW0_B   6488064u
#define U_XW1_B   6619136u
#define U_TOTAL   6750208u
__device__ __align__(16) unsigned g_hi[U_TOTAL];
__device__ __align__(16) unsigned g_lo[U_TOTAL];

__device__ __forceinline__ float siluf(float v)     { return v * (1.0f / (1.0f + __expf(-v))); }
__device__ __forceinline__ float softplusf(float v) { return v > 20.f ? v : log1pf(__expf(v)); }

__device__ __forceinline__ void split_pack(float x0, float x1, unsigned& ph, unsigned& pl) {
    __half h0 = __float2half_rn(x0), h1 = __float2half_rn(x1);
    __half l0 = __float2half_rn(x0 - __half2float(h0));
    __half l1 = __float2half_rn(x1 - __half2float(h1));
    ph = ((unsigned)__half_as_ushort(h1) << 16) | __half_as_ushort(h0);
    pl = ((unsigned)__half_as_ushort(l1) << 16) | __half_as_ushort(l0);
}

// A-fragment u32 index within a 128x32 chunk, for element pair (r, k even)
__device__ __forceinline__ int afrag_idx(int r, int k) {
    int mt = r >> 4, rr = r & 15;
    int ks = k >> 4, kk = k & 15;
    int lane = ((rr & 7) << 2) | ((kk >> 1) & 3);
    int reg  = (rr >> 3) | ((kk >> 3) << 1);
    return ((mt * 2 + ks) * 32 + lane) * 4 + reg;
}

// ---------------------------------------------------------------------------
// Batched converter: fp32 -> fragment-packed fp16 hi/lo planes.
// nrows < 128 pads the tail rows with zeros (for N=96 B matrices).
// ---------------------------------------------------------------------------
struct CDesc { const float* src; unsigned off; int ld; int nchunks; int nblk; int isA; int nrows; };
struct CTable { CDesc d[9]; };

__global__ __launch_bounds__(256) void conv_all(CTable t)
{
    __shared__ float s[128][33];
    int b = blockIdx.x;
    int di = 0;
    while (b >= t.d[di].nblk) { b -= t.d[di].nblk; di++; }
    const CDesc d = t.d[di];
    const int rb = b / d.nchunks, c = b % d.nchunks;
    const int tid = threadIdx.x;
    const float* sp = d.src + (size_t)(rb * 128) * d.ld + c * 32;
#pragma unroll
    for (int it = 0; it < 4; it++) {
        int r = (tid >> 3) + it * 32, c4 = tid & 7;
        float4 v = make_float4(0.f, 0.f, 0.f, 0.f);
        if (r < d.nrows)
            v = *reinterpret_cast<const float4*>(sp + (size_t)r * d.ld + c4 * 4);
        s[r][c4*4+0]=v.x; s[r][c4*4+1]=v.y; s[r][c4*4+2]=v.z; s[r][c4*4+3]=v.w;
    }
    __syncthreads();
    unsigned* oh = g_hi + d.off + (size_t)(rb * d.nchunks + c) * 2048;
    unsigned* ol = g_lo + d.off + (size_t)(rb * d.nchunks + c) * 2048;
    if (d.isA) {
#pragma unroll
        for (int j = 0; j < 8; j++) {
            int idx = tid + 256*j;
            int reg = idx&3, lane=(idx>>2)&31, ks=(idx>>7)&1, mt=idx>>8;
            int r = mt*16 + ((reg&1)<<3) + (lane>>2);
            int k = ks*16 + ((reg>>1)<<3) + ((lane&3)<<1);
            unsigned ph, pl;
            split_pack(s[r][k], s[r][k+1], ph, pl);
            oh[idx] = ph; ol[idx] = pl;
        }
    } else {
#pragma unroll
        for (int j = 0; j < 8; j++) {
            int idx = tid + 256*j;
            int reg = idx&1, lane=(idx>>1)&31, ks=(idx>>6)&1, nt=idx>>7;
            int n = nt*8 + (lane>>2);
            int k = ks*16 + reg*8 + ((lane&3)<<1);
            unsigned ph, pl;
            split_pack(s[n][k], s[n][k+1], ph, pl);
            oh[idx] = ph; ol[idx] = pl;
        }
    }
}

// ---------------------------------------------------------------------------
// fp16 3-pass split GEMM core pieces
// ---------------------------------------------------------------------------
struct HArgs { unsigned aoff; unsigned boff; float* C; const float* bias; };

__device__ __forceinline__ void mma_h(float* c, const unsigned* a, const unsigned* b) {
    asm volatile(
        "mma.sync.aligned.m16n8k16.row.col.f32.f16.f16.f32 "
        "{%0,%1,%2,%3},{%4,%5,%6,%7},{%8,%9},{%0,%1,%2,%3};"
        : "+f"(c[0]), "+f"(c[1]), "+f"(c[2]), "+f"(c[3])
        : "r"(a[0]), "r"(a[1]), "r"(a[2]), "r"(a[3]), "r"(b[0]), "r"(b[1]));
}
__device__ __forceinline__ void cp16(unsigned saddr, const void* g) {
    asm volatile("cp.async.cg.shared.global [%0], [%1], 16;" :: "r"(saddr), "l"(g));
}

#define HG_SMEM_BYTES 65536

// Shared mainloop: issues chunk range [c0, c1) from the given plane bases.
template<typename EpiFn>
__device__ __forceinline__ void hgemm_body(
    const unsigned* gAh, const unsigned* gAl,
    const unsigned* gBh, const unsigned* gBl,
    int c0, int c1, unsigned* sm, unsigned sbase,
    int tid, int lane, int warp_m, int warp_n, EpiFn epi)
{
    auto issue = [&](int s, int c) {
        const unsigned dst = sbase + s * 32768;
        const unsigned* srcs[4] = {gAh + (size_t)c*2048, gAl + (size_t)c*2048,
                                   gBh + (size_t)c*2048, gBl + (size_t)c*2048};
#pragma unroll
        for (int p = 0; p < 4; p++)
#pragma unroll
            for (int q = 0; q < 2; q++) {
                const int o = (tid + q*256) * 4;
                cp16(dst + p*8192 + o*4, srcs[p] + o);
            }
        asm volatile("cp.async.commit_group;");
    };

    float acc[4][4][4];
#pragma unroll
    for (int mt = 0; mt < 4; mt++)
#pragma unroll
        for (int nt = 0; nt < 4; nt++)
#pragma unroll
            for (int j = 0; j < 4; j++) acc[mt][nt][j] = 0.f;

    issue(0, c0);
    for (int c = c0; c < c1; c++) {
        if (c + 1 < c1) {
            issue((c + 1) & 1, c + 1);
            asm volatile("cp.async.wait_group 1;");
        } else {
            asm volatile("cp.async.wait_group 0;");
        }
        __syncthreads();
        const unsigned* st  = sm + (c & 1) * 8192;
        const unsigned* sAh = st;
        const unsigned* sAl = st + 2048;
        const unsigned* sBh = st + 4096;
        const unsigned* sBl = st + 6144;
#pragma unroll
        for (int ks = 0; ks < 2; ks++) {
            unsigned ah[4][4], al[4][4], bh[4][2], bl[4][2];
#pragma unroll
            for (int mt = 0; mt < 4; mt++) {
                const int base = (((warp_m*4 + mt)*2 + ks)*32 + lane) * 4;
                uint4 v = *reinterpret_cast<const uint4*>(sAh + base);
                ah[mt][0]=v.x; ah[mt][1]=v.y; ah[mt][2]=v.z; ah[mt][3]=v.w;
                v = *reinterpret_cast<const uint4*>(sAl + base);
                al[mt][0]=v.x; al[mt][1]=v.y; al[mt][2]=v.z; al[mt][3]=v.w;
            }
#pragma unroll
            for (int nt = 0; nt < 4; nt++) {
                const int base = (((warp_n*4 + nt)*2 + ks)*32 + lane) * 2;
                uint2 v = *reinterpret_cast<const uint2*>(sBh + base);
                bh[nt][0]=v.x; bh[nt][1]=v.y;
                v = *reinterpret_cast<const uint2*>(sBl + base);
                bl[nt][0]=v.x; bl[nt][1]=v.y;
            }
#pragma unroll
            for (int mt = 0; mt < 4; mt++)
#pragma unroll
                for (int nt = 0; nt < 4; nt++) mma_h(acc[mt][nt], ah[mt], bh[nt]);
#pragma unroll
            for (int mt = 0; mt < 4; mt++)
#pragma unroll
                for (int nt = 0; nt < 4; nt++) mma_h(acc[mt][nt], ah[mt], bl[nt]);
#pragma unroll
            for (int mt = 0; mt < 4; mt++)
#pragma unroll
                for (int nt = 0; nt < 4; nt++) mma_h(acc[mt][nt], al[mt], bh[nt]);
        }
        __syncthreads();
    }
    epi(acc);
}

template<int EPI>
__global__ __launch_bounds__(256) void hgemm(HArgs h0, HArgs h1, int nchunks, int ldc)
{
    extern __shared__ unsigned sm[];
    const unsigned sbase = (unsigned)__cvta_generic_to_shared(sm);
    HArgs h = blockIdx.z ? h1 : h0;
    const int tid = threadIdx.x, lane = tid & 31, wid = tid >> 5;
    const int warp_m = wid & 1, warp_n = wid >> 1;
    const unsigned* gAh = g_hi + h.aoff + (size_t)blockIdx.y * nchunks * 2048;
    const unsigned* gAl = g_lo + h.aoff + (size_t)blockIdx.y * nchunks * 2048;
    const unsigned* gBh = g_hi + h.boff + (size_t)blockIdx.x * nchunks * 2048;
    const unsigned* gBl = g_lo + h.boff + (size_t)blockIdx.x * nchunks * 2048;
    const int row0 = blockIdx.y * 128, col0 = blockIdx.x * 128;
    const int rw = lane >> 2, cw = (lane & 3) * 2;

    hgemm_body(gAh, gAl, gBh, gBl, 0, nchunks, sm, sbase, tid, lane, warp_m, warp_n,
        [&](float acc[4][4][4]) {
#pragma unroll
            for (int mt = 0; mt < 4; mt++) {
                const int m = row0 + warp_m*64 + mt*16 + rw;
#pragma unroll
                for (int nt = 0; nt < 4; nt++) {
                    const int n = col0 + warp_n*32 + nt*8 + cw;
                    float v0 = acc[mt][nt][0], v1 = acc[mt][nt][1];
                    float v2 = acc[mt][nt][2], v3 = acc[mt][nt][3];
                    if (EPI == 1) {
                        const float b0 = __ldg(h.bias + n);
                        const float b1 = __ldg(h.bias + n + 1);
                        v0 = softplusf(v0 + b0); v1 = softplusf(v1 + b1);
                        v2 = softplusf(v2 + b0); v3 = softplusf(v3 + b1);
                    }
                    *reinterpret_cast<float2*>(h.C + (size_t)m * ldc + n)       = make_float2(v0, v1);
                    *reinterpret_cast<float2*>(h.C + (size_t)(m + 8) * ldc + n) = make_float2(v2, v3);
                }
            }
        });
}

// G3 tensor GEMM: partial[dir][split] = u[mblock, Kseg] @ xw^T (N=96 padded to 128)
// grid (8 mblocks, 8 = dir*4+split)
__global__ __launch_bounds__(256) void hgemm_g3()
{
    extern __shared__ unsigned sm[];
    const unsigned sbase = (unsigned)__cvta_generic_to_shared(sm);
    const int mblock = blockIdx.x;
    const int dir = blockIdx.y >> 2, split = blockIdx.y & 3;
    const int tid = threadIdx.x, lane = tid & 31, wid = tid >> 5;
    const int warp_m = wid & 1, warp_n = wid >> 1;
    const unsigned* gAh = g_hi + U_U_A + (size_t)mblock * 64 * 2048;
    const unsigned* gAl = g_lo + U_U_A + (size_t)mblock * 64 * 2048;
    const unsigned xoff = dir ? U_XW1_B : U_XW0_B;
    const unsigned* gBh = g_hi + xoff;
    const unsigned* gBl = g_lo + xoff;
    const int row0 = mblock * 128;
    const int rw = lane >> 2, cw = (lane & 3) * 2;
    float* C = g_part[dir][split];

    hgemm_body(gAh, gAl, gBh, gBl, split*16, split*16 + 16, sm, sbase, tid, lane, warp_m, warp_n,
        [&](float acc[4][4][4]) {
#pragma unroll
            for (int mt = 0; mt < 4; mt++) {
                const int m = row0 + warp_m*64 + mt*16 + rw;
#pragma unroll
                for (int nt = 0; nt < 4; nt++) {
                    const int n = warp_n*32 + nt*8 + cw;
                    if (n < 96) {
                        *reinterpret_cast<float2*>(C + (size_t)m * 96 + n) =
                            make_float2(acc[mt][nt][0], acc[mt][nt][1]);
                        *reinterpret_cast<float2*>(C + (size_t)(m + 8) * 96 + n) =
                            make_float2(acc[mt][nt][2], acc[mt][nt][3]);
                    }
                }
            }
        });
}

// ---------------------------------------------------------------------------
// reduce partials; dt cols -> split planes (A-frag layout), B/C cols -> g_ssm
// ---------------------------------------------------------------------------
__global__ __launch_bounds__(256) void reduce_pack_g3()
{
    const int idx = blockIdx.x * blockDim.x + threadIdx.x;   // < 2*1024*48
    const int pr  = idx % 48;
    const int R   = (idx / 48) % ML;
    const int dir = idx / (48 * ML);
    const int c0  = pr * 2;
    const size_t o = (size_t)R * 96 + c0;
    float2 s = make_float2(0.f, 0.f);
#pragma unroll
    for (int p = 0; p < 4; p++) {
        float2 v = *reinterpret_cast<const float2*>(g_part[dir][p] + o);
        s.x += v.x; s.y += v.y;
    }
    if (c0 < 64) {
        unsigned ph, pl;
        split_pack(s.x, s.y, ph, pl);
        const unsigned uoff = dir ? U_SSM1_A : U_SSM0_A;
        const int d = uoff + ((R >> 7) * 2 + (c0 >> 5)) * 2048 + afrag_idx(R & 127, c0 & 31);
        g_hi[d] = ph; g_lo[d] = pl;
    } else {
        *reinterpret_cast<float2*>(g_ssm[dir] + o) = s;
    }
}

// ---------------------------------------------------------------------------
// conv + silu; also emits u as A-fragment split planes for tensor G3
// ---------------------------------------------------------------------------
__global__ __launch_bounds__(256) void conv_silu_kernel(const float* __restrict__ w,
                                                        const float* __restrict__ bias)
{
    const int idx = blockIdx.x * blockDim.x + threadIdx.x;   // < ML*ID/2
    const int R  = idx >> 10;
    const int ch = (idx & 1023) << 1;
    const int l  = R & (LL - 1);
    const size_t o = (size_t)R * ID + ch;
    float acc0 = bias[ch], acc1 = bias[ch + 1];
#pragma unroll
    for (int k = 0; k < 4; k++) {
        int ls = l - 3 + k;
        if (ls >= 0) {
            float2 xv = *reinterpret_cast<const float2*>(g_x + o + (ptrdiff_t)(k - 3) * ID);
            acc0 = fmaf(xv.x, w[ch*4 + k],       acc0);
            acc1 = fmaf(xv.y, w[(ch+1)*4 + k],   acc1);
        }
    }
    float u0 = siluf(acc0), u1 = siluf(acc1);
    *reinterpret_cast<float2*>(g_u + o) = make_float2(u0, u1);
    unsigned ph, pl;
    split_pack(u0, u1, ph, pl);
    const int d = U_U_A + ((R >> 7) * 64 + (ch >> 5)) * 2048 + afrag_idx(R & 127, ch & 31);
    g_hi[d] = ph; g_lo[d] = pl;
}

// ---------------------------------------------------------------------------
// selective scan
// ---------------------------------------------------------------------------
__global__ void scan_kernel(const float* __restrict__ Alog_f,
                            const float* __restrict__ Alog_b,
                            const float* __restrict__ D_f,
                            const float* __restrict__ D_b)
{
    int gw   = (blockIdx.x * blockDim.x + threadIdx.x) >> 5;
    int lane = threadIdx.x & 31;
    int dir  = gw >> 11;
    int b    = (gw >> 10) & 1;
    int i    = ((gw & 1023) << 1) | (lane >> 4);
    int n    = lane & 15;

    const float* Alog = dir ? Alog_b : Alog_f;
    float An = -expf(Alog[i*NSTATE + n]);
    float Dv = dir ? D_b[i] : D_f[i];

    const float* dbase = g_delta[dir] + (size_t)(b*LL)*ID + i;
    const float* ubase = g_u          + (size_t)(b*LL)*ID + i;
    const float* sbase = g_ssm[dir]   + (size_t)(b*LL)*96;
    float*       ybase = g_y[dir]     + (size_t)(b*LL)*ID + i;

    int l0 = dir ? (LL-1) : 0;
    ptrdiff_t dstep = dir ? -(ptrdiff_t)ID : (ptrdiff_t)ID;
    ptrdiff_t sstep = dir ? -96 : 96;

    const float* dp = dbase + (size_t)l0*ID;
    const float* up = ubase + (size_t)l0*ID;
    const float* sp = sbase + (size_t)l0*96;
    float*       yp = ybase + (size_t)l0*ID;

    float x = 0.f;
#pragma unroll 2
    for (int t = 0; t < LL; t++) {
        float d  = *dp;
        float uu = *up;
        float Bv = *(sp + RD + n);
        float Cv = *(sp + RD + NSTATE + n);
        float dA = __expf(d * An);
        x = fmaf(x, dA, d * Bv * uu);
        float p = x * Cv;
        p += __shfl_xor_sync(0xffffffffu, p, 1);
        p += __shfl_xor_sync(0xffffffffu, p, 2);
        p += __shfl_xor_sync(0xffffffffu, p, 4);
        p += __shfl_xor_sync(0xffffffffu, p, 8);
        if (n == 0) *yp = fmaf(uu, Dv, p);
        dp += dstep; up += dstep; sp += sstep; yp += dstep;
    }
}

// ---------------------------------------------------------------------------
// combine: yt = (yf+yb)*silu(gate), written directly as split planes (A layout)
// ---------------------------------------------------------------------------
__global__ __launch_bounds__(256) void combine_kernel()
{
    const int idx = blockIdx.x * blockDim.x + threadIdx.x;   // over ML*ID/2
    const int R  = idx >> 10;
    const int ch = (idx & 1023) << 1;
    const size_t o = (size_t)R * ID + ch;
    float2 yf = *reinterpret_cast<const float2*>(g_y[0] + o);
    float2 yb = *reinterpret_cast<const float2*>(g_y[1] + o);
    float2 gt = *reinterpret_cast<const float2*>(g_gate + o);
    float yt0 = (yf.x + yb.x) * siluf(gt.x);
    float yt1 = (yf.y + yb.y) * siluf(gt.y);
    unsigned ph, pl;
    split_pack(yt0, yt1, ph, pl);
    const int d = U_YT_A + ((R >> 7) * 64 + (ch >> 5)) * 2048 + afrag_idx(R & 127, ch & 31);
    g_hi[d] = ph; g_lo[d] = pl;
}

// ---------------------------------------------------------------------------
// Launch
// ---------------------------------------------------------------------------
extern "C" void kernel_launch(void* const* d_in, const int* in_sizes, int n_in,
                              void* d_out, int out_size)
{
    const float* hs     = (const float*)d_in[0];
    const float* hs2    = (const float*)d_in[1];
    const float* in_w   = (const float*)d_in[2];
    const float* in_dw  = (const float*)d_in[3];
    const float* conv_w = (const float*)d_in[4];
    const float* conv_b = (const float*)d_in[5];
    const float* xw_f   = (const float*)d_in[6];
    const float* xw_b   = (const float*)d_in[7];
    const float* dtw_f  = (const float*)d_in[8];
    const float* dtb_f  = (const float*)d_in[9];
    const float* dtw_b  = (const float*)d_in[10];
    const float* dtb_b  = (const float*)d_in[11];
    const float* Alog_f = (const float*)d_in[12];
    const float* Alog_b = (const float*)d_in[13];
    const float* D_f    = (const float*)d_in[14];
    const float* D_b    = (const float*)d_in[15];
    const float* outw   = (const float*)d_in[16];
    float* out = (float*)d_out;

    float *px, *pgate, *pdelta;
    cudaGetSymbolAddress((void**)&px,     g_x);
    cudaGetSymbolAddress((void**)&pgate,  g_gate);
    cudaGetSymbolAddress((void**)&pdelta, g_delta);
    float* pd0 = pdelta;
    float* pd1 = pdelta + (size_t)ML*ID;

    cudaFuncSetAttribute(hgemm<0>, cudaFuncAttributeMaxDynamicSharedMemorySize, HG_SMEM_BYTES);
    cudaFuncSetAttribute(hgemm<1>, cudaFuncAttributeMaxDynamicSharedMemorySize, HG_SMEM_BYTES);
    cudaFuncSetAttribute(hgemm_g3, cudaFuncAttributeMaxDynamicSharedMemorySize, HG_SMEM_BYTES);

    // Batched conversions (weights + inputs) in ONE launch
    {
        CTable t;
        t.d[0] = {in_w,                  U_INW_B,  HD, 32, 512, 0, 128};
        t.d[1] = {in_dw + (size_t)ID*HD, U_INDW_B, HD, 32, 512, 0, 128};
        t.d[2] = {dtw_f,                 U_DTW0_B, RD, 2,  32,  0, 128};
        t.d[3] = {dtw_b,                 U_DTW1_B, RD, 2,  32,  0, 128};
        t.d[4] = {outw,                  U_OUTW_B, ID, 64, 512, 0, 128};
        t.d[5] = {hs,                    U_HS_A,   HD, 32, 256, 1, 128};
        t.d[6] = {hs2,                   U_HS2_A,  HD, 32, 256, 1, 128};
        t.d[7] = {xw_f,                  U_XW0_B,  ID, 64, 64,  0, 96};
        t.d[8] = {xw_b,                  U_XW1_B,  ID, 64, 64,  0, 96};
        conv_all<<<2240, 256>>>(t);
    }

    // G1: x = hs @ in_w[:I]^T ; gate = hs2 @ in_dw[I:2I]^T
    {
        HArgs a{U_HS_A,  U_INW_B,  px,    nullptr};
        HArgs b{U_HS2_A, U_INDW_B, pgate, nullptr};
        hgemm<0><<<dim3(ID/128, ML/128, 2), 256, HG_SMEM_BYTES>>>(a, b, 32, ID);
    }

    // conv + silu (+ u split planes)
    conv_silu_kernel<<<(ML*ID)/512, 256>>>(conv_w, conv_b);

    // G3 on tensor cores: split-K partials then reduce+pack
    hgemm_g3<<<dim3(8, 8), 256, HG_SMEM_BYTES>>>();
    reduce_pack_g3<<<(2*ML*48)/256, 256>>>();

    // G4: delta = softplus(dt @ dt_w^T + b)
    {
        HArgs a{U_SSM0_A, U_DTW0_B, pd0, dtb_f};
        HArgs b{U_SSM1_A, U_DTW1_B, pd1, dtb_b};
        hgemm<1><<<dim3(ID/128, ML/128, 2), 256, HG_SMEM_BYTES>>>(a, b, 2, ID);
    }

    scan_kernel<<<512, 256>>>(Alog_f, Alog_b, D_f, D_b);
    combine_kernel<<<(ML*ID)/512, 256>>>();

    // G5: out = yt @ out_proj_w^T
    {
        HArgs a{U_YT_A, U_OUTW_B, out, nullptr};
        hgemm<0><<<dim3(HD/128, ML/128, 1), 256, HG_SMEM_BYTES>>>(a, a, 64, HD);
    }

    (void)in_sizes; (void)n_in; (void)out_size;
}

// round 12
// speedup vs baseline: 1.2598x; 1.0961x over previous
#include <cuda_runtime.h>
#include <cuda_fp16.h>
#include <cstdint>
#include <cstddef>

// Problem constants
#define HD 1024
#define ID 2048
#define NSTATE 16
#define RD 64
#define BB 2
#define LL 512
#define ML (BB*LL)

// ---------------------------------------------------------------------------
// Scratch
// ---------------------------------------------------------------------------
__device__ __align__(16) float g_x   [(size_t)ML*ID];
__device__ __align__(16) float g_gate[(size_t)ML*ID];
__device__ __align__(16) float g_u   [(size_t)ML*ID];
__device__ __align__(16) float g_ssm [2][(size_t)ML*96];    // only cols 64..95 read (B|C)
__device__ __align__(16) float g_part[2][4][(size_t)ML*96]; // split-K partials for G3
__device__ __align__(16) float g_delta[2][(size_t)ML*ID];
__device__ __align__(16) float g_y   [2][(size_t)ML*ID];

// fp16 split-plane pools (fragment-packed u32 = half2 pairs)
#define U_HS_A    0u
#define U_HS2_A   524288u
#define U_INW_B   1048576u
#define U_INDW_B  2097152u
#define U_SSM0_A  3145728u
#define U_SSM1_A  3178496u
#define U_DTW0_B  3211264u
#define U_DTW1_B  3276800u
#define U_YT_A    3342336u
#define U_OUTW_B  4390912u
#define U_U_A     5439488u
#define U_XW0_B   6488064u
#define U_XW1_B   6619136u
#define U_TOTAL   6750208u
__device__ __align__(16) unsigned g_hi[U_TOTAL];
__device__ __align__(16) unsigned g_lo[U_TOTAL];

__device__ __forceinline__ float siluf(float v)     { return v * (1.0f / (1.0f + __expf(-v))); }
__device__ __forceinline__ float softplusf(float v) { return v > 20.f ? v : log1pf(__expf(v)); }

__device__ __forceinline__ void split_pack(float x0, float x1, unsigned& ph, unsigned& pl) {
    __half h0 = __float2half_rn(x0), h1 = __float2half_rn(x1);
    __half l0 = __float2half_rn(x0 - __half2float(h0));
    __half l1 = __float2half_rn(x1 - __half2float(h1));
    ph = ((unsigned)__half_as_ushort(h1) << 16) | __half_as_ushort(h0);
    pl = ((unsigned)__half_as_ushort(l1) << 16) | __half_as_ushort(l0);
}

// A-fragment u32 index within a 128x32 chunk, for element pair (r, k even)
__device__ __forceinline__ int afrag_idx(int r, int k) {
    int mt = r >> 4, rr = r & 15;
    int ks = k >> 4, kk = k & 15;
    int lane = ((rr & 7) << 2) | ((kk >> 1) & 3);
    int reg  = (rr >> 3) | ((kk >> 3) << 1);
    return ((mt * 2 + ks) * 32 + lane) * 4 + reg;
}

// ---------------------------------------------------------------------------
// Batched converter: fp32 -> fragment-packed fp16 hi/lo planes.
// nrows < 128 pads the tail rows with zeros (for N=96 B matrices).
// ---------------------------------------------------------------------------
struct CDesc { const float* src; unsigned off; int ld; int nchunks; int nblk; int isA; int nrows; };
struct CTable { CDesc d[9]; };

__global__ __launch_bounds__(256) void conv_all(CTable t)
{
    __shared__ float s[128][33];
    int b = blockIdx.x;
    int di = 0;
    while (b >= t.d[di].nblk) { b -= t.d[di].nblk; di++; }
    const CDesc d = t.d[di];
    const int rb = b / d.nchunks, c = b % d.nchunks;
    const int tid = threadIdx.x;
    const float* sp = d.src + (size_t)(rb * 128) * d.ld + c * 32;
#pragma unroll
    for (int it = 0; it < 4; it++) {
        int r = (tid >> 3) + it * 32, c4 = tid & 7;
        float4 v = make_float4(0.f, 0.f, 0.f, 0.f);
        if (r < d.nrows)
            v = *reinterpret_cast<const float4*>(sp + (size_t)r * d.ld + c4 * 4);
        s[r][c4*4+0]=v.x; s[r][c4*4+1]=v.y; s[r][c4*4+2]=v.z; s[r][c4*4+3]=v.w;
    }
    __syncthreads();
    unsigned* oh = g_hi + d.off + (size_t)(rb * d.nchunks + c) * 2048;
    unsigned* ol = g_lo + d.off + (size_t)(rb * d.nchunks + c) * 2048;
    if (d.isA) {
#pragma unroll
        for (int j = 0; j < 8; j++) {
            int idx = tid + 256*j;
            int reg = idx&3, lane=(idx>>2)&31, ks=(idx>>7)&1, mt=idx>>8;
            int r = mt*16 + ((reg&1)<<3) + (lane>>2);
            int k = ks*16 + ((reg>>1)<<3) + ((lane&3)<<1);
            unsigned ph, pl;
            split_pack(s[r][k], s[r][k+1], ph, pl);
            oh[idx] = ph; ol[idx] = pl;
        }
    } else {
#pragma unroll
        for (int j = 0; j < 8; j++) {
            int idx = tid + 256*j;
            int reg = idx&1, lane=(idx>>1)&31, ks=(idx>>6)&1, nt=idx>>7;
            int n = nt*8 + (lane>>2);
            int k = ks*16 + reg*8 + ((lane&3)<<1);
            unsigned ph, pl;
            split_pack(s[n][k], s[n][k+1], ph, pl);
            oh[idx] = ph; ol[idx] = pl;
        }
    }
}

// ---------------------------------------------------------------------------
// fp16 3-pass split GEMM, 128x64 tiles, 3-stage cp.async, 2 CTAs/SM.
// SMEM stage (u32): Ah[2048] Al[2048] Bh[1024] Bl[1024] = 24KB
// ---------------------------------------------------------------------------
struct HArgs { unsigned aoff; unsigned boff; float* C; const float* bias; };

__device__ __forceinline__ void mma_h(float* c, const unsigned* a, const unsigned* b) {
    asm volatile(
        "mma.sync.aligned.m16n8k16.row.col.f32.f16.f16.f32 "
        "{%0,%1,%2,%3},{%4,%5,%6,%7},{%8,%9},{%0,%1,%2,%3};"
        : "+f"(c[0]), "+f"(c[1]), "+f"(c[2]), "+f"(c[3])
        : "r"(a[0]), "r"(a[1]), "r"(a[2]), "r"(a[3]), "r"(b[0]), "r"(b[1]));
}
__device__ __forceinline__ void cp16(unsigned saddr, const void* g) {
    asm volatile("cp.async.cg.shared.global [%0], [%1], 16;" :: "r"(saddr), "l"(g));
}

#define ST_U32 6144
#define NSTAGE 3
#define HG_SMEM_BYTES (NSTAGE * ST_U32 * 4)   // 73728

// Pointers already offset to chunk 0 of this block's row/col tiles.
// gB* chunk stride in gmem remains 2048 u32 (we copy the 1024-u32 half).
template<typename EpiFn>
__device__ __forceinline__ void hgemm_body(
    const unsigned* gAh, const unsigned* gAl,
    const unsigned* gBh, const unsigned* gBl,
    int nch, unsigned* sm, unsigned sbase,
    int tid, int lane, int warp_m, int warp_n, EpiFn epi)
{
    auto issue = [&](int s, int c) {
        const unsigned dst = sbase + s * (ST_U32 * 4);
        const unsigned* a0 = gAh + (size_t)c * 2048;
        const unsigned* a1 = gAl + (size_t)c * 2048;
        const unsigned* b0 = gBh + (size_t)c * 2048;
        const unsigned* b1 = gBl + (size_t)c * 2048;
#pragma unroll
        for (int q = 0; q < 2; q++) {
            const int o = (tid + q * 256) * 4;
            cp16(dst + o * 4,         a0 + o);
            cp16(dst + 8192 + o * 4,  a1 + o);
        }
        {
            const int o = tid * 4;
            cp16(dst + 16384 + o * 4, b0 + o);
            cp16(dst + 20480 + o * 4, b1 + o);
        }
        asm volatile("cp.async.commit_group;");
    };

    float acc[2][4][4];
#pragma unroll
    for (int mt = 0; mt < 2; mt++)
#pragma unroll
        for (int nt = 0; nt < 4; nt++)
#pragma unroll
            for (int j = 0; j < 4; j++) acc[mt][nt][j] = 0.f;

    issue(0, 0);
    if (nch > 1) issue(1, 1);
    int sidx = 0;
    for (int c = 0; c < nch; c++) {
        if (c + 2 < nch) {
            int s2 = sidx + 2; if (s2 >= NSTAGE) s2 -= NSTAGE;
            issue(s2, c + 2);
            asm volatile("cp.async.wait_group 2;");
        } else if (c + 1 < nch) {
            asm volatile("cp.async.wait_group 1;");
        } else {
            asm volatile("cp.async.wait_group 0;");
        }
        __syncthreads();
        const unsigned* st  = sm + sidx * ST_U32;
        const unsigned* sAh = st;
        const unsigned* sAl = st + 2048;
        const unsigned* sBh = st + 4096;
        const unsigned* sBl = st + 5120;
#pragma unroll
        for (int ks = 0; ks < 2; ks++) {
            unsigned ah[2][4], al[2][4], bh[4][2], bl[4][2];
#pragma unroll
            for (int mt = 0; mt < 2; mt++) {
                const int base = (((warp_m*2 + mt)*2 + ks)*32 + lane) * 4;
                uint4 v = *reinterpret_cast<const uint4*>(sAh + base);
                ah[mt][0]=v.x; ah[mt][1]=v.y; ah[mt][2]=v.z; ah[mt][3]=v.w;
                v = *reinterpret_cast<const uint4*>(sAl + base);
                al[mt][0]=v.x; al[mt][1]=v.y; al[mt][2]=v.z; al[mt][3]=v.w;
            }
#pragma unroll
            for (int nt = 0; nt < 4; nt++) {
                const int base = (((warp_n*4 + nt)*2 + ks)*32 + lane) * 2;
                uint2 v = *reinterpret_cast<const uint2*>(sBh + base);
                bh[nt][0]=v.x; bh[nt][1]=v.y;
                v = *reinterpret_cast<const uint2*>(sBl + base);
                bl[nt][0]=v.x; bl[nt][1]=v.y;
            }
#pragma unroll
            for (int mt = 0; mt < 2; mt++)
#pragma unroll
                for (int nt = 0; nt < 4; nt++) mma_h(acc[mt][nt], ah[mt], bh[nt]);
#pragma unroll
            for (int mt = 0; mt < 2; mt++)
#pragma unroll
                for (int nt = 0; nt < 4; nt++) mma_h(acc[mt][nt], ah[mt], bl[nt]);
#pragma unroll
            for (int mt = 0; mt < 2; mt++)
#pragma unroll
                for (int nt = 0; nt < 4; nt++) mma_h(acc[mt][nt], al[mt], bh[nt]);
        }
        __syncthreads();
        if (++sidx == NSTAGE) sidx = 0;
    }
    epi(acc);
}

template<int EPI>
__global__ __launch_bounds__(256, 2) void hgemm(HArgs h0, HArgs h1, int nchunks, int ldc)
{
    extern __shared__ unsigned sm[];
    const unsigned sbase = (unsigned)__cvta_generic_to_shared(sm);
    HArgs h = blockIdx.z ? h1 : h0;
    const int tid = threadIdx.x, lane = tid & 31, wid = tid >> 5;
    const int warp_m = wid & 3, warp_n = wid >> 2;
    const int row0 = blockIdx.y * 128, col0 = blockIdx.x * 64;
    const unsigned* gAh = g_hi + h.aoff + (size_t)blockIdx.y * nchunks * 2048;
    const unsigned* gAl = g_lo + h.aoff + (size_t)blockIdx.y * nchunks * 2048;
    const size_t bbase = h.boff + (size_t)(col0 >> 7) * nchunks * 2048 + ((col0 >> 6) & 1) * 1024;
    const unsigned* gBh = g_hi + bbase;
    const unsigned* gBl = g_lo + bbase;
    const int rw = lane >> 2, cw = (lane & 3) * 2;

    hgemm_body(gAh, gAl, gBh, gBl, nchunks, sm, sbase, tid, lane, warp_m, warp_n,
        [&](float acc[2][4][4]) {
#pragma unroll
            for (int mt = 0; mt < 2; mt++) {
                const int m = row0 + warp_m*32 + mt*16 + rw;
#pragma unroll
                for (int nt = 0; nt < 4; nt++) {
                    const int n = col0 + warp_n*32 + nt*8 + cw;
                    float v0 = acc[mt][nt][0], v1 = acc[mt][nt][1];
                    float v2 = acc[mt][nt][2], v3 = acc[mt][nt][3];
                    if (EPI == 1) {
                        const float b0 = __ldg(h.bias + n);
                        const float b1 = __ldg(h.bias + n + 1);
                        v0 = softplusf(v0 + b0); v1 = softplusf(v1 + b1);
                        v2 = softplusf(v2 + b0); v3 = softplusf(v3 + b1);
                    }
                    *reinterpret_cast<float2*>(h.C + (size_t)m * ldc + n)       = make_float2(v0, v1);
                    *reinterpret_cast<float2*>(h.C + (size_t)(m + 8) * ldc + n) = make_float2(v2, v3);
                }
            }
        });
}

// G3 tensor GEMM: partial[dir][split] = u[mblock, Kseg] @ xw^T (N=96 padded to 128)
// grid (2 nblocks, 8 mblocks, 8 = dir*4+split)
__global__ __launch_bounds__(256, 2) void hgemm_g3()
{
    extern __shared__ unsigned sm[];
    const unsigned sbase = (unsigned)__cvta_generic_to_shared(sm);
    const int nblock = blockIdx.x, mblock = blockIdx.y;
    const int dir = blockIdx.z >> 2, split = blockIdx.z & 3;
    const int tid = threadIdx.x, lane = tid & 31, wid = tid >> 5;
    const int warp_m = wid & 3, warp_n = wid >> 2;
    const size_t abase = U_U_A + (size_t)mblock * 64 * 2048 + (size_t)split * 16 * 2048;
    const unsigned* gAh = g_hi + abase;
    const unsigned* gAl = g_lo + abase;
    const size_t bbase = (dir ? U_XW1_B : U_XW0_B) + (size_t)split * 16 * 2048 + nblock * 1024;
    const unsigned* gBh = g_hi + bbase;
    const unsigned* gBl = g_lo + bbase;
    const int row0 = mblock * 128, col0 = nblock * 64;
    const int rw = lane >> 2, cw = (lane & 3) * 2;
    float* C = g_part[dir][split];

    hgemm_body(gAh, gAl, gBh, gBl, 16, sm, sbase, tid, lane, warp_m, warp_n,
        [&](float acc[2][4][4]) {
#pragma unroll
            for (int mt = 0; mt < 2; mt++) {
                const int m = row0 + warp_m*32 + mt*16 + rw;
#pragma unroll
                for (int nt = 0; nt < 4; nt++) {
                    const int n = col0 + warp_n*32 + nt*8 + cw;
                    if (n < 96) {
                        *reinterpret_cast<float2*>(C + (size_t)m * 96 + n) =
                            make_float2(acc[mt][nt][0], acc[mt][nt][1]);
                        *reinterpret_cast<float2*>(C + (size_t)(m + 8) * 96 + n) =
                            make_float2(acc[mt][nt][2], acc[mt][nt][3]);
                    }
                }
            }
        });
}

// ---------------------------------------------------------------------------
// reduce partials; dt cols -> split planes (A-frag layout), B/C cols -> g_ssm
// ---------------------------------------------------------------------------
__global__ __launch_bounds__(256) void reduce_pack_g3()
{
    const int idx = blockIdx.x * blockDim.x + threadIdx.x;   // < 2*1024*48
    const int pr  = idx % 48;
    const int R   = (idx / 48) % ML;
    const int dir = idx / (48 * ML);
    const int c0  = pr * 2;
    const size_t o = (size_t)R * 96 + c0;
    float2 s = make_float2(0.f, 0.f);
#pragma unroll
    for (int p = 0; p < 4; p++) {
        float2 v = *reinterpret_cast<const float2*>(g_part[dir][p] + o);
        s.x += v.x; s.y += v.y;
    }
    if (c0 < 64) {
        unsigned ph, pl;
        split_pack(s.x, s.y, ph, pl);
        const unsigned uoff = dir ? U_SSM1_A : U_SSM0_A;
        const int d = uoff + ((R >> 7) * 2 + (c0 >> 5)) * 2048 + afrag_idx(R & 127, c0 & 31);
        g_hi[d] = ph; g_lo[d] = pl;
    } else {
        *reinterpret_cast<float2*>(g_ssm[dir] + o) = s;
    }
}

// ---------------------------------------------------------------------------
// conv + silu; also emits u as A-fragment split planes for tensor G3
// ---------------------------------------------------------------------------
__global__ __launch_bounds__(256) void conv_silu_kernel(const float* __restrict__ w,
                                                        const float* __restrict__ bias)
{
    const int idx = blockIdx.x * blockDim.x + threadIdx.x;   // < ML*ID/2
    const int R  = idx >> 10;
    const int ch = (idx & 1023) << 1;
    const int l  = R & (LL - 1);
    const size_t o = (size_t)R * ID + ch;
    float acc0 = bias[ch], acc1 = bias[ch + 1];
#pragma unroll
    for (int k = 0; k < 4; k++) {
        int ls = l - 3 + k;
        if (ls >= 0) {
            float2 xv = *reinterpret_cast<const float2*>(g_x + o + (ptrdiff_t)(k - 3) * ID);
            acc0 = fmaf(xv.x, w[ch*4 + k],       acc0);
            acc1 = fmaf(xv.y, w[(ch+1)*4 + k],   acc1);
        }
    }
    float u0 = siluf(acc0), u1 = siluf(acc1);
    *reinterpret_cast<float2*>(g_u + o) = make_float2(u0, u1);
    unsigned ph, pl;
    split_pack(u0, u1, ph, pl);
    const int d = U_U_A + ((R >> 7) * 64 + (ch >> 5)) * 2048 + afrag_idx(R & 127, ch & 31);
    g_hi[d] = ph; g_lo[d] = pl;
}

// ---------------------------------------------------------------------------
// selective scan
// ---------------------------------------------------------------------------
__global__ void scan_kernel(const float* __restrict__ Alog_f,
                            const float* __restrict__ Alog_b,
                            const float* __restrict__ D_f,
                            const float* __restrict__ D_b)
{
    int gw   = (blockIdx.x * blockDim.x + threadIdx.x) >> 5;
    int lane = threadIdx.x & 31;
    int dir  = gw >> 11;
    int b    = (gw >> 10) & 1;
    int i    = ((gw & 1023) << 1) | (lane >> 4);
    int n    = lane & 15;

    const float* Alog = dir ? Alog_b : Alog_f;
    float An = -expf(Alog[i*NSTATE + n]);
    float Dv = dir ? D_b[i] : D_f[i];

    const float* dbase = g_delta[dir] + (size_t)(b*LL)*ID + i;
    const float* ubase = g_u          + (size_t)(b*LL)*ID + i;
    const float* sbase = g_ssm[dir]   + (size_t)(b*LL)*96;
    float*       ybase = g_y[dir]     + (size_t)(b*LL)*ID + i;

    int l0 = dir ? (LL-1) : 0;
    ptrdiff_t dstep = dir ? -(ptrdiff_t)ID : (ptrdiff_t)ID;
    ptrdiff_t sstep = dir ? -96 : 96;

    const float* dp = dbase + (size_t)l0*ID;
    const float* up = ubase + (size_t)l0*ID;
    const float* sp = sbase + (size_t)l0*96;
    float*       yp = ybase + (size_t)l0*ID;

    float x = 0.f;
#pragma unroll 2
    for (int t = 0; t < LL; t++) {
        float d  = *dp;
        float uu = *up;
        float Bv = *(sp + RD + n);
        float Cv = *(sp + RD + NSTATE + n);
        float dA = __expf(d * An);
        x = fmaf(x, dA, d * Bv * uu);
        float p = x * Cv;
        p += __shfl_xor_sync(0xffffffffu, p, 1);
        p += __shfl_xor_sync(0xffffffffu, p, 2);
        p += __shfl_xor_sync(0xffffffffu, p, 4);
        p += __shfl_xor_sync(0xffffffffu, p, 8);
        if (n == 0) *yp = fmaf(uu, Dv, p);
        dp += dstep; up += dstep; sp += sstep; yp += dstep;
    }
}

// ---------------------------------------------------------------------------
// combine: yt = (yf+yb)*silu(gate), written directly as split planes (A layout)
// ---------------------------------------------------------------------------
__global__ __launch_bounds__(256) void combine_kernel()
{
    const int idx = blockIdx.x * blockDim.x + threadIdx.x;   // over ML*ID/2
    const int R  = idx >> 10;
    const int ch = (idx & 1023) << 1;
    const size_t o = (size_t)R * ID + ch;
    float2 yf = *reinterpret_cast<const float2*>(g_y[0] + o);
    float2 yb = *reinterpret_cast<const float2*>(g_y[1] + o);
    float2 gt = *reinterpret_cast<const float2*>(g_gate + o);
    float yt0 = (yf.x + yb.x) * siluf(gt.x);
    float yt1 = (yf.y + yb.y) * siluf(gt.y);
    unsigned ph, pl;
    split_pack(yt0, yt1, ph, pl);
    const int d = U_YT_A + ((R >> 7) * 64 + (ch >> 5)) * 2048 + afrag_idx(R & 127, ch & 31);
    g_hi[d] = ph; g_lo[d] = pl;
}

// ---------------------------------------------------------------------------
// Launch
// ---------------------------------------------------------------------------
extern "C" void kernel_launch(void* const* d_in, const int* in_sizes, int n_in,
                              void* d_out, int out_size)
{
    const float* hs     = (const float*)d_in[0];
    const float* hs2    = (const float*)d_in[1];
    const float* in_w   = (const float*)d_in[2];
    const float* in_dw  = (const float*)d_in[3];
    const float* conv_w = (const float*)d_in[4];
    const float* conv_b = (const float*)d_in[5];
    const float* xw_f   = (const float*)d_in[6];
    const float* xw_b   = (const float*)d_in[7];
    const float* dtw_f  = (const float*)d_in[8];
    const float* dtb_f  = (const float*)d_in[9];
    const float* dtw_b  = (const float*)d_in[10];
    const float* dtb_b  = (const float*)d_in[11];
    const float* Alog_f = (const float*)d_in[12];
    const float* Alog_b = (const float*)d_in[13];
    const float* D_f    = (const float*)d_in[14];
    const float* D_b    = (const float*)d_in[15];
    const float* outw   = (const float*)d_in[16];
    float* out = (float*)d_out;

    float *px, *pgate, *pdelta;
    cudaGetSymbolAddress((void**)&px,     g_x);
    cudaGetSymbolAddress((void**)&pgate,  g_gate);
    cudaGetSymbolAddress((void**)&pdelta, g_delta);
    float* pd0 = pdelta;
    float* pd1 = pdelta + (size_t)ML*ID;

    cudaFuncSetAttribute(hgemm<0>, cudaFuncAttributeMaxDynamicSharedMemorySize, HG_SMEM_BYTES);
    cudaFuncSetAttribute(hgemm<1>, cudaFuncAttributeMaxDynamicSharedMemorySize, HG_SMEM_BYTES);
    cudaFuncSetAttribute(hgemm_g3, cudaFuncAttributeMaxDynamicSharedMemorySize, HG_SMEM_BYTES);

    // Batched conversions (weights + inputs) in ONE launch
    {
        CTable t;
        t.d[0] = {in_w,                  U_INW_B,  HD, 32, 512, 0, 128};
        t.d[1] = {in_dw + (size_t)ID*HD, U_INDW_B, HD, 32, 512, 0, 128};
        t.d[2] = {dtw_f,                 U_DTW0_B, RD, 2,  32,  0, 128};
        t.d[3] = {dtw_b,                 U_DTW1_B, RD, 2,  32,  0, 128};
        t.d[4] = {outw,                  U_OUTW_B, ID, 64, 512, 0, 128};
        t.d[5] = {hs,                    U_HS_A,   HD, 32, 256, 1, 128};
        t.d[6] = {hs2,                   U_HS2_A,  HD, 32, 256, 1, 128};
        t.d[7] = {xw_f,                  U_XW0_B,  ID, 64, 64,  0, 96};
        t.d[8] = {xw_b,                  U_XW1_B,  ID, 64, 64,  0, 96};
        conv_all<<<2240, 256>>>(t);
    }

    // G1: x = hs @ in_w[:I]^T ; gate = hs2 @ in_dw[I:2I]^T
    {
        HArgs a{U_HS_A,  U_INW_B,  px,    nullptr};
        HArgs b{U_HS2_A, U_INDW_B, pgate, nullptr};
        hgemm<0><<<dim3(ID/64, ML/128, 2), 256, HG_SMEM_BYTES>>>(a, b, 32, ID);
    }

    // conv + silu (+ u split planes)
    conv_silu_kernel<<<(ML*ID)/512, 256>>>(conv_w, conv_b);

    // G3 on tensor cores: split-K partials then reduce+pack
    hgemm_g3<<<dim3(2, 8, 8), 256, HG_SMEM_BYTES>>>();
    reduce_pack_g3<<<(2*ML*48)/256, 256>>>();

    // G4: delta = softplus(dt @ dt_w^T + b)
    {
        HArgs a{U_SSM0_A, U_DTW0_B, pd0, dtb_f};
        HArgs b{U_SSM1_A, U_DTW1_B, pd1, dtb_b};
        hgemm<1><<<dim3(ID/64, ML/128, 2), 256, HG_SMEM_BYTES>>>(a, b, 2, ID);
    }

    scan_kernel<<<512, 256>>>(Alog_f, Alog_b, D_f, D_b);
    combine_kernel<<<(ML*ID)/512, 256>>>();

    // G5: out = yt @ out_proj_w^T
    {
        HArgs a{U_YT_A, U_OUTW_B, out, nullptr};
        hgemm<0><<<dim3(HD/64, ML/128, 1), 256, HG_SMEM_BYTES>>>(a, a, 64, HD);
    }

    (void)in_sizes; (void)n_in; (void)out_size;
}

// round 13
// speedup vs baseline: 1.3519x; 1.0732x over previous
#include <cuda_runtime.h>
#include <cuda_fp16.h>
#include <cstdint>
#include <cstddef>

// Problem constants
#define HD 1024
#define ID 2048
#define NSTATE 16
#define RD 64
#define BB 2
#define LL 512
#define ML (BB*LL)

// ---------------------------------------------------------------------------
// Scratch
// ---------------------------------------------------------------------------
__device__ __align__(16) float g_x   [(size_t)ML*ID];
__device__ __align__(16) float g_gate[(size_t)ML*ID];
__device__ __align__(16) float g_u   [(size_t)ML*ID];
__device__ __align__(16) float g_ssm [2][(size_t)ML*96];    // only cols 64..95 read (B|C)
__device__ __align__(16) float g_part[2][8][(size_t)ML*96]; // split-K partials for G3
__device__ __align__(16) float g_delta[2][(size_t)ML*ID];
__device__ __align__(16) float g_y   [2][(size_t)ML*ID];

// fp16 split-plane pools (fragment-packed u32 = half2 pairs)
#define U_HS_A    0u
#define U_HS2_A   524288u
#define U_INW_B   1048576u
#define U_INDW_B  2097152u
#define U_SSM0_A  3145728u
#define U_SSM1_A  3178496u
#define U_DTW0_B  3211264u
#define U_DTW1_B  3276800u
#define U_YT_A    3342336u
#define U_OUTW_B  4390912u
#define U_U_A     5439488u
#define U_XW0_B   6488064u
#define U_XW1_B   6619136u
#define U_TOTAL   6750208u
__device__ __align__(16) unsigned g_hi[U_TOTAL];
__device__ __align__(16) unsigned g_lo[U_TOTAL];   // only B (weight) lo planes consumed

__device__ __forceinline__ float siluf(float v)     { return v * (1.0f / (1.0f + __expf(-v))); }
__device__ __forceinline__ float softplusf(float v) { return v > 20.f ? v : log1pf(__expf(v)); }

__device__ __forceinline__ void split_pack(float x0, float x1, unsigned& ph, unsigned& pl) {
    __half h0 = __float2half_rn(x0), h1 = __float2half_rn(x1);
    __half l0 = __float2half_rn(x0 - __half2float(h0));
    __half l1 = __float2half_rn(x1 - __half2float(h1));
    ph = ((unsigned)__half_as_ushort(h1) << 16) | __half_as_ushort(h0);
    pl = ((unsigned)__half_as_ushort(l1) << 16) | __half_as_ushort(l0);
}
__device__ __forceinline__ unsigned pack_h2(float x0, float x1) {
    __half h0 = __float2half_rn(x0), h1 = __float2half_rn(x1);
    return ((unsigned)__half_as_ushort(h1) << 16) | __half_as_ushort(h0);
}

// A-fragment u32 index within a 128x32 chunk, for element pair (r, k even)
__device__ __forceinline__ int afrag_idx(int r, int k) {
    int mt = r >> 4, rr = r & 15;
    int ks = k >> 4, kk = k & 15;
    int lane = ((rr & 7) << 2) | ((kk >> 1) & 3);
    int reg  = (rr >> 3) | ((kk >> 3) << 1);
    return ((mt * 2 + ks) * 32 + lane) * 4 + reg;
}

// ---------------------------------------------------------------------------
// Batched converter: fp32 -> fragment-packed fp16 hi/lo planes.
// ---------------------------------------------------------------------------
struct CDesc { const float* src; unsigned off; int ld; int nchunks; int nblk; int isA; int nrows; };
struct CTable { CDesc d[9]; };

__global__ __launch_bounds__(256) void conv_all(CTable t)
{
    __shared__ float s[128][33];
    int b = blockIdx.x;
    int di = 0;
    while (b >= t.d[di].nblk) { b -= t.d[di].nblk; di++; }
    const CDesc d = t.d[di];
    const int rb = b / d.nchunks, c = b % d.nchunks;
    const int tid = threadIdx.x;
    const float* sp = d.src + (size_t)(rb * 128) * d.ld + c * 32;
#pragma unroll
    for (int it = 0; it < 4; it++) {
        int r = (tid >> 3) + it * 32, c4 = tid & 7;
        float4 v = make_float4(0.f, 0.f, 0.f, 0.f);
        if (r < d.nrows)
            v = *reinterpret_cast<const float4*>(sp + (size_t)r * d.ld + c4 * 4);
        s[r][c4*4+0]=v.x; s[r][c4*4+1]=v.y; s[r][c4*4+2]=v.z; s[r][c4*4+3]=v.w;
    }
    __syncthreads();
    unsigned* oh = g_hi + d.off + (size_t)(rb * d.nchunks + c) * 2048;
    unsigned* ol = g_lo + d.off + (size_t)(rb * d.nchunks + c) * 2048;
    if (d.isA) {
#pragma unroll
        for (int j = 0; j < 8; j++) {
            int idx = tid + 256*j;
            int reg = idx&3, lane=(idx>>2)&31, ks=(idx>>7)&1, mt=idx>>8;
            int r = mt*16 + ((reg&1)<<3) + (lane>>2);
            int k = ks*16 + ((reg>>1)<<3) + ((lane&3)<<1);
            oh[idx] = pack_h2(s[r][k], s[r][k+1]);
        }
    } else {
#pragma unroll
        for (int j = 0; j < 8; j++) {
            int idx = tid + 256*j;
            int reg = idx&1, lane=(idx>>1)&31, ks=(idx>>6)&1, nt=idx>>7;
            int n = nt*8 + (lane>>2);
            int k = ks*16 + reg*8 + ((lane&3)<<1);
            unsigned ph, pl;
            split_pack(s[n][k], s[n][k+1], ph, pl);
            oh[idx] = ph; ol[idx] = pl;
        }
    }
}

// ---------------------------------------------------------------------------
// fp16 2-pass split GEMM (A in fp16-hi; B hi+lo), 128x64 tiles, 3-stage cp.async.
// SMEM stage (u32): Ah[2048] Bh[1024] Bl[1024] = 16KB
// ---------------------------------------------------------------------------
struct HArgs { unsigned aoff; unsigned boff; float* C; const float* bias; };

__device__ __forceinline__ void mma_h(float* c, const unsigned* a, const unsigned* b) {
    asm volatile(
        "mma.sync.aligned.m16n8k16.row.col.f32.f16.f16.f32 "
        "{%0,%1,%2,%3},{%4,%5,%6,%7},{%8,%9},{%0,%1,%2,%3};"
        : "+f"(c[0]), "+f"(c[1]), "+f"(c[2]), "+f"(c[3])
        : "r"(a[0]), "r"(a[1]), "r"(a[2]), "r"(a[3]), "r"(b[0]), "r"(b[1]));
}
__device__ __forceinline__ void cp16(unsigned saddr, const void* g) {
    asm volatile("cp.async.cg.shared.global [%0], [%1], 16;" :: "r"(saddr), "l"(g));
}

#define ST_U32 4096
#define NSTAGE 3
#define HG_SMEM_BYTES (NSTAGE * ST_U32 * 4)   // 49152

template<typename EpiFn>
__device__ __forceinline__ void hgemm_body(
    const unsigned* gAh, const unsigned* gBh, const unsigned* gBl,
    int nch, unsigned* sm, unsigned sbase,
    int tid, int lane, int warp_m, int warp_n, EpiFn epi)
{
    auto issue = [&](int s, int c) {
        const unsigned dst = sbase + s * (ST_U32 * 4);
        const unsigned* a0 = gAh + (size_t)c * 2048;
        const unsigned* b0 = gBh + (size_t)c * 2048;
        const unsigned* b1 = gBl + (size_t)c * 2048;
#pragma unroll
        for (int q = 0; q < 2; q++) {
            const int o = (tid + q * 256) * 4;
            cp16(dst + o * 4, a0 + o);
        }
        {
            const int o = tid * 4;
            cp16(dst + 8192 + o * 4,  b0 + o);
            cp16(dst + 12288 + o * 4, b1 + o);
        }
        asm volatile("cp.async.commit_group;");
    };

    float acc[2][4][4];
#pragma unroll
    for (int mt = 0; mt < 2; mt++)
#pragma unroll
        for (int nt = 0; nt < 4; nt++)
#pragma unroll
            for (int j = 0; j < 4; j++) acc[mt][nt][j] = 0.f;

    issue(0, 0);
    if (nch > 1) issue(1, 1);
    int sidx = 0;
    for (int c = 0; c < nch; c++) {
        if (c + 2 < nch) {
            int s2 = sidx + 2; if (s2 >= NSTAGE) s2 -= NSTAGE;
            issue(s2, c + 2);
            asm volatile("cp.async.wait_group 2;");
        } else if (c + 1 < nch) {
            asm volatile("cp.async.wait_group 1;");
        } else {
            asm volatile("cp.async.wait_group 0;");
        }
        __syncthreads();
        const unsigned* st  = sm + sidx * ST_U32;
        const unsigned* sAh = st;
        const unsigned* sBh = st + 2048;
        const unsigned* sBl = st + 3072;
#pragma unroll
        for (int ks = 0; ks < 2; ks++) {
            unsigned ah[2][4], bh[4][2], bl[4][2];
#pragma unroll
            for (int mt = 0; mt < 2; mt++) {
                const int base = (((warp_m*2 + mt)*2 + ks)*32 + lane) * 4;
                uint4 v = *reinterpret_cast<const uint4*>(sAh + base);
                ah[mt][0]=v.x; ah[mt][1]=v.y; ah[mt][2]=v.z; ah[mt][3]=v.w;
            }
#pragma unroll
            for (int nt = 0; nt < 4; nt++) {
                const int base = (((warp_n*4 + nt)*2 + ks)*32 + lane) * 2;
                uint2 v = *reinterpret_cast<const uint2*>(sBh + base);
                bh[nt][0]=v.x; bh[nt][1]=v.y;
                v = *reinterpret_cast<const uint2*>(sBl + base);
                bl[nt][0]=v.x; bl[nt][1]=v.y;
            }
#pragma unroll
            for (int mt = 0; mt < 2; mt++)
#pragma unroll
                for (int nt = 0; nt < 4; nt++) mma_h(acc[mt][nt], ah[mt], bh[nt]);
#pragma unroll
            for (int mt = 0; mt < 2; mt++)
#pragma unroll
                for (int nt = 0; nt < 4; nt++) mma_h(acc[mt][nt], ah[mt], bl[nt]);
        }
        __syncthreads();
        if (++sidx == NSTAGE) sidx = 0;
    }
    epi(acc);
}

template<int EPI>
__global__ __launch_bounds__(256, 2) void hgemm(HArgs h0, HArgs h1, int nchunks, int ldc)
{
    extern __shared__ unsigned sm[];
    const unsigned sbase = (unsigned)__cvta_generic_to_shared(sm);
    HArgs h = blockIdx.z ? h1 : h0;
    const int tid = threadIdx.x, lane = tid & 31, wid = tid >> 5;
    const int warp_m = wid & 3, warp_n = wid >> 2;
    const int row0 = blockIdx.y * 128, col0 = blockIdx.x * 64;
    const unsigned* gAh = g_hi + h.aoff + (size_t)blockIdx.y * nchunks * 2048;
    const size_t bbase = h.boff + (size_t)(col0 >> 7) * nchunks * 2048 + ((col0 >> 6) & 1) * 1024;
    const unsigned* gBh = g_hi + bbase;
    const unsigned* gBl = g_lo + bbase;
    const int rw = lane >> 2, cw = (lane & 3) * 2;

    hgemm_body(gAh, gBh, gBl, nchunks, sm, sbase, tid, lane, warp_m, warp_n,
        [&](float acc[2][4][4]) {
#pragma unroll
            for (int mt = 0; mt < 2; mt++) {
                const int m = row0 + warp_m*32 + mt*16 + rw;
#pragma unroll
                for (int nt = 0; nt < 4; nt++) {
                    const int n = col0 + warp_n*32 + nt*8 + cw;
                    float v0 = acc[mt][nt][0], v1 = acc[mt][nt][1];
                    float v2 = acc[mt][nt][2], v3 = acc[mt][nt][3];
                    if (EPI == 1) {
                        const float b0 = __ldg(h.bias + n);
                        const float b1 = __ldg(h.bias + n + 1);
                        v0 = softplusf(v0 + b0); v1 = softplusf(v1 + b1);
                        v2 = softplusf(v2 + b0); v3 = softplusf(v3 + b1);
                    }
                    *reinterpret_cast<float2*>(h.C + (size_t)m * ldc + n)       = make_float2(v0, v1);
                    *reinterpret_cast<float2*>(h.C + (size_t)(m + 8) * ldc + n) = make_float2(v2, v3);
                }
            }
        });
}

// G3 tensor GEMM: partial[dir][split] = u[mblock, Kseg] @ xw^T (N=96 padded to 128)
// grid (2 nblocks, 8 mblocks, 16 = dir*8+split), 8 chunks per block
__global__ __launch_bounds__(256, 2) void hgemm_g3()
{
    extern __shared__ unsigned sm[];
    const unsigned sbase = (unsigned)__cvta_generic_to_shared(sm);
    const int nblock = blockIdx.x, mblock = blockIdx.y;
    const int dir = blockIdx.z >> 3, split = blockIdx.z & 7;
    const int tid = threadIdx.x, lane = tid & 31, wid = tid >> 5;
    const int warp_m = wid & 3, warp_n = wid >> 2;
    const size_t abase = U_U_A + (size_t)mblock * 64 * 2048 + (size_t)split * 8 * 2048;
    const unsigned* gAh = g_hi + abase;
    const size_t bbase = (dir ? U_XW1_B : U_XW0_B) + (size_t)split * 8 * 2048 + nblock * 1024;
    const unsigned* gBh = g_hi + bbase;
    const unsigned* gBl = g_lo + bbase;
    const int row0 = mblock * 128, col0 = nblock * 64;
    const int rw = lane >> 2, cw = (lane & 3) * 2;
    float* C = g_part[dir][split];

    hgemm_body(gAh, gBh, gBl, 8, sm, sbase, tid, lane, warp_m, warp_n,
        [&](float acc[2][4][4]) {
#pragma unroll
            for (int mt = 0; mt < 2; mt++) {
                const int m = row0 + warp_m*32 + mt*16 + rw;
#pragma unroll
                for (int nt = 0; nt < 4; nt++) {
                    const int n = col0 + warp_n*32 + nt*8 + cw;
                    if (n < 96) {
                        *reinterpret_cast<float2*>(C + (size_t)m * 96 + n) =
                            make_float2(acc[mt][nt][0], acc[mt][nt][1]);
                        *reinterpret_cast<float2*>(C + (size_t)(m + 8) * 96 + n) =
                            make_float2(acc[mt][nt][2], acc[mt][nt][3]);
                    }
                }
            }
        });
}

// ---------------------------------------------------------------------------
// reduce partials; dt cols -> hi plane (A-frag layout), B/C cols -> g_ssm
// ---------------------------------------------------------------------------
__global__ __launch_bounds__(256) void reduce_pack_g3()
{
    const int idx = blockIdx.x * blockDim.x + threadIdx.x;   // < 2*1024*48
    const int pr  = idx % 48;
    const int R   = (idx / 48) % ML;
    const int dir = idx / (48 * ML);
    const int c0  = pr * 2;
    const size_t o = (size_t)R * 96 + c0;
    float2 s = make_float2(0.f, 0.f);
#pragma unroll
    for (int p = 0; p < 8; p++) {
        float2 v = *reinterpret_cast<const float2*>(g_part[dir][p] + o);
        s.x += v.x; s.y += v.y;
    }
    if (c0 < 64) {
        const unsigned uoff = dir ? U_SSM1_A : U_SSM0_A;
        const int d = uoff + ((R >> 7) * 2 + (c0 >> 5)) * 2048 + afrag_idx(R & 127, c0 & 31);
        g_hi[d] = pack_h2(s.x, s.y);
    } else {
        *reinterpret_cast<float2*>(g_ssm[dir] + o) = s;
    }
}

// ---------------------------------------------------------------------------
// conv + silu; emits u float + A-fragment hi plane for tensor G3
// ---------------------------------------------------------------------------
__global__ __launch_bounds__(256) void conv_silu_kernel(const float* __restrict__ w,
                                                        const float* __restrict__ bias)
{
    const int idx = blockIdx.x * blockDim.x + threadIdx.x;   // < ML*ID/2
    const int R  = idx >> 10;
    const int ch = (idx & 1023) << 1;
    const int l  = R & (LL - 1);
    const size_t o = (size_t)R * ID + ch;
    float acc0 = bias[ch], acc1 = bias[ch + 1];
#pragma unroll
    for (int k = 0; k < 4; k++) {
        int ls = l - 3 + k;
        if (ls >= 0) {
            float2 xv = *reinterpret_cast<const float2*>(g_x + o + (ptrdiff_t)(k - 3) * ID);
            acc0 = fmaf(xv.x, w[ch*4 + k],       acc0);
            acc1 = fmaf(xv.y, w[(ch+1)*4 + k],   acc1);
        }
    }
    float u0 = siluf(acc0), u1 = siluf(acc1);
    *reinterpret_cast<float2*>(g_u + o) = make_float2(u0, u1);
    const int d = U_U_A + ((R >> 7) * 64 + (ch >> 5)) * 2048 + afrag_idx(R & 127, ch & 31);
    g_hi[d] = pack_h2(u0, u1);
}

// ---------------------------------------------------------------------------
// selective scan
// ---------------------------------------------------------------------------
__global__ void scan_kernel(const float* __restrict__ Alog_f,
                            const float* __restrict__ Alog_b,
                            const float* __restrict__ D_f,
                            const float* __restrict__ D_b)
{
    int gw   = (blockIdx.x * blockDim.x + threadIdx.x) >> 5;
    int lane = threadIdx.x & 31;
    int dir  = gw >> 11;
    int b    = (gw >> 10) & 1;
    int i    = ((gw & 1023) << 1) | (lane >> 4);
    int n    = lane & 15;

    const float* Alog = dir ? Alog_b : Alog_f;
    float An = -expf(Alog[i*NSTATE + n]);
    float Dv = dir ? D_b[i] : D_f[i];

    const float* dbase = g_delta[dir] + (size_t)(b*LL)*ID + i;
    const float* ubase = g_u          + (size_t)(b*LL)*ID + i;
    const float* sbase = g_ssm[dir]   + (size_t)(b*LL)*96;
    float*       ybase = g_y[dir]     + (size_t)(b*LL)*ID + i;

    int l0 = dir ? (LL-1) : 0;
    ptrdiff_t dstep = dir ? -(ptrdiff_t)ID : (ptrdiff_t)ID;
    ptrdiff_t sstep = dir ? -96 : 96;

    const float* dp = dbase + (size_t)l0*ID;
    const float* up = ubase + (size_t)l0*ID;
    const float* sp = sbase + (size_t)l0*96;
    float*       yp = ybase + (size_t)l0*ID;

    float x = 0.f;
#pragma unroll 2
    for (int t = 0; t < LL; t++) {
        float d  = *dp;
        float uu = *up;
        float Bv = *(sp + RD + n);
        float Cv = *(sp + RD + NSTATE + n);
        float dA = __expf(d * An);
        x = fmaf(x, dA, d * Bv * uu);
        float p = x * Cv;
        p += __shfl_xor_sync(0xffffffffu, p, 1);
        p += __shfl_xor_sync(0xffffffffu, p, 2);
        p += __shfl_xor_sync(0xffffffffu, p, 4);
        p += __shfl_xor_sync(0xffffffffu, p, 8);
        if (n == 0) *yp = fmaf(uu, Dv, p);
        dp += dstep; up += dstep; sp += sstep; yp += dstep;
    }
}

// ---------------------------------------------------------------------------
// combine: yt = (yf+yb)*silu(gate), written directly as A-frag hi plane
// ---------------------------------------------------------------------------
__global__ __launch_bounds__(256) void combine_kernel()
{
    const int idx = blockIdx.x * blockDim.x + threadIdx.x;   // over ML*ID/2
    const int R  = idx >> 10;
    const int ch = (idx & 1023) << 1;
    const size_t o = (size_t)R * ID + ch;
    float2 yf = *reinterpret_cast<const float2*>(g_y[0] + o);
    float2 yb = *reinterpret_cast<const float2*>(g_y[1] + o);
    float2 gt = *reinterpret_cast<const float2*>(g_gate + o);
    float yt0 = (yf.x + yb.x) * siluf(gt.x);
    float yt1 = (yf.y + yb.y) * siluf(gt.y);
    const int d = U_YT_A + ((R >> 7) * 64 + (ch >> 5)) * 2048 + afrag_idx(R & 127, ch & 31);
    g_hi[d] = pack_h2(yt0, yt1);
}

// ---------------------------------------------------------------------------
// Launch
// ---------------------------------------------------------------------------
extern "C" void kernel_launch(void* const* d_in, const int* in_sizes, int n_in,
                              void* d_out, int out_size)
{
    const float* hs     = (const float*)d_in[0];
    const float* hs2    = (const float*)d_in[1];
    const float* in_w   = (const float*)d_in[2];
    const float* in_dw  = (const float*)d_in[3];
    const float* conv_w = (const float*)d_in[4];
    const float* conv_b = (const float*)d_in[5];
    const float* xw_f   = (const float*)d_in[6];
    const float* xw_b   = (const float*)d_in[7];
    const float* dtw_f  = (const float*)d_in[8];
    const float* dtb_f  = (const float*)d_in[9];
    const float* dtw_b  = (const float*)d_in[10];
    const float* dtb_b  = (const float*)d_in[11];
    const float* Alog_f = (const float*)d_in[12];
    const float* Alog_b = (const float*)d_in[13];
    const float* D_f    = (const float*)d_in[14];
    const float* D_b    = (const float*)d_in[15];
    const float* outw   = (const float*)d_in[16];
    float* out = (float*)d_out;

    float *px, *pgate, *pdelta;
    cudaGetSymbolAddress((void**)&px,     g_x);
    cudaGetSymbolAddress((void**)&pgate,  g_gate);
    cudaGetSymbolAddress((void**)&pdelta, g_delta);
    float* pd0 = pdelta;
    float* pd1 = pdelta + (size_t)ML*ID;

    cudaFuncSetAttribute(hgemm<0>, cudaFuncAttributeMaxDynamicSharedMemorySize, HG_SMEM_BYTES);
    cudaFuncSetAttribute(hgemm<1>, cudaFuncAttributeMaxDynamicSharedMemorySize, HG_SMEM_BYTES);
    cudaFuncSetAttribute(hgemm_g3, cudaFuncAttributeMaxDynamicSharedMemorySize, HG_SMEM_BYTES);

    // Batched conversions (weights + inputs) in ONE launch
    {
        CTable t;
        t.d[0] = {in_w,                  U_INW_B,  HD, 32, 512, 0, 128};
        t.d[1] = {in_dw + (size_t)ID*HD, U_INDW_B, HD, 32, 512, 0, 128};
        t.d[2] = {dtw_f,                 U_DTW0_B, RD, 2,  32,  0, 128};
        t.d[3] = {dtw_b,                 U_DTW1_B, RD, 2,  32,  0, 128};
        t.d[4] = {outw,                  U_OUTW_B, ID, 64, 512, 0, 128};
        t.d[5] = {hs,                    U_HS_A,   HD, 32, 256, 1, 128};
        t.d[6] = {hs2,                   U_HS2_A,  HD, 32, 256, 1, 128};
        t.d[7] = {xw_f,                  U_XW0_B,  ID, 64, 64,  0, 96};
        t.d[8] = {xw_b,                  U_XW1_B,  ID, 64, 64,  0, 96};
        conv_all<<<2240, 256>>>(t);
    }

    // G1: x = hs @ in_w[:I]^T ; gate = hs2 @ in_dw[I:2I]^T
    {
        HArgs a{U_HS_A,  U_INW_B,  px,    nullptr};
        HArgs b{U_HS2_A, U_INDW_B, pgate, nullptr};
        hgemm<0><<<dim3(ID/64, ML/128, 2), 256, HG_SMEM_BYTES>>>(a, b, 32, ID);
    }

    // conv + silu (+ u hi plane)
    conv_silu_kernel<<<(ML*ID)/512, 256>>>(conv_w, conv_b);

    // G3 on tensor cores: split-K(8) partials then reduce+pack
    hgemm_g3<<<dim3(2, 8, 16), 256, HG_SMEM_BYTES>>>();
    reduce_pack_g3<<<(2*ML*48)/256, 256>>>();

    // G4: delta = softplus(dt @ dt_w^T + b)
    {
        HArgs a{U_SSM0_A, U_DTW0_B, pd0, dtb_f};
        HArgs b{U_SSM1_A, U_DTW1_B, pd1, dtb_b};
        hgemm<1><<<dim3(ID/64, ML/128, 2), 256, HG_SMEM_BYTES>>>(a, b, 2, ID);
    }

    scan_kernel<<<512, 256>>>(Alog_f, Alog_b, D_f, D_b);
    combine_kernel<<<(ML*ID)/512, 256>>>();

    // G5: out = yt @ out_proj_w^T
    {
        HArgs a{U_YT_A, U_OUTW_B, out, nullptr};
        hgemm<0><<<dim3(HD/64, ML/128, 1), 256, HG_SMEM_BYTES>>>(a, a, 64, HD);
    }

    (void)in_sizes; (void)n_in; (void)out_size;
}

// round 14
// speedup vs baseline: 1.3915x; 1.0292x over previous
#include <cuda_runtime.h>
#include <cuda_fp16.h>
#include <cstdint>
#include <cstddef>

// Problem constants
#define HD 1024
#define ID 2048
#define NSTATE 16
#define RD 64
#define BB 2
#define LL 512
#define ML (BB*LL)

// ---------------------------------------------------------------------------
// Scratch
// ---------------------------------------------------------------------------
__device__ __align__(16) float g_x   [(size_t)ML*ID];
__device__ __align__(16) float g_gate[(size_t)ML*ID];
__device__ __align__(16) float g_u   [(size_t)ML*ID];
__device__ __align__(16) float g_ssm [2][(size_t)ML*96];    // only cols 64..95 read (B|C)
__device__ __align__(16) float g_part[2][8][(size_t)ML*96]; // split-K partials for G3
__device__ __align__(16) float g_delta[2][(size_t)ML*ID];
__device__ __align__(16) float g_y   [2][(size_t)ML*ID];

// fp16 split-plane pools (fragment-packed u32 = half2 pairs)
#define U_HS_A    0u
#define U_HS2_A   524288u
#define U_INW_B   1048576u
#define U_INDW_B  2097152u
#define U_SSM0_A  3145728u
#define U_SSM1_A  3178496u
#define U_DTW0_B  3211264u
#define U_DTW1_B  3276800u
#define U_YT_A    3342336u
#define U_OUTW_B  4390912u
#define U_U_A     5439488u
#define U_XW0_B   6488064u
#define U_XW1_B   6619136u
#define U_TOTAL   6750208u
__device__ __align__(16) unsigned g_hi[U_TOTAL];
__device__ __align__(16) unsigned g_lo[U_TOTAL];   // only B (weight) lo planes consumed

__device__ __forceinline__ float siluf(float v)     { return v * (1.0f / (1.0f + __expf(-v))); }
__device__ __forceinline__ float softplusf(float v) { return v > 20.f ? v : log1pf(__expf(v)); }

__device__ __forceinline__ void split_pack(float x0, float x1, unsigned& ph, unsigned& pl) {
    __half h0 = __float2half_rn(x0), h1 = __float2half_rn(x1);
    __half l0 = __float2half_rn(x0 - __half2float(h0));
    __half l1 = __float2half_rn(x1 - __half2float(h1));
    ph = ((unsigned)__half_as_ushort(h1) << 16) | __half_as_ushort(h0);
    pl = ((unsigned)__half_as_ushort(l1) << 16) | __half_as_ushort(l0);
}
__device__ __forceinline__ unsigned pack_h2(float x0, float x1) {
    __half h0 = __float2half_rn(x0), h1 = __float2half_rn(x1);
    return ((unsigned)__half_as_ushort(h1) << 16) | __half_as_ushort(h0);
}

// A-fragment u32 index within a 128x32 chunk, for element pair (r, k even)
__device__ __forceinline__ int afrag_idx(int r, int k) {
    int mt = r >> 4, rr = r & 15;
    int ks = k >> 4, kk = k & 15;
    int lane = ((rr & 7) << 2) | ((kk >> 1) & 3);
    int reg  = (rr >> 3) | ((kk >> 3) << 1);
    return ((mt * 2 + ks) * 32 + lane) * 4 + reg;
}

// ---------------------------------------------------------------------------
// Batched converter: fp32 -> fragment-packed fp16 hi/lo planes.
// ---------------------------------------------------------------------------
struct CDesc { const float* src; unsigned off; int ld; int nchunks; int nblk; int isA; int nrows; };
struct CTable { CDesc d[9]; };

__global__ __launch_bounds__(256) void conv_all(CTable t)
{
    __shared__ float s[128][33];
    int b = blockIdx.x;
    int di = 0;
    while (b >= t.d[di].nblk) { b -= t.d[di].nblk; di++; }
    const CDesc d = t.d[di];
    const int rb = b / d.nchunks, c = b % d.nchunks;
    const int tid = threadIdx.x;
    const float* sp = d.src + (size_t)(rb * 128) * d.ld + c * 32;
#pragma unroll
    for (int it = 0; it < 4; it++) {
        int r = (tid >> 3) + it * 32, c4 = tid & 7;
        float4 v = make_float4(0.f, 0.f, 0.f, 0.f);
        if (r < d.nrows)
            v = *reinterpret_cast<const float4*>(sp + (size_t)r * d.ld + c4 * 4);
        s[r][c4*4+0]=v.x; s[r][c4*4+1]=v.y; s[r][c4*4+2]=v.z; s[r][c4*4+3]=v.w;
    }
    __syncthreads();
    unsigned* oh = g_hi + d.off + (size_t)(rb * d.nchunks + c) * 2048;
    unsigned* ol = g_lo + d.off + (size_t)(rb * d.nchunks + c) * 2048;
    if (d.isA) {
#pragma unroll
        for (int j = 0; j < 8; j++) {
            int idx = tid + 256*j;
            int reg = idx&3, lane=(idx>>2)&31, ks=(idx>>7)&1, mt=idx>>8;
            int r = mt*16 + ((reg&1)<<3) + (lane>>2);
            int k = ks*16 + ((reg>>1)<<3) + ((lane&3)<<1);
            oh[idx] = pack_h2(s[r][k], s[r][k+1]);
        }
    } else {
#pragma unroll
        for (int j = 0; j < 8; j++) {
            int idx = tid + 256*j;
            int reg = idx&1, lane=(idx>>1)&31, ks=(idx>>6)&1, nt=idx>>7;
            int n = nt*8 + (lane>>2);
            int k = ks*16 + reg*8 + ((lane&3)<<1);
            unsigned ph, pl;
            split_pack(s[n][k], s[n][k+1], ph, pl);
            oh[idx] = ph; ol[idx] = pl;
        }
    }
}

// ---------------------------------------------------------------------------
// fp16 2-pass split GEMM (A fp16-hi; B hi+lo), templated tile:
//   MT=2 -> 128x64 tile (4 M-warps x 2 N-warps), B plane 1024 u32/chunk
//   MT=4 -> 128x128 tile (2 M-warps x 4 N-warps), B plane 2048 u32/chunk
// 3-stage cp.async, 2 CTAs/SM.
// ---------------------------------------------------------------------------
struct HArgs { unsigned aoff; unsigned boff; float* C; const float* bias; };

__device__ __forceinline__ void mma_h(float* c, const unsigned* a, const unsigned* b) {
    asm volatile(
        "mma.sync.aligned.m16n8k16.row.col.f32.f16.f16.f32 "
        "{%0,%1,%2,%3},{%4,%5,%6,%7},{%8,%9},{%0,%1,%2,%3};"
        : "+f"(c[0]), "+f"(c[1]), "+f"(c[2]), "+f"(c[3])
        : "r"(a[0]), "r"(a[1]), "r"(a[2]), "r"(a[3]), "r"(b[0]), "r"(b[1]));
}
__device__ __forceinline__ void cp16(unsigned saddr, const void* g) {
    asm volatile("cp.async.cg.shared.global [%0], [%1], 16;" :: "r"(saddr), "l"(g));
}

#define NSTAGE 3
#define SMEM_BYTES_OF(BNU) (NSTAGE * (2048 + 2*(BNU)) * 4)

template<int MT, int BNU, typename EpiFn>
__device__ __forceinline__ void hgemm_body(
    const unsigned* gAh, const unsigned* gBh, const unsigned* gBl,
    int nch, unsigned* sm, unsigned sbase,
    int tid, int lane, int warp_m, int warp_n, EpiFn epi)
{
    constexpr int ST = 2048 + 2 * BNU;
    auto issue = [&](int s, int c) {
        const unsigned dst = sbase + s * (ST * 4);
        const unsigned* a0 = gAh + (size_t)c * 2048;
        const unsigned* b0 = gBh + (size_t)c * 2048;
        const unsigned* b1 = gBl + (size_t)c * 2048;
#pragma unroll
        for (int q = 0; q < 2; q++) {
            const int o = (tid + q * 256) * 4;
            cp16(dst + o * 4, a0 + o);
        }
#pragma unroll
        for (int q = 0; q < BNU/1024; q++) {
            const int o = (tid + q * 256) * 4;
            cp16(dst + 8192 + o * 4,            b0 + o);
            cp16(dst + 8192 + BNU*4 + o * 4,    b1 + o);
        }
        asm volatile("cp.async.commit_group;");
    };

    float acc[MT][4][4];
#pragma unroll
    for (int mt = 0; mt < MT; mt++)
#pragma unroll
        for (int nt = 0; nt < 4; nt++)
#pragma unroll
            for (int j = 0; j < 4; j++) acc[mt][nt][j] = 0.f;

    issue(0, 0);
    if (nch > 1) issue(1, 1);
    int sidx = 0;
    for (int c = 0; c < nch; c++) {
        if (c + 2 < nch) {
            int s2 = sidx + 2; if (s2 >= NSTAGE) s2 -= NSTAGE;
            issue(s2, c + 2);
            asm volatile("cp.async.wait_group 2;");
        } else if (c + 1 < nch) {
            asm volatile("cp.async.wait_group 1;");
        } else {
            asm volatile("cp.async.wait_group 0;");
        }
        __syncthreads();
        const unsigned* st  = sm + sidx * ST;
        const unsigned* sAh = st;
        const unsigned* sBh = st + 2048;
        const unsigned* sBl = st + 2048 + BNU;
#pragma unroll
        for (int ks = 0; ks < 2; ks++) {
            unsigned ah[MT][4], bh[4][2], bl[4][2];
#pragma unroll
            for (int mt = 0; mt < MT; mt++) {
                const int base = (((warp_m*MT + mt)*2 + ks)*32 + lane) * 4;
                uint4 v = *reinterpret_cast<const uint4*>(sAh + base);
                ah[mt][0]=v.x; ah[mt][1]=v.y; ah[mt][2]=v.z; ah[mt][3]=v.w;
            }
#pragma unroll
            for (int nt = 0; nt < 4; nt++) {
                const int base = (((warp_n*4 + nt)*2 + ks)*32 + lane) * 2;
                uint2 v = *reinterpret_cast<const uint2*>(sBh + base);
                bh[nt][0]=v.x; bh[nt][1]=v.y;
                v = *reinterpret_cast<const uint2*>(sBl + base);
                bl[nt][0]=v.x; bl[nt][1]=v.y;
            }
#pragma unroll
            for (int mt = 0; mt < MT; mt++)
#pragma unroll
                for (int nt = 0; nt < 4; nt++) mma_h(acc[mt][nt], ah[mt], bh[nt]);
#pragma unroll
            for (int mt = 0; mt < MT; mt++)
#pragma unroll
                for (int nt = 0; nt < 4; nt++) mma_h(acc[mt][nt], ah[mt], bl[nt]);
        }
        __syncthreads();
        if (++sidx == NSTAGE) sidx = 0;
    }
    epi(acc);
}

template<int EPI, int MT, int BNU>
__global__ __launch_bounds__(256, 2) void hgemm(HArgs h0, HArgs h1, int nchunks, int ldc)
{
    extern __shared__ unsigned sm[];
    const unsigned sbase = (unsigned)__cvta_generic_to_shared(sm);
    HArgs h = blockIdx.z ? h1 : h0;
    const int tid = threadIdx.x, lane = tid & 31, wid = tid >> 5;
    const int warp_m = (MT == 2) ? (wid & 3) : (wid & 1);
    const int warp_n = (MT == 2) ? (wid >> 2) : (wid >> 1);
    constexpr int BN = (BNU == 1024) ? 64 : 128;
    const int row0 = blockIdx.y * 128, col0 = blockIdx.x * BN;
    const unsigned* gAh = g_hi + h.aoff + (size_t)blockIdx.y * nchunks * 2048;
    const size_t bbase = h.boff + (size_t)(col0 >> 7) * nchunks * 2048 + ((col0 >> 6) & 1) * 1024;
    const unsigned* gBh = g_hi + bbase;
    const unsigned* gBl = g_lo + bbase;
    const int rw = lane >> 2, cw = (lane & 3) * 2;

    hgemm_body<MT, BNU>(gAh, gBh, gBl, nchunks, sm, sbase, tid, lane, warp_m, warp_n,
        [&](float acc[MT][4][4]) {
#pragma unroll
            for (int mt = 0; mt < MT; mt++) {
                const int m = row0 + warp_m*(MT*16) + mt*16 + rw;
#pragma unroll
                for (int nt = 0; nt < 4; nt++) {
                    const int n = col0 + warp_n*32 + nt*8 + cw;
                    float v0 = acc[mt][nt][0], v1 = acc[mt][nt][1];
                    float v2 = acc[mt][nt][2], v3 = acc[mt][nt][3];
                    if (EPI == 1) {
                        const float b0 = __ldg(h.bias + n);
                        const float b1 = __ldg(h.bias + n + 1);
                        v0 = softplusf(v0 + b0); v1 = softplusf(v1 + b1);
                        v2 = softplusf(v2 + b0); v3 = softplusf(v3 + b1);
                    }
                    *reinterpret_cast<float2*>(h.C + (size_t)m * ldc + n)       = make_float2(v0, v1);
                    *reinterpret_cast<float2*>(h.C + (size_t)(m + 8) * ldc + n) = make_float2(v2, v3);
                }
            }
        });
}

// G3 tensor GEMM: partial[dir][split] = u[mblock, Kseg] @ xw^T (N=96 padded to 128)
// grid (2 nblocks, 8 mblocks, 16 = dir*8+split), 8 chunks per block; 128x64 tile
__global__ __launch_bounds__(256, 2) void hgemm_g3()
{
    extern __shared__ unsigned sm[];
    const unsigned sbase = (unsigned)__cvta_generic_to_shared(sm);
    const int nblock = blockIdx.x, mblock = blockIdx.y;
    const int dir = blockIdx.z >> 3, split = blockIdx.z & 7;
    const int tid = threadIdx.x, lane = tid & 31, wid = tid >> 5;
    const int warp_m = wid & 3, warp_n = wid >> 2;
    const size_t abase = U_U_A + (size_t)mblock * 64 * 2048 + (size_t)split * 8 * 2048;
    const unsigned* gAh = g_hi + abase;
    const size_t bbase = (dir ? U_XW1_B : U_XW0_B) + (size_t)split * 8 * 2048 + nblock * 1024;
    const unsigned* gBh = g_hi + bbase;
    const unsigned* gBl = g_lo + bbase;
    const int row0 = mblock * 128, col0 = nblock * 64;
    const int rw = lane >> 2, cw = (lane & 3) * 2;
    float* C = g_part[dir][split];

    hgemm_body<2, 1024>(gAh, gBh, gBl, 8, sm, sbase, tid, lane, warp_m, warp_n,
        [&](float acc[2][4][4]) {
#pragma unroll
            for (int mt = 0; mt < 2; mt++) {
                const int m = row0 + warp_m*32 + mt*16 + rw;
#pragma unroll
                for (int nt = 0; nt < 4; nt++) {
                    const int n = col0 + warp_n*32 + nt*8 + cw;
                    if (n < 96) {
                        *reinterpret_cast<float2*>(C + (size_t)m * 96 + n) =
                            make_float2(acc[mt][nt][0], acc[mt][nt][1]);
                        *reinterpret_cast<float2*>(C + (size_t)(m + 8) * 96 + n) =
                            make_float2(acc[mt][nt][2], acc[mt][nt][3]);
                    }
                }
            }
        });
}

// ---------------------------------------------------------------------------
// reduce partials; dt cols -> hi plane (A-frag layout), B/C cols -> g_ssm
// ---------------------------------------------------------------------------
__global__ __launch_bounds__(256) void reduce_pack_g3()
{
    const int idx = blockIdx.x * blockDim.x + threadIdx.x;   // < 2*1024*48
    const int pr  = idx % 48;
    const int R   = (idx / 48) % ML;
    const int dir = idx / (48 * ML);
    const int c0  = pr * 2;
    const size_t o = (size_t)R * 96 + c0;
    float2 s = make_float2(0.f, 0.f);
#pragma unroll
    for (int p = 0; p < 8; p++) {
        float2 v = *reinterpret_cast<const float2*>(g_part[dir][p] + o);
        s.x += v.x; s.y += v.y;
    }
    if (c0 < 64) {
        const unsigned uoff = dir ? U_SSM1_A : U_SSM0_A;
        const int d = uoff + ((R >> 7) * 2 + (c0 >> 5)) * 2048 + afrag_idx(R & 127, c0 & 31);
        g_hi[d] = pack_h2(s.x, s.y);
    } else {
        *reinterpret_cast<float2*>(g_ssm[dir] + o) = s;
    }
}

// ---------------------------------------------------------------------------
// conv + silu; emits u float + A-fragment hi plane for tensor G3
// ---------------------------------------------------------------------------
__global__ __launch_bounds__(256) void conv_silu_kernel(const float* __restrict__ w,
                                                        const float* __restrict__ bias)
{
    const int idx = blockIdx.x * blockDim.x + threadIdx.x;   // < ML*ID/2
    const int R  = idx >> 10;
    const int ch = (idx & 1023) << 1;
    const int l  = R & (LL - 1);
    const size_t o = (size_t)R * ID + ch;
    float acc0 = bias[ch], acc1 = bias[ch + 1];
#pragma unroll
    for (int k = 0; k < 4; k++) {
        int ls = l - 3 + k;
        if (ls >= 0) {
            float2 xv = *reinterpret_cast<const float2*>(g_x + o + (ptrdiff_t)(k - 3) * ID);
            acc0 = fmaf(xv.x, w[ch*4 + k],       acc0);
            acc1 = fmaf(xv.y, w[(ch+1)*4 + k],   acc1);
        }
    }
    float u0 = siluf(acc0), u1 = siluf(acc1);
    *reinterpret_cast<float2*>(g_u + o) = make_float2(u0, u1);
    const int d = U_U_A + ((R >> 7) * 64 + (ch >> 5)) * 2048 + afrag_idx(R & 127, ch & 31);
    g_hi[d] = pack_h2(u0, u1);
}

// ---------------------------------------------------------------------------
// selective scan
// ---------------------------------------------------------------------------
__global__ void scan_kernel(const float* __restrict__ Alog_f,
                            const float* __restrict__ Alog_b,
                            const float* __restrict__ D_f,
                            const float* __restrict__ D_b)
{
    int gw   = (blockIdx.x * blockDim.x + threadIdx.x) >> 5;
    int lane = threadIdx.x & 31;
    int dir  = gw >> 11;
    int b    = (gw >> 10) & 1;
    int i    = ((gw & 1023) << 1) | (lane >> 4);
    int n    = lane & 15;

    const float* Alog = dir ? Alog_b : Alog_f;
    float An = -expf(Alog[i*NSTATE + n]);
    float Dv = dir ? D_b[i] : D_f[i];

    const float* dbase = g_delta[dir] + (size_t)(b*LL)*ID + i;
    const float* ubase = g_u          + (size_t)(b*LL)*ID + i;
    const float* sbase = g_ssm[dir]   + (size_t)(b*LL)*96;
    float*       ybase = g_y[dir]     + (size_t)(b*LL)*ID + i;

    int l0 = dir ? (LL-1) : 0;
    ptrdiff_t dstep = dir ? -(ptrdiff_t)ID : (ptrdiff_t)ID;
    ptrdiff_t sstep = dir ? -96 : 96;

    const float* dp = dbase + (size_t)l0*ID;
    const float* up = ubase + (size_t)l0*ID;
    const float* sp = sbase + (size_t)l0*96;
    float*       yp = ybase + (size_t)l0*ID;

    float x = 0.f;
#pragma unroll 2
    for (int t = 0; t < LL; t++) {
        float d  = *dp;
        float uu = *up;
        float Bv = *(sp + RD + n);
        float Cv = *(sp + RD + NSTATE + n);
        float dA = __expf(d * An);
        x = fmaf(x, dA, d * Bv * uu);
        float p = x * Cv;
        p += __shfl_xor_sync(0xffffffffu, p, 1);
        p += __shfl_xor_sync(0xffffffffu, p, 2);
        p += __shfl_xor_sync(0xffffffffu, p, 4);
        p += __shfl_xor_sync(0xffffffffu, p, 8);
        if (n == 0) *yp = fmaf(uu, Dv, p);
        dp += dstep; up += dstep; sp += sstep; yp += dstep;
    }
}

// ---------------------------------------------------------------------------
// combine: yt = (yf+yb)*silu(gate), written directly as A-frag hi plane
// ---------------------------------------------------------------------------
__global__ __launch_bounds__(256) void combine_kernel()
{
    const int idx = blockIdx.x * blockDim.x + threadIdx.x;   // over ML*ID/2
    const int R  = idx >> 10;
    const int ch = (idx & 1023) << 1;
    const size_t o = (size_t)R * ID + ch;
    float2 yf = *reinterpret_cast<const float2*>(g_y[0] + o);
    float2 yb = *reinterpret_cast<const float2*>(g_y[1] + o);
    float2 gt = *reinterpret_cast<const float2*>(g_gate + o);
    float yt0 = (yf.x + yb.x) * siluf(gt.x);
    float yt1 = (yf.y + yb.y) * siluf(gt.y);
    const int d = U_YT_A + ((R >> 7) * 64 + (ch >> 5)) * 2048 + afrag_idx(R & 127, ch & 31);
    g_hi[d] = pack_h2(yt0, yt1);
}

// ---------------------------------------------------------------------------
// Launch
// ---------------------------------------------------------------------------
extern "C" void kernel_launch(void* const* d_in, const int* in_sizes, int n_in,
                              void* d_out, int out_size)
{
    const float* hs     = (const float*)d_in[0];
    const float* hs2    = (const float*)d_in[1];
    const float* in_w   = (const float*)d_in[2];
    const float* in_dw  = (const float*)d_in[3];
    const float* conv_w = (const float*)d_in[4];
    const float* conv_b = (const float*)d_in[5];
    const float* xw_f   = (const float*)d_in[6];
    const float* xw_b   = (const float*)d_in[7];
    const float* dtw_f  = (const float*)d_in[8];
    const float* dtb_f  = (const float*)d_in[9];
    const float* dtw_b  = (const float*)d_in[10];
    const float* dtb_b  = (const float*)d_in[11];
    const float* Alog_f = (const float*)d_in[12];
    const float* Alog_b = (const float*)d_in[13];
    const float* D_f    = (const float*)d_in[14];
    const float* D_b    = (const float*)d_in[15];
    const float* outw   = (const float*)d_in[16];
    float* out = (float*)d_out;

    float *px, *pgate, *pdelta;
    cudaGetSymbolAddress((void**)&px,     g_x);
    cudaGetSymbolAddress((void**)&pgate,  g_gate);
    cudaGetSymbolAddress((void**)&pdelta, g_delta);
    float* pd0 = pdelta;
    float* pd1 = pdelta + (size_t)ML*ID;

    cudaFuncSetAttribute((const void*)hgemm<0,4,2048>, cudaFuncAttributeMaxDynamicSharedMemorySize, SMEM_BYTES_OF(2048));
    cudaFuncSetAttribute((const void*)hgemm<1,4,2048>, cudaFuncAttributeMaxDynamicSharedMemorySize, SMEM_BYTES_OF(2048));
    cudaFuncSetAttribute((const void*)hgemm<0,2,1024>, cudaFuncAttributeMaxDynamicSharedMemorySize, SMEM_BYTES_OF(1024));
    cudaFuncSetAttribute((const void*)hgemm_g3,        cudaFuncAttributeMaxDynamicSharedMemorySize, SMEM_BYTES_OF(1024));

    // Batched conversions (weights + inputs) in ONE launch
    {
        CTable t;
        t.d[0] = {in_w,                  U_INW_B,  HD, 32, 512, 0, 128};
        t.d[1] = {in_dw + (size_t)ID*HD, U_INDW_B, HD, 32, 512, 0, 128};
        t.d[2] = {dtw_f,                 U_DTW0_B, RD, 2,  32,  0, 128};
        t.d[3] = {dtw_b,                 U_DTW1_B, RD, 2,  32,  0, 128};
        t.d[4] = {outw,                  U_OUTW_B, ID, 64, 512, 0, 128};
        t.d[5] = {hs,                    U_HS_A,   HD, 32, 256, 1, 128};
        t.d[6] = {hs2,                   U_HS2_A,  HD, 32, 256, 1, 128};
        t.d[7] = {xw_f,                  U_XW0_B,  ID, 64, 64,  0, 96};
        t.d[8] = {xw_b,                  U_XW1_B,  ID, 64, 64,  0, 96};
        conv_all<<<2240, 256>>>(t);
    }

    // G1: x = hs @ in_w[:I]^T ; gate = hs2 @ in_dw[I:2I]^T   (128x128 tiles)
    {
        HArgs a{U_HS_A,  U_INW_B,  px,    nullptr};
        HArgs b{U_HS2_A, U_INDW_B, pgate, nullptr};
        hgemm<0,4,2048><<<dim3(ID/128, ML/128, 2), 256, SMEM_BYTES_OF(2048)>>>(a, b, 32, ID);
    }

    // conv + silu (+ u hi plane)
    conv_silu_kernel<<<(ML*ID)/512, 256>>>(conv_w, conv_b);

    // G3 on tensor cores: split-K(8) partials then reduce+pack  (128x64 tiles)
    hgemm_g3<<<dim3(2, 8, 16), 256, SMEM_BYTES_OF(1024)>>>();
    reduce_pack_g3<<<(2*ML*48)/256, 256>>>();

    // G4: delta = softplus(dt @ dt_w^T + b)   (128x128 tiles)
    {
        HArgs a{U_SSM0_A, U_DTW0_B, pd0, dtb_f};
        HArgs b{U_SSM1_A, U_DTW1_B, pd1, dtb_b};
        hgemm<1,4,2048><<<dim3(ID/128, ML/128, 2), 256, SMEM_BYTES_OF(2048)>>>(a, b, 2, ID);
    }

    scan_kernel<<<512, 256>>>(Alog_f, Alog_b, D_f, D_b);
    combine_kernel<<<(ML*ID)/512, 256>>>();

    // G5: out = yt @ out_proj_w^T   (128x64 tiles, grid 128)
    {
        HArgs a{U_YT_A, U_OUTW_B, out, nullptr};
        hgemm<0,2,1024><<<dim3(HD/64, ML/128, 1), 256, SMEM_BYTES_OF(1024)>>>(a, a, 64, HD);
    }

    (void)in_sizes; (void)n_in; (void)out_size;
}

// round 15
// speedup vs baseline: 1.4001x; 1.0062x over previous
#include <cuda_runtime.h>
#include <cuda_fp16.h>
#include <cstdint>
#include <cstddef>

// Problem constants
#define HD 1024
#define ID 2048
#define NSTATE 16
#define RD 64
#define BB 2
#define LL 512
#define ML (BB*LL)

// ---------------------------------------------------------------------------
// Scratch
// ---------------------------------------------------------------------------
__device__ __align__(16) float g_x   [(size_t)ML*ID];
__device__ __align__(16) float g_gate[(size_t)ML*ID];
__device__ __align__(16) float g_u   [(size_t)ML*ID];
__device__ __align__(16) float g_ssm [2][(size_t)ML*96];    // only cols 64..95 read (B|C)
__device__ __align__(16) float g_part[2][8][(size_t)ML*96]; // split-K partials for G3
__device__ __align__(16) float g_delta[2][(size_t)ML*ID];   // delta; reused as G5 partials
__device__ __align__(16) float g_y   [2][(size_t)ML*ID];

// fp16 split-plane pools (fragment-packed u32 = half2 pairs)
#define U_HS_A    0u
#define U_HS2_A   524288u
#define U_INW_B   1048576u
#define U_INDW_B  2097152u
#define U_SSM0_A  3145728u
#define U_SSM1_A  3178496u
#define U_DTW0_B  3211264u
#define U_DTW1_B  3276800u
#define U_YT_A    3342336u
#define U_OUTW_B  4390912u
#define U_U_A     5439488u
#define U_XW0_B   6488064u
#define U_XW1_B   6619136u
#define U_TOTAL   6750208u
__device__ __align__(16) unsigned g_hi[U_TOTAL];
__device__ __align__(16) unsigned g_lo[U_TOTAL];   // only B (weight) lo planes consumed

__device__ __forceinline__ float siluf(float v)     { return v * (1.0f / (1.0f + __expf(-v))); }
__device__ __forceinline__ float softplusf(float v) { return v > 20.f ? v : log1pf(__expf(v)); }

__device__ __forceinline__ void split_pack(float x0, float x1, unsigned& ph, unsigned& pl) {
    __half h0 = __float2half_rn(x0), h1 = __float2half_rn(x1);
    __half l0 = __float2half_rn(x0 - __half2float(h0));
    __half l1 = __float2half_rn(x1 - __half2float(h1));
    ph = ((unsigned)__half_as_ushort(h1) << 16) | __half_as_ushort(h0);
    pl = ((unsigned)__half_as_ushort(l1) << 16) | __half_as_ushort(l0);
}
__device__ __forceinline__ unsigned pack_h2(float x0, float x1) {
    __half h0 = __float2half_rn(x0), h1 = __float2half_rn(x1);
    return ((unsigned)__half_as_ushort(h1) << 16) | __half_as_ushort(h0);
}

// A-fragment u32 index within a 128x32 chunk, for element pair (r, k even)
__device__ __forceinline__ int afrag_idx(int r, int k) {
    int mt = r >> 4, rr = r & 15;
    int ks = k >> 4, kk = k & 15;
    int lane = ((rr & 7) << 2) | ((kk >> 1) & 3);
    int reg  = (rr >> 3) | ((kk >> 3) << 1);
    return ((mt * 2 + ks) * 32 + lane) * 4 + reg;
}

// ---------------------------------------------------------------------------
// Batched converter: fp32 -> fragment-packed fp16 hi/lo planes.
// ---------------------------------------------------------------------------
struct CDesc { const float* src; unsigned off; int ld; int nchunks; int nblk; int isA; int nrows; };
struct CTable { CDesc d[9]; };

__global__ __launch_bounds__(256) void conv_all(CTable t)
{
    __shared__ float s[128][33];
    int b = blockIdx.x;
    int di = 0;
    while (b >= t.d[di].nblk) { b -= t.d[di].nblk; di++; }
    const CDesc d = t.d[di];
    const int rb = b / d.nchunks, c = b % d.nchunks;
    const int tid = threadIdx.x;
    const float* sp = d.src + (size_t)(rb * 128) * d.ld + c * 32;
#pragma unroll
    for (int it = 0; it < 4; it++) {
        int r = (tid >> 3) + it * 32, c4 = tid & 7;
        float4 v = make_float4(0.f, 0.f, 0.f, 0.f);
        if (r < d.nrows)
            v = *reinterpret_cast<const float4*>(sp + (size_t)r * d.ld + c4 * 4);
        s[r][c4*4+0]=v.x; s[r][c4*4+1]=v.y; s[r][c4*4+2]=v.z; s[r][c4*4+3]=v.w;
    }
    __syncthreads();
    unsigned* oh = g_hi + d.off + (size_t)(rb * d.nchunks + c) * 2048;
    unsigned* ol = g_lo + d.off + (size_t)(rb * d.nchunks + c) * 2048;
    if (d.isA) {
#pragma unroll
        for (int j = 0; j < 8; j++) {
            int idx = tid + 256*j;
            int reg = idx&3, lane=(idx>>2)&31, ks=(idx>>7)&1, mt=idx>>8;
            int r = mt*16 + ((reg&1)<<3) + (lane>>2);
            int k = ks*16 + ((reg>>1)<<3) + ((lane&3)<<1);
            oh[idx] = pack_h2(s[r][k], s[r][k+1]);
        }
    } else {
#pragma unroll
        for (int j = 0; j < 8; j++) {
            int idx = tid + 256*j;
            int reg = idx&1, lane=(idx>>1)&31, ks=(idx>>6)&1, nt=idx>>7;
            int n = nt*8 + (lane>>2);
            int k = ks*16 + reg*8 + ((lane&3)<<1);
            unsigned ph, pl;
            split_pack(s[n][k], s[n][k+1], ph, pl);
            oh[idx] = ph; ol[idx] = pl;
        }
    }
}

// ---------------------------------------------------------------------------
// fp16 2-pass split GEMM (A fp16-hi; B hi+lo), templated tile, 4-stage cp.async.
//   MT=2 -> 128x64 tile, MT=4 -> 128x128 tile
// ---------------------------------------------------------------------------
struct HArgs { unsigned aoff; unsigned boff; float* C; const float* bias;
               unsigned astr; unsigned bstr; };

__device__ __forceinline__ void mma_h(float* c, const unsigned* a, const unsigned* b) {
    asm volatile(
        "mma.sync.aligned.m16n8k16.row.col.f32.f16.f16.f32 "
        "{%0,%1,%2,%3},{%4,%5,%6,%7},{%8,%9},{%0,%1,%2,%3};"
        : "+f"(c[0]), "+f"(c[1]), "+f"(c[2]), "+f"(c[3])
        : "r"(a[0]), "r"(a[1]), "r"(a[2]), "r"(a[3]), "r"(b[0]), "r"(b[1]));
}
__device__ __forceinline__ void cp16(unsigned saddr, const void* g) {
    asm volatile("cp.async.cg.shared.global [%0], [%1], 16;" :: "r"(saddr), "l"(g));
}

#define NSTAGE 4
#define SMEM_BYTES_OF(BNU) (NSTAGE * (2048 + 2*(BNU)) * 4)

template<int MT, int BNU, typename EpiFn>
__device__ __forceinline__ void hgemm_body(
    const unsigned* gAh, const unsigned* gBh, const unsigned* gBl,
    int nch, unsigned* sm, unsigned sbase,
    int tid, int lane, int warp_m, int warp_n, EpiFn epi)
{
    constexpr int ST = 2048 + 2 * BNU;
    auto issue = [&](int s, int c) {
        const unsigned dst = sbase + s * (ST * 4);
        const unsigned* a0 = gAh + (size_t)c * 2048;
        const unsigned* b0 = gBh + (size_t)c * 2048;
        const unsigned* b1 = gBl + (size_t)c * 2048;
#pragma unroll
        for (int q = 0; q < 2; q++) {
            const int o = (tid + q * 256) * 4;
            cp16(dst + o * 4, a0 + o);
        }
#pragma unroll
        for (int q = 0; q < BNU/1024; q++) {
            const int o = (tid + q * 256) * 4;
            cp16(dst + 8192 + o * 4,            b0 + o);
            cp16(dst + 8192 + BNU*4 + o * 4,    b1 + o);
        }
        asm volatile("cp.async.commit_group;");
    };

    float acc[MT][4][4];
#pragma unroll
    for (int mt = 0; mt < MT; mt++)
#pragma unroll
        for (int nt = 0; nt < 4; nt++)
#pragma unroll
            for (int j = 0; j < 4; j++) acc[mt][nt][j] = 0.f;

    issue(0, 0);
    if (nch > 1) issue(1, 1);
    if (nch > 2) issue(2, 2);
    int sidx = 0;
    for (int c = 0; c < nch; c++) {
        if (c + 3 < nch) {
            int s3 = sidx + 3; if (s3 >= NSTAGE) s3 -= NSTAGE;
            issue(s3, c + 3);
            asm volatile("cp.async.wait_group 3;");
        } else if (c + 2 < nch) {
            asm volatile("cp.async.wait_group 2;");
        } else if (c + 1 < nch) {
            asm volatile("cp.async.wait_group 1;");
        } else {
            asm volatile("cp.async.wait_group 0;");
        }
        __syncthreads();
        const unsigned* st  = sm + sidx * ST;
        const unsigned* sAh = st;
        const unsigned* sBh = st + 2048;
        const unsigned* sBl = st + 2048 + BNU;
#pragma unroll
        for (int ks = 0; ks < 2; ks++) {
            unsigned ah[MT][4], bh[4][2], bl[4][2];
#pragma unroll
            for (int mt = 0; mt < MT; mt++) {
                const int base = (((warp_m*MT + mt)*2 + ks)*32 + lane) * 4;
                uint4 v = *reinterpret_cast<const uint4*>(sAh + base);
                ah[mt][0]=v.x; ah[mt][1]=v.y; ah[mt][2]=v.z; ah[mt][3]=v.w;
            }
#pragma unroll
            for (int nt = 0; nt < 4; nt++) {
                const int base = (((warp_n*4 + nt)*2 + ks)*32 + lane) * 2;
                uint2 v = *reinterpret_cast<const uint2*>(sBh + base);
                bh[nt][0]=v.x; bh[nt][1]=v.y;
                v = *reinterpret_cast<const uint2*>(sBl + base);
                bl[nt][0]=v.x; bl[nt][1]=v.y;
            }
#pragma unroll
            for (int mt = 0; mt < MT; mt++)
#pragma unroll
                for (int nt = 0; nt < 4; nt++) mma_h(acc[mt][nt], ah[mt], bh[nt]);
#pragma unroll
            for (int mt = 0; mt < MT; mt++)
#pragma unroll
                for (int nt = 0; nt < 4; nt++) mma_h(acc[mt][nt], ah[mt], bl[nt]);
        }
        __syncthreads();
        if (++sidx == NSTAGE) sidx = 0;
    }
    epi(acc);
}

template<int EPI, int MT, int BNU>
__global__ __launch_bounds__(256, 2) void hgemm(HArgs h0, HArgs h1, int nchunks, int ldc)
{
    extern __shared__ unsigned sm[];
    const unsigned sbase = (unsigned)__cvta_generic_to_shared(sm);
    HArgs h = blockIdx.z ? h1 : h0;
    const int tid = threadIdx.x, lane = tid & 31, wid = tid >> 5;
    const int warp_m = (MT == 2) ? (wid & 3) : (wid & 1);
    const int warp_n = (MT == 2) ? (wid >> 2) : (wid >> 1);
    constexpr int BN = (BNU == 1024) ? 64 : 128;
    const int row0 = blockIdx.y * 128, col0 = blockIdx.x * BN;
    const unsigned* gAh = g_hi + h.aoff + (size_t)blockIdx.y * h.astr;
    const size_t bbase = h.boff + (size_t)(col0 >> 7) * h.bstr + ((col0 >> 6) & 1) * 1024;
    const unsigned* gBh = g_hi + bbase;
    const unsigned* gBl = g_lo + bbase;
    const int rw = lane >> 2, cw = (lane & 3) * 2;

    hgemm_body<MT, BNU>(gAh, gBh, gBl, nchunks, sm, sbase, tid, lane, warp_m, warp_n,
        [&](float acc[MT][4][4]) {
#pragma unroll
            for (int mt = 0; mt < MT; mt++) {
                const int m = row0 + warp_m*(MT*16) + mt*16 + rw;
#pragma unroll
                for (int nt = 0; nt < 4; nt++) {
                    const int n = col0 + warp_n*32 + nt*8 + cw;
                    float v0 = acc[mt][nt][0], v1 = acc[mt][nt][1];
                    float v2 = acc[mt][nt][2], v3 = acc[mt][nt][3];
                    if (EPI == 1) {
                        const float b0 = __ldg(h.bias + n);
                        const float b1 = __ldg(h.bias + n + 1);
                        v0 = softplusf(v0 + b0); v1 = softplusf(v1 + b1);
                        v2 = softplusf(v2 + b0); v3 = softplusf(v3 + b1);
                    }
                    *reinterpret_cast<float2*>(h.C + (size_t)m * ldc + n)       = make_float2(v0, v1);
                    *reinterpret_cast<float2*>(h.C + (size_t)(m + 8) * ldc + n) = make_float2(v2, v3);
                }
            }
        });
}

// G3 tensor GEMM: partial[dir][split] = u[mblock, Kseg] @ xw^T (N=96 padded to 128)
// grid (2 nblocks, 8 mblocks, 16 = dir*8+split), 8 chunks per block; 128x64 tile
__global__ __launch_bounds__(256, 2) void hgemm_g3()
{
    extern __shared__ unsigned sm[];
    const unsigned sbase = (unsigned)__cvta_generic_to_shared(sm);
    const int nblock = blockIdx.x, mblock = blockIdx.y;
    const int dir = blockIdx.z >> 3, split = blockIdx.z & 7;
    const int tid = threadIdx.x, lane = tid & 31, wid = tid >> 5;
    const int warp_m = wid & 3, warp_n = wid >> 2;
    const size_t abase = U_U_A + (size_t)mblock * 64 * 2048 + (size_t)split * 8 * 2048;
    const unsigned* gAh = g_hi + abase;
    const size_t bbase = (dir ? U_XW1_B : U_XW0_B) + (size_t)split * 8 * 2048 + nblock * 1024;
    const unsigned* gBh = g_hi + bbase;
    const unsigned* gBl = g_lo + bbase;
    const int row0 = mblock * 128, col0 = nblock * 64;
    const int rw = lane >> 2, cw = (lane & 3) * 2;
    float* C = g_part[dir][split];

    hgemm_body<2, 1024>(gAh, gBh, gBl, 8, sm, sbase, tid, lane, warp_m, warp_n,
        [&](float acc[2][4][4]) {
#pragma unroll
            for (int mt = 0; mt < 2; mt++) {
                const int m = row0 + warp_m*32 + mt*16 + rw;
#pragma unroll
                for (int nt = 0; nt < 4; nt++) {
                    const int n = col0 + warp_n*32 + nt*8 + cw;
                    if (n < 96) {
                        *reinterpret_cast<float2*>(C + (size_t)m * 96 + n) =
                            make_float2(acc[mt][nt][0], acc[mt][nt][1]);
                        *reinterpret_cast<float2*>(C + (size_t)(m + 8) * 96 + n) =
                            make_float2(acc[mt][nt][2], acc[mt][nt][3]);
                    }
                }
            }
        });
}

// ---------------------------------------------------------------------------
// reduce partials; dt cols -> hi plane (A-frag layout), B/C cols -> g_ssm
// ---------------------------------------------------------------------------
__global__ __launch_bounds__(256) void reduce_pack_g3()
{
    const int idx = blockIdx.x * blockDim.x + threadIdx.x;   // < 2*1024*48
    const int pr  = idx % 48;
    const int R   = (idx / 48) % ML;
    const int dir = idx / (48 * ML);
    const int c0  = pr * 2;
    const size_t o = (size_t)R * 96 + c0;
    float2 s = make_float2(0.f, 0.f);
#pragma unroll
    for (int p = 0; p < 8; p++) {
        float2 v = *reinterpret_cast<const float2*>(g_part[dir][p] + o);
        s.x += v.x; s.y += v.y;
    }
    if (c0 < 64) {
        const unsigned uoff = dir ? U_SSM1_A : U_SSM0_A;
        const int d = uoff + ((R >> 7) * 2 + (c0 >> 5)) * 2048 + afrag_idx(R & 127, c0 & 31);
        g_hi[d] = pack_h2(s.x, s.y);
    } else {
        *reinterpret_cast<float2*>(g_ssm[dir] + o) = s;
    }
}

// ---------------------------------------------------------------------------
// conv + silu; emits u float + A-fragment hi plane for tensor G3
// ---------------------------------------------------------------------------
__global__ __launch_bounds__(256) void conv_silu_kernel(const float* __restrict__ w,
                                                        const float* __restrict__ bias)
{
    const int idx = blockIdx.x * blockDim.x + threadIdx.x;   // < ML*ID/2
    const int R  = idx >> 10;
    const int ch = (idx & 1023) << 1;
    const int l  = R & (LL - 1);
    const size_t o = (size_t)R * ID + ch;
    float acc0 = bias[ch], acc1 = bias[ch + 1];
#pragma unroll
    for (int k = 0; k < 4; k++) {
        int ls = l - 3 + k;
        if (ls >= 0) {
            float2 xv = *reinterpret_cast<const float2*>(g_x + o + (ptrdiff_t)(k - 3) * ID);
            acc0 = fmaf(xv.x, w[ch*4 + k],       acc0);
            acc1 = fmaf(xv.y, w[(ch+1)*4 + k],   acc1);
        }
    }
    float u0 = siluf(acc0), u1 = siluf(acc1);
    *reinterpret_cast<float2*>(g_u + o) = make_float2(u0, u1);
    const int d = U_U_A + ((R >> 7) * 64 + (ch >> 5)) * 2048 + afrag_idx(R & 127, ch & 31);
    g_hi[d] = pack_h2(u0, u1);
}

// ---------------------------------------------------------------------------
// selective scan
// ---------------------------------------------------------------------------
__global__ void scan_kernel(const float* __restrict__ Alog_f,
                            const float* __restrict__ Alog_b,
                            const float* __restrict__ D_f,
                            const float* __restrict__ D_b)
{
    int gw   = (blockIdx.x * blockDim.x + threadIdx.x) >> 5;
    int lane = threadIdx.x & 31;
    int dir  = gw >> 11;
    int b    = (gw >> 10) & 1;
    int i    = ((gw & 1023) << 1) | (lane >> 4);
    int n    = lane & 15;

    const float* Alog = dir ? Alog_b : Alog_f;
    float An = -expf(Alog[i*NSTATE + n]);
    float Dv = dir ? D_b[i] : D_f[i];

    const float* dbase = g_delta[dir] + (size_t)(b*LL)*ID + i;
    const float* ubase = g_u          + (size_t)(b*LL)*ID + i;
    const float* sbase = g_ssm[dir]   + (size_t)(b*LL)*96;
    float*       ybase = g_y[dir]     + (size_t)(b*LL)*ID + i;

    int l0 = dir ? (LL-1) : 0;
    ptrdiff_t dstep = dir ? -(ptrdiff_t)ID : (ptrdiff_t)ID;
    ptrdiff_t sstep = dir ? -96 : 96;

    const float* dp = dbase + (size_t)l0*ID;
    const float* up = ubase + (size_t)l0*ID;
    const float* sp = sbase + (size_t)l0*96;
    float*       yp = ybase + (size_t)l0*ID;

    float x = 0.f;
#pragma unroll 2
    for (int t = 0; t < LL; t++) {
        float d  = *dp;
        float uu = *up;
        float Bv = *(sp + RD + n);
        float Cv = *(sp + RD + NSTATE + n);
        float dA = __expf(d * An);
        x = fmaf(x, dA, d * Bv * uu);
        float p = x * Cv;
        p += __shfl_xor_sync(0xffffffffu, p, 1);
        p += __shfl_xor_sync(0xffffffffu, p, 2);
        p += __shfl_xor_sync(0xffffffffu, p, 4);
        p += __shfl_xor_sync(0xffffffffu, p, 8);
        if (n == 0) *yp = fmaf(uu, Dv, p);
        dp += dstep; up += dstep; sp += sstep; yp += dstep;
    }
}

// ---------------------------------------------------------------------------
// combine: yt = (yf+yb)*silu(gate), written directly as A-frag hi plane
// ---------------------------------------------------------------------------
__global__ __launch_bounds__(256) void combine_kernel()
{
    const int idx = blockIdx.x * blockDim.x + threadIdx.x;   // over ML*ID/2
    const int R  = idx >> 10;
    const int ch = (idx & 1023) << 1;
    const size_t o = (size_t)R * ID + ch;
    float2 yf = *reinterpret_cast<const float2*>(g_y[0] + o);
    float2 yb = *reinterpret_cast<const float2*>(g_y[1] + o);
    float2 gt = *reinterpret_cast<const float2*>(g_gate + o);
    float yt0 = (yf.x + yb.x) * siluf(gt.x);
    float yt1 = (yf.y + yb.y) * siluf(gt.y);
    const int d = U_YT_A + ((R >> 7) * 64 + (ch >> 5)) * 2048 + afrag_idx(R & 127, ch & 31);
    g_hi[d] = pack_h2(yt0, yt1);
}

// ---------------------------------------------------------------------------
// add G5 split-K partials: out = p0 + p1 (deterministic order)
// ---------------------------------------------------------------------------
__global__ __launch_bounds__(256) void add_out(float* __restrict__ out)
{
    const int idx = blockIdx.x * blockDim.x + threadIdx.x;   // over ML*HD/4
    float4 a = *reinterpret_cast<const float4*>(g_delta[0] + (size_t)idx * 4);
    float4 b = *reinterpret_cast<const float4*>(g_delta[1] + (size_t)idx * 4);
    *reinterpret_cast<float4*>(out + (size_t)idx * 4) =
        make_float4(a.x + b.x, a.y + b.y, a.z + b.z, a.w + b.w);
}

// ---------------------------------------------------------------------------
// Launch
// ---------------------------------------------------------------------------
extern "C" void kernel_launch(void* const* d_in, const int* in_sizes, int n_in,
                              void* d_out, int out_size)
{
    const float* hs     = (const float*)d_in[0];
    const float* hs2    = (const float*)d_in[1];
    const float* in_w   = (const float*)d_in[2];
    const float* in_dw  = (const float*)d_in[3];
    const float* conv_w = (const float*)d_in[4];
    const float* conv_b = (const float*)d_in[5];
    const float* xw_f   = (const float*)d_in[6];
    const float* xw_b   = (const float*)d_in[7];
    const float* dtw_f  = (const float*)d_in[8];
    const float* dtb_f  = (const float*)d_in[9];
    const float* dtw_b  = (const float*)d_in[10];
    const float* dtb_b  = (const float*)d_in[11];
    const float* Alog_f = (const float*)d_in[12];
    const float* Alog_b = (const float*)d_in[13];
    const float* D_f    = (const float*)d_in[14];
    const float* D_b    = (const float*)d_in[15];
    const float* outw   = (const float*)d_in[16];
    float* out = (float*)d_out;

    float *px, *pgate, *pdelta;
    cudaGetSymbolAddress((void**)&px,     g_x);
    cudaGetSymbolAddress((void**)&pgate,  g_gate);
    cudaGetSymbolAddress((void**)&pdelta, g_delta);
    float* pd0 = pdelta;
    float* pd1 = pdelta + (size_t)ML*ID;

    cudaFuncSetAttribute((const void*)hgemm<0,4,2048>, cudaFuncAttributeMaxDynamicSharedMemorySize, SMEM_BYTES_OF(2048));
    cudaFuncSetAttribute((const void*)hgemm<1,4,2048>, cudaFuncAttributeMaxDynamicSharedMemorySize, SMEM_BYTES_OF(2048));
    cudaFuncSetAttribute((const void*)hgemm<0,2,1024>, cudaFuncAttributeMaxDynamicSharedMemorySize, SMEM_BYTES_OF(1024));
    cudaFuncSetAttribute((const void*)hgemm_g3,        cudaFuncAttributeMaxDynamicSharedMemorySize, SMEM_BYTES_OF(1024));

    // Batched conversions (weights + inputs) in ONE launch
    {
        CTable t;
        t.d[0] = {in_w,                  U_INW_B,  HD, 32, 512, 0, 128};
        t.d[1] = {in_dw + (size_t)ID*HD, U_INDW_B, HD, 32, 512, 0, 128};
        t.d[2] = {dtw_f,                 U_DTW0_B, RD, 2,  32,  0, 128};
        t.d[3] = {dtw_b,                 U_DTW1_B, RD, 2,  32,  0, 128};
        t.d[4] = {outw,                  U_OUTW_B, ID, 64, 512, 0, 128};
        t.d[5] = {hs,                    U_HS_A,   HD, 32, 256, 1, 128};
        t.d[6] = {hs2,                   U_HS2_A,  HD, 32, 256, 1, 128};
        t.d[7] = {xw_f,                  U_XW0_B,  ID, 64, 64,  0, 96};
        t.d[8] = {xw_b,                  U_XW1_B,  ID, 64, 64,  0, 96};
        conv_all<<<2240, 256>>>(t);
    }

    // G1: x = hs @ in_w[:I]^T ; gate = hs2 @ in_dw[I:2I]^T   (128x128 tiles)
    {
        HArgs a{U_HS_A,  U_INW_B,  px,    nullptr, 32*2048u, 32*2048u};
        HArgs b{U_HS2_A, U_INDW_B, pgate, nullptr, 32*2048u, 32*2048u};
        hgemm<0,4,2048><<<dim3(ID/128, ML/128, 2), 256, SMEM_BYTES_OF(2048)>>>(a, b, 32, ID);
    }

    // conv + silu (+ u hi plane)
    conv_silu_kernel<<<(ML*ID)/512, 256>>>(conv_w, conv_b);

    // G3 on tensor cores: split-K(8) partials then reduce+pack  (128x64 tiles)
    hgemm_g3<<<dim3(2, 8, 16), 256, SMEM_BYTES_OF(1024)>>>();
    reduce_pack_g3<<<(2*ML*48)/256, 256>>>();

    // G4: delta = softplus(dt @ dt_w^T + b)   (128x128 tiles)
    {
        HArgs a{U_SSM0_A, U_DTW0_B, pd0, dtb_f, 2*2048u, 2*2048u};
        HArgs b{U_SSM1_A, U_DTW1_B, pd1, dtb_b, 2*2048u, 2*2048u};
        hgemm<1,4,2048><<<dim3(ID/128, ML/128, 2), 256, SMEM_BYTES_OF(2048)>>>(a, b, 2, ID);
    }

    scan_kernel<<<512, 256>>>(Alog_f, Alog_b, D_f, D_b);
    combine_kernel<<<(ML*ID)/512, 256>>>();

    // G5: out = yt @ out_proj_w^T, split-K x2 into g_delta partials (256 blocks)
    {
        HArgs a{U_YT_A,            U_OUTW_B,            pd0, nullptr, 64*2048u, 64*2048u};
        HArgs b{U_YT_A + 32*2048u, U_OUTW_B + 32*2048u, pd1, nullptr, 64*2048u, 64*2048u};
        hgemm<0,2,1024><<<dim3(HD/64, ML/128, 2), 256, SMEM_BYTES_OF(1024)>>>(a, b, 32, HD);
    }
    add_out<<<(ML*HD)/1024, 256>>>(out);

    (void)in_sizes; (void)n_in; (void)out_size;
}

// round 16
// speedup vs baseline: 1.6640x; 1.1885x over previous
#include <cuda_runtime.h>
#include <cuda_fp16.h>
#include <cstdint>
#include <cstddef>

// Problem constants
#define HD 1024
#define ID 2048
#define NSTATE 16
#define RD 64
#define BB 2
#define LL 512
#define ML (BB*LL)

// ---------------------------------------------------------------------------
// Scratch
// ---------------------------------------------------------------------------
__device__ __align__(16) float g_x   [(size_t)ML*ID];
__device__ __align__(16) float g_gate[(size_t)ML*ID];
__device__ __align__(16) float g_u   [(size_t)ML*ID];
__device__ __align__(16) float g_ssm [2][(size_t)ML*32];    // interleaved (B,C) pairs per state
__device__ __align__(16) float g_part[2][8][(size_t)ML*96]; // split-K partials for G3
__device__ __align__(16) float g_delta[2][(size_t)ML*ID];   // delta; reused as G5 partials
__device__ __align__(16) float g_y   [2][(size_t)ML*ID];

// fp16 split-plane pools (fragment-packed u32 = half2 pairs)
#define U_HS_A    0u
#define U_HS2_A   524288u
#define U_INW_B   1048576u
#define U_INDW_B  2097152u
#define U_SSM0_A  3145728u
#define U_SSM1_A  3178496u
#define U_DTW0_B  3211264u
#define U_DTW1_B  3276800u
#define U_YT_A    3342336u
#define U_OUTW_B  4390912u
#define U_U_A     5439488u
#define U_XW0_B   6488064u
#define U_XW1_B   6619136u
#define U_TOTAL   6750208u
__device__ __align__(16) unsigned g_hi[U_TOTAL];
__device__ __align__(16) unsigned g_lo[U_TOTAL];   // only B (weight) lo planes consumed

__device__ __forceinline__ float siluf(float v)     { return v * (1.0f / (1.0f + __expf(-v))); }
__device__ __forceinline__ float softplusf(float v) { return v > 20.f ? v : log1pf(__expf(v)); }

__device__ __forceinline__ void split_pack(float x0, float x1, unsigned& ph, unsigned& pl) {
    __half h0 = __float2half_rn(x0), h1 = __float2half_rn(x1);
    __half l0 = __float2half_rn(x0 - __half2float(h0));
    __half l1 = __float2half_rn(x1 - __half2float(h1));
    ph = ((unsigned)__half_as_ushort(h1) << 16) | __half_as_ushort(h0);
    pl = ((unsigned)__half_as_ushort(l1) << 16) | __half_as_ushort(l0);
}
__device__ __forceinline__ unsigned pack_h2(float x0, float x1) {
    __half h0 = __float2half_rn(x0), h1 = __float2half_rn(x1);
    return ((unsigned)__half_as_ushort(h1) << 16) | __half_as_ushort(h0);
}

// A-fragment u32 index within a 128x32 chunk, for element pair (r, k even)
__device__ __forceinline__ int afrag_idx(int r, int k) {
    int mt = r >> 4, rr = r & 15;
    int ks = k >> 4, kk = k & 15;
    int lane = ((rr & 7) << 2) | ((kk >> 1) & 3);
    int reg  = (rr >> 3) | ((kk >> 3) << 1);
    return ((mt * 2 + ks) * 32 + lane) * 4 + reg;
}

// ---------------------------------------------------------------------------
// Batched converter: fp32 -> fragment-packed fp16 hi/lo planes.
// ---------------------------------------------------------------------------
struct CDesc { const float* src; unsigned off; int ld; int nchunks; int nblk; int isA; int nrows; };
struct CTable { CDesc d[9]; };

__global__ __launch_bounds__(256) void conv_all(CTable t)
{
    __shared__ float s[128][33];
    int b = blockIdx.x;
    int di = 0;
    while (b >= t.d[di].nblk) { b -= t.d[di].nblk; di++; }
    const CDesc d = t.d[di];
    const int rb = b / d.nchunks, c = b % d.nchunks;
    const int tid = threadIdx.x;
    const float* sp = d.src + (size_t)(rb * 128) * d.ld + c * 32;
#pragma unroll
    for (int it = 0; it < 4; it++) {
        int r = (tid >> 3) + it * 32, c4 = tid & 7;
        float4 v = make_float4(0.f, 0.f, 0.f, 0.f);
        if (r < d.nrows)
            v = *reinterpret_cast<const float4*>(sp + (size_t)r * d.ld + c4 * 4);
        s[r][c4*4+0]=v.x; s[r][c4*4+1]=v.y; s[r][c4*4+2]=v.z; s[r][c4*4+3]=v.w;
    }
    __syncthreads();
    unsigned* oh = g_hi + d.off + (size_t)(rb * d.nchunks + c) * 2048;
    unsigned* ol = g_lo + d.off + (size_t)(rb * d.nchunks + c) * 2048;
    if (d.isA) {
#pragma unroll
        for (int j = 0; j < 8; j++) {
            int idx = tid + 256*j;
            int reg = idx&3, lane=(idx>>2)&31, ks=(idx>>7)&1, mt=idx>>8;
            int r = mt*16 + ((reg&1)<<3) + (lane>>2);
            int k = ks*16 + ((reg>>1)<<3) + ((lane&3)<<1);
            oh[idx] = pack_h2(s[r][k], s[r][k+1]);
        }
    } else {
#pragma unroll
        for (int j = 0; j < 8; j++) {
            int idx = tid + 256*j;
            int reg = idx&1, lane=(idx>>1)&31, ks=(idx>>6)&1, nt=idx>>7;
            int n = nt*8 + (lane>>2);
            int k = ks*16 + reg*8 + ((lane&3)<<1);
            unsigned ph, pl;
            split_pack(s[n][k], s[n][k+1], ph, pl);
            oh[idx] = ph; ol[idx] = pl;
        }
    }
}

// ---------------------------------------------------------------------------
// fp16 2-pass split GEMM (A fp16-hi; B hi+lo), templated tile, 4-stage cp.async.
//   MT=2 -> 128x64 tile, MT=4 -> 128x128 tile
// ---------------------------------------------------------------------------
struct HArgs { unsigned aoff; unsigned boff; float* C; const float* bias;
               unsigned astr; unsigned bstr; };

__device__ __forceinline__ void mma_h(float* c, const unsigned* a, const unsigned* b) {
    asm volatile(
        "mma.sync.aligned.m16n8k16.row.col.f32.f16.f16.f32 "
        "{%0,%1,%2,%3},{%4,%5,%6,%7},{%8,%9},{%0,%1,%2,%3};"
        : "+f"(c[0]), "+f"(c[1]), "+f"(c[2]), "+f"(c[3])
        : "r"(a[0]), "r"(a[1]), "r"(a[2]), "r"(a[3]), "r"(b[0]), "r"(b[1]));
}
__device__ __forceinline__ void cp16(unsigned saddr, const void* g) {
    asm volatile("cp.async.cg.shared.global [%0], [%1], 16;" :: "r"(saddr), "l"(g));
}

#define NSTAGE 4
#define SMEM_BYTES_OF(BNU) (NSTAGE * (2048 + 2*(BNU)) * 4)

template<int MT, int BNU, typename EpiFn>
__device__ __forceinline__ void hgemm_body(
    const unsigned* gAh, const unsigned* gBh, const unsigned* gBl,
    int nch, unsigned* sm, unsigned sbase,
    int tid, int lane, int warp_m, int warp_n, EpiFn epi)
{
    constexpr int ST = 2048 + 2 * BNU;
    auto issue = [&](int s, int c) {
        const unsigned dst = sbase + s * (ST * 4);
        const unsigned* a0 = gAh + (size_t)c * 2048;
        const unsigned* b0 = gBh + (size_t)c * 2048;
        const unsigned* b1 = gBl + (size_t)c * 2048;
#pragma unroll
        for (int q = 0; q < 2; q++) {
            const int o = (tid + q * 256) * 4;
            cp16(dst + o * 4, a0 + o);
        }
#pragma unroll
        for (int q = 0; q < BNU/1024; q++) {
            const int o = (tid + q * 256) * 4;
            cp16(dst + 8192 + o * 4,            b0 + o);
            cp16(dst + 8192 + BNU*4 + o * 4,    b1 + o);
        }
        asm volatile("cp.async.commit_group;");
    };

    float acc[MT][4][4];
#pragma unroll
    for (int mt = 0; mt < MT; mt++)
#pragma unroll
        for (int nt = 0; nt < 4; nt++)
#pragma unroll
            for (int j = 0; j < 4; j++) acc[mt][nt][j] = 0.f;

    issue(0, 0);
    if (nch > 1) issue(1, 1);
    if (nch > 2) issue(2, 2);
    int sidx = 0;
    for (int c = 0; c < nch; c++) {
        if (c + 3 < nch) {
            int s3 = sidx + 3; if (s3 >= NSTAGE) s3 -= NSTAGE;
            issue(s3, c + 3);
            asm volatile("cp.async.wait_group 3;");
        } else if (c + 2 < nch) {
            asm volatile("cp.async.wait_group 2;");
        } else if (c + 1 < nch) {
            asm volatile("cp.async.wait_group 1;");
        } else {
            asm volatile("cp.async.wait_group 0;");
        }
        __syncthreads();
        const unsigned* st  = sm + sidx * ST;
        const unsigned* sAh = st;
        const unsigned* sBh = st + 2048;
        const unsigned* sBl = st + 2048 + BNU;
#pragma unroll
        for (int ks = 0; ks < 2; ks++) {
            unsigned ah[MT][4], bh[4][2], bl[4][2];
#pragma unroll
            for (int mt = 0; mt < MT; mt++) {
                const int base = (((warp_m*MT + mt)*2 + ks)*32 + lane) * 4;
                uint4 v = *reinterpret_cast<const uint4*>(sAh + base);
                ah[mt][0]=v.x; ah[mt][1]=v.y; ah[mt][2]=v.z; ah[mt][3]=v.w;
            }
#pragma unroll
            for (int nt = 0; nt < 4; nt++) {
                const int base = (((warp_n*4 + nt)*2 + ks)*32 + lane) * 2;
                uint2 v = *reinterpret_cast<const uint2*>(sBh + base);
                bh[nt][0]=v.x; bh[nt][1]=v.y;
                v = *reinterpret_cast<const uint2*>(sBl + base);
                bl[nt][0]=v.x; bl[nt][1]=v.y;
            }
#pragma unroll
            for (int mt = 0; mt < MT; mt++)
#pragma unroll
                for (int nt = 0; nt < 4; nt++) mma_h(acc[mt][nt], ah[mt], bh[nt]);
#pragma unroll
            for (int mt = 0; mt < MT; mt++)
#pragma unroll
                for (int nt = 0; nt < 4; nt++) mma_h(acc[mt][nt], ah[mt], bl[nt]);
        }
        __syncthreads();
        if (++sidx == NSTAGE) sidx = 0;
    }
    epi(acc);
}

template<int EPI, int MT, int BNU>
__global__ __launch_bounds__(256, 2) void hgemm(HArgs h0, HArgs h1, int nchunks, int ldc)
{
    extern __shared__ unsigned sm[];
    const unsigned sbase = (unsigned)__cvta_generic_to_shared(sm);
    HArgs h = blockIdx.z ? h1 : h0;
    const int tid = threadIdx.x, lane = tid & 31, wid = tid >> 5;
    const int warp_m = (MT == 2) ? (wid & 3) : (wid & 1);
    const int warp_n = (MT == 2) ? (wid >> 2) : (wid >> 1);
    constexpr int BN = (BNU == 1024) ? 64 : 128;
    const int row0 = blockIdx.y * 128, col0 = blockIdx.x * BN;
    const unsigned* gAh = g_hi + h.aoff + (size_t)blockIdx.y * h.astr;
    const size_t bbase = h.boff + (size_t)(col0 >> 7) * h.bstr + ((col0 >> 6) & 1) * 1024;
    const unsigned* gBh = g_hi + bbase;
    const unsigned* gBl = g_lo + bbase;
    const int rw = lane >> 2, cw = (lane & 3) * 2;

    hgemm_body<MT, BNU>(gAh, gBh, gBl, nchunks, sm, sbase, tid, lane, warp_m, warp_n,
        [&](float acc[MT][4][4]) {
#pragma unroll
            for (int mt = 0; mt < MT; mt++) {
                const int m = row0 + warp_m*(MT*16) + mt*16 + rw;
#pragma unroll
                for (int nt = 0; nt < 4; nt++) {
                    const int n = col0 + warp_n*32 + nt*8 + cw;
                    float v0 = acc[mt][nt][0], v1 = acc[mt][nt][1];
                    float v2 = acc[mt][nt][2], v3 = acc[mt][nt][3];
                    if (EPI == 1) {
                        const float b0 = __ldg(h.bias + n);
                        const float b1 = __ldg(h.bias + n + 1);
                        v0 = softplusf(v0 + b0); v1 = softplusf(v1 + b1);
                        v2 = softplusf(v2 + b0); v3 = softplusf(v3 + b1);
                    }
                    *reinterpret_cast<float2*>(h.C + (size_t)m * ldc + n)       = make_float2(v0, v1);
                    *reinterpret_cast<float2*>(h.C + (size_t)(m + 8) * ldc + n) = make_float2(v2, v3);
                }
            }
        });
}

// G3 tensor GEMM: partial[dir][split] = u[mblock, Kseg] @ xw^T (N=96 padded to 128)
// grid (2 nblocks, 8 mblocks, 16 = dir*8+split), 8 chunks per block; 128x64 tile
__global__ __launch_bounds__(256, 2) void hgemm_g3()
{
    extern __shared__ unsigned sm[];
    const unsigned sbase = (unsigned)__cvta_generic_to_shared(sm);
    const int nblock = blockIdx.x, mblock = blockIdx.y;
    const int dir = blockIdx.z >> 3, split = blockIdx.z & 7;
    const int tid = threadIdx.x, lane = tid & 31, wid = tid >> 5;
    const int warp_m = wid & 3, warp_n = wid >> 2;
    const size_t abase = U_U_A + (size_t)mblock * 64 * 2048 + (size_t)split * 8 * 2048;
    const unsigned* gAh = g_hi + abase;
    const size_t bbase = (dir ? U_XW1_B : U_XW0_B) + (size_t)split * 8 * 2048 + nblock * 1024;
    const unsigned* gBh = g_hi + bbase;
    const unsigned* gBl = g_lo + bbase;
    const int row0 = mblock * 128, col0 = nblock * 64;
    const int rw = lane >> 2, cw = (lane & 3) * 2;
    float* C = g_part[dir][split];

    hgemm_body<2, 1024>(gAh, gBh, gBl, 8, sm, sbase, tid, lane, warp_m, warp_n,
        [&](float acc[2][4][4]) {
#pragma unroll
            for (int mt = 0; mt < 2; mt++) {
                const int m = row0 + warp_m*32 + mt*16 + rw;
#pragma unroll
                for (int nt = 0; nt < 4; nt++) {
                    const int n = col0 + warp_n*32 + nt*8 + cw;
                    if (n < 96) {
                        *reinterpret_cast<float2*>(C + (size_t)m * 96 + n) =
                            make_float2(acc[mt][nt][0], acc[mt][nt][1]);
                        *reinterpret_cast<float2*>(C + (size_t)(m + 8) * 96 + n) =
                            make_float2(acc[mt][nt][2], acc[mt][nt][3]);
                    }
                }
            }
        });
}

// ---------------------------------------------------------------------------
// reduce partials; dt cols -> hi plane (A-frag layout),
// B/C cols -> g_ssm interleaved pairs: [R*32 + 2n] = B_n, [R*32 + 2n + 1] = C_n
// ---------------------------------------------------------------------------
__global__ __launch_bounds__(256) void reduce_pack_g3()
{
    const int idx = blockIdx.x * blockDim.x + threadIdx.x;   // < 2*1024*48
    const int pr  = idx % 48;
    const int R   = (idx / 48) % ML;
    const int dir = idx / (48 * ML);
    const int c0  = pr * 2;
    const size_t o = (size_t)R * 96 + c0;
    float2 s = make_float2(0.f, 0.f);
#pragma unroll
    for (int p = 0; p < 8; p++) {
        float2 v = *reinterpret_cast<const float2*>(g_part[dir][p] + o);
        s.x += v.x; s.y += v.y;
    }
    if (c0 < 64) {
        const unsigned uoff = dir ? U_SSM1_A : U_SSM0_A;
        const int d = uoff + ((R >> 7) * 2 + (c0 >> 5)) * 2048 + afrag_idx(R & 127, c0 & 31);
        g_hi[d] = pack_h2(s.x, s.y);
    } else {
        const int q = c0 - 64;          // 0..30 even
        float* row = g_ssm[dir] + (size_t)R * 32;
        if (q < 16) {                   // B values for states q, q+1
            row[2*q]     = s.x;
            row[2*q + 2] = s.y;
        } else {                        // C values for states q-16, q-15
            const int n0 = q - 16;
            row[2*n0 + 1] = s.x;
            row[2*n0 + 3] = s.y;
        }
    }
}

// ---------------------------------------------------------------------------
// conv + silu; emits u float + A-fragment hi plane for tensor G3
// ---------------------------------------------------------------------------
__global__ __launch_bounds__(256) void conv_silu_kernel(const float* __restrict__ w,
                                                        const float* __restrict__ bias)
{
    const int idx = blockIdx.x * blockDim.x + threadIdx.x;   // < ML*ID/2
    const int R  = idx >> 10;
    const int ch = (idx & 1023) << 1;
    const int l  = R & (LL - 1);
    const size_t o = (size_t)R * ID + ch;
    float acc0 = bias[ch], acc1 = bias[ch + 1];
#pragma unroll
    for (int k = 0; k < 4; k++) {
        int ls = l - 3 + k;
        if (ls >= 0) {
            float2 xv = *reinterpret_cast<const float2*>(g_x + o + (ptrdiff_t)(k - 3) * ID);
            acc0 = fmaf(xv.x, w[ch*4 + k],       acc0);
            acc1 = fmaf(xv.y, w[(ch+1)*4 + k],   acc1);
        }
    }
    float u0 = siluf(acc0), u1 = siluf(acc1);
    *reinterpret_cast<float2*>(g_u + o) = make_float2(u0, u1);
    const int d = U_U_A + ((R >> 7) * 64 + (ch >> 5)) * 2048 + afrag_idx(R & 127, ch & 31);
    g_hi[d] = pack_h2(u0, u1);
}

// ---------------------------------------------------------------------------
// selective scan: __ldg loads (hoistable), interleaved (B,C) float2, unroll 4
// ---------------------------------------------------------------------------
__global__ void scan_kernel(const float* __restrict__ Alog_f,
                            const float* __restrict__ Alog_b,
                            const float* __restrict__ D_f,
                            const float* __restrict__ D_b)
{
    int gw   = (blockIdx.x * blockDim.x + threadIdx.x) >> 5;
    int lane = threadIdx.x & 31;
    int dir  = gw >> 11;
    int b    = (gw >> 10) & 1;
    int i    = ((gw & 1023) << 1) | (lane >> 4);
    int n    = lane & 15;

    const float* Alog = dir ? Alog_b : Alog_f;
    float An = -expf(Alog[i*NSTATE + n]);
    float Dv = dir ? D_b[i] : D_f[i];

    const float* dbase = g_delta[dir] + (size_t)(b*LL)*ID + i;
    const float* ubase = g_u          + (size_t)(b*LL)*ID + i;
    const float* sbase = g_ssm[dir]   + (size_t)(b*LL)*32;
    float*       ybase = g_y[dir]     + (size_t)(b*LL)*ID + i;

    int l0 = dir ? (LL-1) : 0;
    ptrdiff_t dstep = dir ? -(ptrdiff_t)ID : (ptrdiff_t)ID;
    ptrdiff_t sstep = dir ? -32 : 32;

    const float* dp = dbase + (size_t)l0*ID;
    const float* up = ubase + (size_t)l0*ID;
    const float* sp = sbase + (size_t)l0*32;
    float*       yp = ybase + (size_t)l0*ID;

    float x = 0.f;
#pragma unroll 4
    for (int t = 0; t < LL; t++) {
        float  d  = __ldg(dp);
        float  uu = __ldg(up);
        float2 bc = __ldg(reinterpret_cast<const float2*>(sp) + n);
        float dA = __expf(d * An);
        x = fmaf(x, dA, d * bc.x * uu);
        float p = x * bc.y;
        p += __shfl_xor_sync(0xffffffffu, p, 1);
        p += __shfl_xor_sync(0xffffffffu, p, 2);
        p += __shfl_xor_sync(0xffffffffu, p, 4);
        p += __shfl_xor_sync(0xffffffffu, p, 8);
        if (n == 0) *yp = fmaf(uu, Dv, p);
        dp += dstep; up += dstep; sp += sstep; yp += dstep;
    }
}

// ---------------------------------------------------------------------------
// combine: yt = (yf+yb)*silu(gate), written directly as A-frag hi plane
// ---------------------------------------------------------------------------
__global__ __launch_bounds__(256) void combine_kernel()
{
    const int idx = blockIdx.x * blockDim.x + threadIdx.x;   // over ML*ID/2
    const int R  = idx >> 10;
    const int ch = (idx & 1023) << 1;
    const size_t o = (size_t)R * ID + ch;
    float2 yf = *reinterpret_cast<const float2*>(g_y[0] + o);
    float2 yb = *reinterpret_cast<const float2*>(g_y[1] + o);
    float2 gt = *reinterpret_cast<const float2*>(g_gate + o);
    float yt0 = (yf.x + yb.x) * siluf(gt.x);
    float yt1 = (yf.y + yb.y) * siluf(gt.y);
    const int d = U_YT_A + ((R >> 7) * 64 + (ch >> 5)) * 2048 + afrag_idx(R & 127, ch & 31);
    g_hi[d] = pack_h2(yt0, yt1);
}

// ---------------------------------------------------------------------------
// add G5 split-K partials: out = p0 + p1 (deterministic order)
// ---------------------------------------------------------------------------
__global__ __launch_bounds__(256) void add_out(float* __restrict__ out)
{
    const int idx = blockIdx.x * blockDim.x + threadIdx.x;   // over ML*HD/4
    float4 a = *reinterpret_cast<const float4*>(g_delta[0] + (size_t)idx * 4);
    float4 b = *reinterpret_cast<const float4*>(g_delta[1] + (size_t)idx * 4);
    *reinterpret_cast<float4*>(out + (size_t)idx * 4) =
        make_float4(a.x + b.x, a.y + b.y, a.z + b.z, a.w + b.w);
}

// ---------------------------------------------------------------------------
// Launch
// ---------------------------------------------------------------------------
extern "C" void kernel_launch(void* const* d_in, const int* in_sizes, int n_in,
                              void* d_out, int out_size)
{
    const float* hs     = (const float*)d_in[0];
    const float* hs2    = (const float*)d_in[1];
    const float* in_w   = (const float*)d_in[2];
    const float* in_dw  = (const float*)d_in[3];
    const float* conv_w = (const float*)d_in[4];
    const float* conv_b = (const float*)d_in[5];
    const float* xw_f   = (const float*)d_in[6];
    const float* xw_b   = (const float*)d_in[7];
    const float* dtw_f  = (const float*)d_in[8];
    const float* dtb_f  = (const float*)d_in[9];
    const float* dtw_b  = (const float*)d_in[10];
    const float* dtb_b  = (const float*)d_in[11];
    const float* Alog_f = (const float*)d_in[12];
    const float* Alog_b = (const float*)d_in[13];
    const float* D_f    = (const float*)d_in[14];
    const float* D_b    = (const float*)d_in[15];
    const float* outw   = (const float*)d_in[16];
    float* out = (float*)d_out;

    float *px, *pgate, *pdelta;
    cudaGetSymbolAddress((void**)&px,     g_x);
    cudaGetSymbolAddress((void**)&pgate,  g_gate);
    cudaGetSymbolAddress((void**)&pdelta, g_delta);
    float* pd0 = pdelta;
    float* pd1 = pdelta + (size_t)ML*ID;

    cudaFuncSetAttribute((const void*)hgemm<0,4,2048>, cudaFuncAttributeMaxDynamicSharedMemorySize, SMEM_BYTES_OF(2048));
    cudaFuncSetAttribute((const void*)hgemm<1,4,2048>, cudaFuncAttributeMaxDynamicSharedMemorySize, SMEM_BYTES_OF(2048));
    cudaFuncSetAttribute((const void*)hgemm<0,2,1024>, cudaFuncAttributeMaxDynamicSharedMemorySize, SMEM_BYTES_OF(1024));
    cudaFuncSetAttribute((const void*)hgemm_g3,        cudaFuncAttributeMaxDynamicSharedMemorySize, SMEM_BYTES_OF(1024));

    // Batched conversions (weights + inputs) in ONE launch
    {
        CTable t;
        t.d[0] = {in_w,                  U_INW_B,  HD, 32, 512, 0, 128};
        t.d[1] = {in_dw + (size_t)ID*HD, U_INDW_B, HD, 32, 512, 0, 128};
        t.d[2] = {dtw_f,                 U_DTW0_B, RD, 2,  32,  0, 128};
        t.d[3] = {dtw_b,                 U_DTW1_B, RD, 2,  32,  0, 128};
        t.d[4] = {outw,                  U_OUTW_B, ID, 64, 512, 0, 128};
        t.d[5] = {hs,                    U_HS_A,   HD, 32, 256, 1, 128};
        t.d[6] = {hs2,                   U_HS2_A,  HD, 32, 256, 1, 128};
        t.d[7] = {xw_f,                  U_XW0_B,  ID, 64, 64,  0, 96};
        t.d[8] = {xw_b,                  U_XW1_B,  ID, 64, 64,  0, 96};
        conv_all<<<2240, 256>>>(t);
    }

    // G1: x = hs @ in_w[:I]^T ; gate = hs2 @ in_dw[I:2I]^T   (128x128 tiles)
    {
        HArgs a{U_HS_A,  U_INW_B,  px,    nullptr, 32*2048u, 32*2048u};
        HArgs b{U_HS2_A, U_INDW_B, pgate, nullptr, 32*2048u, 32*2048u};
        hgemm<0,4,2048><<<dim3(ID/128, ML/128, 2), 256, SMEM_BYTES_OF(2048)>>>(a, b, 32, ID);
    }

    // conv + silu (+ u hi plane)
    conv_silu_kernel<<<(ML*ID)/512, 256>>>(conv_w, conv_b);

    // G3 on tensor cores: split-K(8) partials then reduce+pack  (128x64 tiles)
    hgemm_g3<<<dim3(2, 8, 16), 256, SMEM_BYTES_OF(1024)>>>();
    reduce_pack_g3<<<(2*ML*48)/256, 256>>>();

    // G4: delta = softplus(dt @ dt_w^T + b)   (128x128 tiles)
    {
        HArgs a{U_SSM0_A, U_DTW0_B, pd0, dtb_f, 2*2048u, 2*2048u};
        HArgs b{U_SSM1_A, U_DTW1_B, pd1, dtb_b, 2*2048u, 2*2048u};
        hgemm<1,4,2048><<<dim3(ID/128, ML/128, 2), 256, SMEM_BYTES_OF(2048)>>>(a, b, 2, ID);
    }

    scan_kernel<<<512, 256>>>(Alog_f, Alog_b, D_f, D_b);
    combine_kernel<<<(ML*ID)/512, 256>>>();

    // G5: out = yt @ out_proj_w^T, split-K x2 into g_delta partials (256 blocks)
    {
        HArgs a{U_YT_A,            U_OUTW_B,            pd0, nullptr, 64*2048u, 64*2048u};
        HArgs b{U_YT_A + 32*2048u, U_OUTW_B + 32*2048u, pd1, nullptr, 64*2048u, 64*2048u};
        hgemm<0,2,1024><<<dim3(HD/64, ML/128, 2), 256, SMEM_BYTES_OF(1024)>>>(a, b, 32, HD);
    }
    add_out<<<(ML*HD)/1024, 256>>>(out);

    (void)in_sizes; (void)n_in; (void)out_size;
}